// round 3
// baseline (speedup 1.0000x reference)
#include <cuda_runtime.h>
#include <math.h>

#define BATCH 4
#define DIM 384
#define HEADS 8
#define CH 48            // DIM/HEADS
#define HW 16384         // 128*128
#define C3 1152          // 3*DIM
#define EPS 1e-12f
#define CLAMPV 50.0f
#define NCHUNKS 16       // n-chunks for attn S partials

typedef unsigned long long ull;

// ---------------- device scratch (no allocation allowed) ----------------
__device__ float g_t0[BATCH * C3 * HW];        // qkv GEMM output   (~302 MB)
__device__ float g_t1[BATCH * C3 * HW];        // depthwise output  (~302 MB)
__device__ float g_attn_out[BATCH * DIM * HW]; // attention output  (~100 MB)
__device__ float g_sigma[4];                   // sigma_qkv, sigma_dw, sigma_proj, combined scale
__device__ float g_invnorm[BATCH * 2 * DIM];   // inv L2 norms of q (0..383) and k (384..767)
__device__ float g_Spart[NCHUNKS * BATCH * HEADS * CH * CH]; // partial logits
__device__ float g_S[BATCH * HEADS * CH * CH];               // softmaxed attn

// packed dual-fp32 FMA (sm_100+): d.lo = a.lo*b.lo+c.lo ; d.hi = a.hi*b.hi+c.hi
__device__ __forceinline__ ull ffma2(ull a, ull b, ull c) {
    ull d;
    asm("fma.rn.f32x2 %0, %1, %2, %3;" : "=l"(d) : "l"(a), "l"(b), "l"(c));
    return d;
}

// ---------------- spectral sigma: sigma = || wm @ unit(wm^T u) || ----------------
__global__ void sigma_kernel(const float* __restrict__ qkvw,
                             const float* __restrict__ dww,
                             const float* __restrict__ projw,
                             const float* __restrict__ uq,
                             const float* __restrict__ ud,
                             const float* __restrict__ up)
{
    int which = blockIdx.x;
    const float* wm; const float* u; int h, w;
    if (which == 0)      { wm = qkvw;  u = uq; h = C3;  w = DIM; }
    else if (which == 1) { wm = dww;   u = ud; h = C3;  w = 9;   }
    else                 { wm = projw; u = up; h = DIM; w = DIM; }

    __shared__ float v[DIM];
    __shared__ float red[256];
    int tid = threadIdx.x;

    // v = wm^T u
    for (int j = tid; j < w; j += 256) {
        float s = 0.f;
        for (int i = 0; i < h; i++) s += wm[i * w + j] * u[i];
        v[j] = s;
    }
    __syncthreads();

    float ss = 0.f;
    for (int j = tid; j < w; j += 256) ss += v[j] * v[j];
    red[tid] = ss; __syncthreads();
    for (int s = 128; s > 0; s >>= 1) { if (tid < s) red[tid] += red[tid + s]; __syncthreads(); }
    float vinv = 1.f / fmaxf(sqrtf(red[0]), EPS);
    __syncthreads();
    for (int j = tid; j < w; j += 256) v[j] *= vinv;
    __syncthreads();

    // wv = wm v ; sigma = ||wv||^2 / max(||wv||, eps)
    float ss2 = 0.f;
    for (int i = tid; i < h; i += 256) {
        float s = 0.f;
        for (int j = 0; j < w; j++) s += wm[i * w + j] * v[j];
        ss2 += s * s;
    }
    red[tid] = ss2; __syncthreads();
    for (int s = 128; s > 0; s >>= 1) { if (tid < s) red[tid] += red[tid + s]; __syncthreads(); }
    if (tid == 0) {
        float sq = red[0];
        g_sigma[which] = sq / fmaxf(sqrtf(sq), EPS);
    }
}

__global__ void scale_kernel()
{
    if (threadIdx.x == 0) {
        float s = 1.f;
        s /= (g_sigma[0] + EPS);
        s /= (g_sigma[1] + EPS);
        s /= (g_sigma[2] + EPS);
        g_sigma[3] = s;
    }
}

// ---------------- SGEMM via f32x2: C[b][m][n] = sum_k A[m][k] * B[b][k][n] ----------------
// 128x128x16 tile, 256 threads, 8x8 per thread.
// A smem tile stored DUPLICATED ({v,v} float2) so the inner loop needs no packs:
// per k-step: 6x LDS.128 + 32x FFMA2 (vs 64x FFMA scalar).
__global__ __launch_bounds__(256)
void sgemm128(const float* __restrict__ A, const float* __restrict__ B,
              float* __restrict__ C, int M, int N, int K,
              long strideB, long strideC, int useScale)
{
    const float* Bb = B + (long)blockIdx.z * strideB;
    float* Cb = C + (long)blockIdx.z * strideC;

    __shared__ float2 As[16][128];   // duplicated: As[k][m] = {a, a}
    __shared__ float  Bs[16][128];

    int tid = threadIdx.x;
    int bm = blockIdx.y, bn = blockIdx.x;
    int ty = tid >> 4, tx = tid & 15;

    ull acc[8][4];   // pairs along n: acc[i][jp] = {C(i,2jp), C(i,2jp+1)}
#pragma unroll
    for (int i = 0; i < 8; i++)
#pragma unroll
        for (int j = 0; j < 4; j++) acc[i][j] = 0ULL;

    for (int kt = 0; kt < K; kt += 16) {
#pragma unroll
        for (int i = 0; i < 2; i++) {
            int idx = tid + i * 256;
            int row = idx >> 2; int k4 = (idx & 3) << 2;
            float4 a4 = *(const float4*)&A[(bm * 128 + row) * K + kt + k4];
            As[k4 + 0][row] = make_float2(a4.x, a4.x);
            As[k4 + 1][row] = make_float2(a4.y, a4.y);
            As[k4 + 2][row] = make_float2(a4.z, a4.z);
            As[k4 + 3][row] = make_float2(a4.w, a4.w);
        }
#pragma unroll
        for (int i = 0; i < 2; i++) {
            int idx = tid + i * 256;
            int row = idx >> 5; int n4 = (idx & 31) << 2;
            *(float4*)&Bs[row][n4] =
                *(const float4*)&Bb[(long)(kt + row) * N + bn * 128 + n4];
        }
        __syncthreads();

#pragma unroll
        for (int kk = 0; kk < 16; kk++) {
            const ulonglong2* ap = (const ulonglong2*)&As[kk][ty * 8];
            ulonglong2 p0 = ap[0], p1 = ap[1], p2 = ap[2], p3 = ap[3];
            ull aa[8] = {p0.x, p0.y, p1.x, p1.y, p2.x, p2.y, p3.x, p3.y};
            const ulonglong2* bp = (const ulonglong2*)&Bs[kk][tx * 8];
            ulonglong2 q0 = bp[0], q1 = bp[1];
            ull bb[4] = {q0.x, q0.y, q1.x, q1.y};
#pragma unroll
            for (int i = 0; i < 8; i++)
#pragma unroll
                for (int j = 0; j < 4; j++)
                    acc[i][j] = ffma2(aa[i], bb[j], acc[i][j]);
        }
        __syncthreads();
    }

    float sc = useScale ? g_sigma[3] : 1.0f;
#pragma unroll
    for (int i = 0; i < 8; i++) {
        long row = bm * 128 + ty * 8 + i;
#pragma unroll
        for (int jp = 0; jp < 4; jp += 2) {
            float4 o;
            o.x = __uint_as_float((unsigned)(acc[i][jp] & 0xffffffffu)) * sc;
            o.y = __uint_as_float((unsigned)(acc[i][jp] >> 32)) * sc;
            o.z = __uint_as_float((unsigned)(acc[i][jp + 1] & 0xffffffffu)) * sc;
            o.w = __uint_as_float((unsigned)(acc[i][jp + 1] >> 32)) * sc;
            *(float4*)&Cb[row * N + bn * 128 + tx * 8 + jp * 2] = o;
        }
    }
}

// ---------------- 3x3 depthwise conv, pad=1 (raw weights) ----------------
// grid (8, 1152, 4) : 16 output rows per block, 128 threads (one per x)
__global__ __launch_bounds__(128)
void dwconv(const float* __restrict__ in, const float* __restrict__ w,
            float* __restrict__ out)
{
    int ych = blockIdx.x * 16;
    int ch = blockIdx.y;
    int b = blockIdx.z;
    const float* ip = in + (((long)b * C3 + ch) << 14);
    float* op = out + (((long)b * C3 + ch) << 14);

    __shared__ float rows[18][130];
    int x = threadIdx.x;
#pragma unroll
    for (int r = 0; r < 18; r++) {
        int yy = ych + r - 1;
        rows[r][x + 1] = (yy >= 0 && yy < 128) ? ip[(yy << 7) + x] : 0.f;
        if (x == 0) { rows[r][0] = 0.f; rows[r][129] = 0.f; }
    }
    float w00 = w[ch * 9 + 0], w01 = w[ch * 9 + 1], w02 = w[ch * 9 + 2];
    float w10 = w[ch * 9 + 3], w11 = w[ch * 9 + 4], w12 = w[ch * 9 + 5];
    float w20 = w[ch * 9 + 6], w21 = w[ch * 9 + 7], w22 = w[ch * 9 + 8];
    __syncthreads();

#pragma unroll
    for (int yo = 0; yo < 16; yo++) {
        float s = rows[yo][x]     * w00 + rows[yo][x + 1]     * w01 + rows[yo][x + 2]     * w02
                + rows[yo + 1][x] * w10 + rows[yo + 1][x + 1] * w11 + rows[yo + 1][x + 2] * w12
                + rows[yo + 2][x] * w20 + rows[yo + 2][x + 1] * w21 + rows[yo + 2][x + 2] * w22;
        op[((ych + yo) << 7) + x] = s;
    }
}

// ---------------- per-(b, channel) inverse L2 norm over spatial dim ----------------
__global__ __launch_bounds__(256)
void norm_kernel(const float* __restrict__ t)
{
    int idx = blockIdx.x;
    int b = idx / (2 * DIM), c = idx % (2 * DIM);
    const float4* p = (const float4*)(t + (((long)b * C3 + c) << 14));
    float ss = 0.f;
    for (int i = threadIdx.x; i < HW / 4; i += 256) {
        float4 v = p[i];
        ss += v.x * v.x + v.y * v.y + v.z * v.z + v.w * v.w;
    }
    __shared__ float red[256];
    red[threadIdx.x] = ss; __syncthreads();
    for (int s = 128; s > 0; s >>= 1) {
        if (threadIdx.x < s) red[threadIdx.x] += red[threadIdx.x + s];
        __syncthreads();
    }
    if (threadIdx.x == 0) g_invnorm[idx] = 1.f / fmaxf(sqrtf(red[0]), EPS);
}

// ---------------- raw attention logits (partial over n-chunks) ----------------
__global__ __launch_bounds__(256)
void attn_s(const float* __restrict__ t)
{
    int bh = blockIdx.y;
    int b = bh >> 3, head = bh & 7;
    int n0 = blockIdx.x * (HW / NCHUNKS);   // 1024
    const float* qp = t + ((((long)b * C3) + head * CH) << 14);
    const float* kp = t + ((((long)b * C3) + DIM + head * CH) << 14);

    __shared__ float qs[32][49];
    __shared__ float ks[32][49];
    int tid = threadIdx.x;
    int ty = tid >> 4, tx = tid & 15;
    float acc[3][3] = {};

    for (int nt = 0; nt < 32; nt++) {
        int nb = n0 + nt * 32;
        for (int i = tid; i < CH * 32; i += 256) {
            int c = i >> 5, nn = i & 31;
            qs[nn][c] = qp[(c << 14) + nb + nn];
            ks[nn][c] = kp[(c << 14) + nb + nn];
        }
        __syncthreads();
#pragma unroll
        for (int nn = 0; nn < 32; nn++) {
            float a0 = qs[nn][ty * 3], a1 = qs[nn][ty * 3 + 1], a2 = qs[nn][ty * 3 + 2];
            float b0 = ks[nn][tx * 3], b1 = ks[nn][tx * 3 + 1], b2 = ks[nn][tx * 3 + 2];
            acc[0][0] = fmaf(a0, b0, acc[0][0]); acc[0][1] = fmaf(a0, b1, acc[0][1]); acc[0][2] = fmaf(a0, b2, acc[0][2]);
            acc[1][0] = fmaf(a1, b0, acc[1][0]); acc[1][1] = fmaf(a1, b1, acc[1][1]); acc[1][2] = fmaf(a1, b2, acc[1][2]);
            acc[2][0] = fmaf(a2, b0, acc[2][0]); acc[2][1] = fmaf(a2, b1, acc[2][1]); acc[2][2] = fmaf(a2, b2, acc[2][2]);
        }
        __syncthreads();
    }

    float* Sp = g_Spart + ((long)blockIdx.x * 32 + bh) * (CH * CH);
#pragma unroll
    for (int i = 0; i < 3; i++)
#pragma unroll
        for (int j = 0; j < 3; j++)
            Sp[(ty * 3 + i) * CH + tx * 3 + j] = acc[i][j];
}

// ---------------- finalize: reduce partials, scale, clamp, softmax ----------------
__global__ __launch_bounds__(64)
void softmax_kernel(const float* __restrict__ temp)
{
    int blk = blockIdx.x;
    int bh = blk / CH, c = blk % CH;
    int b = bh >> 3, head = bh & 7;
    int d = threadIdx.x;
    __shared__ float sm[64];

    float myv = 0.f, val = -1e30f;
    if (d < CH) {
        float raw = 0.f;
#pragma unroll
        for (int ch = 0; ch < NCHUNKS; ch++)
            raw += g_Spart[((long)ch * 32 + bh) * (CH * CH) + c * CH + d];
        float invq = g_invnorm[b * 2 * DIM + head * CH + c];
        float invk = g_invnorm[b * 2 * DIM + DIM + head * CH + d];
        myv = raw * invq * invk * temp[head];
        myv = fminf(fmaxf(myv, -CLAMPV), CLAMPV);
        val = myv;
    }
    sm[d] = val; __syncthreads();
    for (int s = 32; s > 0; s >>= 1) { if (d < s) sm[d] = fmaxf(sm[d], sm[d + s]); __syncthreads(); }
    float m = sm[0]; __syncthreads();
    float e = (d < CH) ? expf(myv - m) : 0.f;
    sm[d] = e; __syncthreads();
    for (int s = 32; s > 0; s >>= 1) { if (d < s) sm[d] += sm[d + s]; __syncthreads(); }
    if (d < CH) g_S[(long)bh * (CH * CH) + c * CH + d] = e / sm[0];
}

// ---------------- out = attn @ v ----------------
__global__ __launch_bounds__(256)
void attn_o(const float* __restrict__ t, float* __restrict__ out)
{
    int bh = blockIdx.y;
    int b = bh >> 3, head = bh & 7;
    const float* vp = t + ((((long)b * C3) + 2 * DIM + head * CH) << 14);
    float* op = out + ((((long)b * DIM) + head * CH) << 14);

    __shared__ float Ss[CH * CH];
    for (int i = threadIdx.x; i < CH * CH; i += 256)
        Ss[i] = g_S[(long)bh * (CH * CH) + i];
    __syncthreads();

    int n = blockIdx.x * 512 + threadIdx.x;
    float acc0[CH], acc1[CH];
#pragma unroll
    for (int c = 0; c < CH; c++) { acc0[c] = 0.f; acc1[c] = 0.f; }

    for (int d = 0; d < CH; d++) {
        float v0 = vp[(d << 14) + n];
        float v1 = vp[(d << 14) + n + 256];
#pragma unroll
        for (int c = 0; c < CH; c++) {
            float s = Ss[c * CH + d];
            acc0[c] = fmaf(s, v0, acc0[c]);
            acc1[c] = fmaf(s, v1, acc1[c]);
        }
    }
#pragma unroll
    for (int c = 0; c < CH; c++) {
        op[(c << 14) + n] = acc0[c];
        op[(c << 14) + n + 256] = acc1[c];
    }
}

// ---------------- launch ----------------
extern "C" void kernel_launch(void* const* d_in, const int* in_sizes, int n_in,
                              void* d_out, int out_size)
{
    const float* x     = (const float*)d_in[0];
    const float* qkvw  = (const float*)d_in[1];
    const float* dww   = (const float*)d_in[2];
    const float* projw = (const float*)d_in[3];
    const float* temp  = (const float*)d_in[4];
    const float* uq    = (const float*)d_in[5];
    const float* ud    = (const float*)d_in[6];
    const float* up    = (const float*)d_in[7];
    float* out = (float*)d_out;

    float *t0, *t1, *ao;
    cudaGetSymbolAddress((void**)&t0, g_t0);
    cudaGetSymbolAddress((void**)&t1, g_t1);
    cudaGetSymbolAddress((void**)&ao, g_attn_out);

    // spectral sigmas + combined output scale (scales cancel everywhere else)
    sigma_kernel<<<3, 256>>>(qkvw, dww, projw, uq, ud, up);
    scale_kernel<<<1, 32>>>();

    // qkv 1x1 conv: GEMM [1152 x 384] x [384 x 16384] per batch (raw weights)
    sgemm128<<<dim3(HW / 128, C3 / 128, BATCH), 256>>>(
        qkvw, x, t0, C3, HW, DIM, (long)DIM * HW, (long)C3 * HW, 0);

    // 3x3 depthwise conv (raw weights)
    dwconv<<<dim3(8, C3, BATCH), 128>>>(t0, dww, t1);

    // q/k inverse L2 norms
    norm_kernel<<<BATCH * 2 * DIM, 256>>>(t1);

    // attention logits (partials), then scale/clamp/softmax
    attn_s<<<dim3(NCHUNKS, BATCH * HEADS), 256>>>(t1);
    softmax_kernel<<<BATCH * HEADS * CH, 64>>>(temp);

    // out = attn @ v
    attn_o<<<dim3(32, BATCH * HEADS), 256>>>(t1, ao);

    // proj 1x1 conv: GEMM [384 x 384] x [384 x 16384] per batch, with combined scale
    sgemm128<<<dim3(HW / 128, DIM / 128, BATCH), 256>>>(
        projw, ao, out, DIM, HW, DIM, (long)DIM * HW, (long)DIM * HW, 1);
}

// round 5
// speedup vs baseline: 1.8300x; 1.8300x over previous
#include <cuda_runtime.h>
#include <cuda_bf16.h>
#include <math.h>
#include <stdint.h>

#define BATCH 4
#define DIM 384
#define HEADS 8
#define CH 48            // DIM/HEADS
#define HW 16384         // 128*128
#define C3 1152          // 3*DIM
#define EPS 1e-12f
#define CLAMPV 50.0f
#define NCHUNKS 16
#define GK 384           // GEMM K (always DIM)

// ---------------- device scratch ----------------
__device__ float g_t0[BATCH * C3 * HW];        // qkv GEMM output fp32
__device__ float g_t1[BATCH * C3 * HW];        // depthwise output fp32
__device__ float g_sigma[4];
__device__ float g_invnorm[BATCH * 2 * DIM];
__device__ float g_Spart[NCHUNKS * BATCH * HEADS * CH * CH];
__device__ float g_S[BATCH * HEADS * CH * CH];
// bf16 split operands (transposed activations: [b][n=hw][k=384])
__device__ __nv_bfloat16 g_xh[(size_t)BATCH * HW * DIM];
__device__ __nv_bfloat16 g_xl[(size_t)BATCH * HW * DIM];
__device__ __nv_bfloat16 g_aoh[(size_t)BATCH * HW * DIM];
__device__ __nv_bfloat16 g_aol[(size_t)BATCH * HW * DIM];
__device__ __nv_bfloat16 g_wqh[C3 * DIM];
__device__ __nv_bfloat16 g_wql[C3 * DIM];
__device__ __nv_bfloat16 g_wph[DIM * DIM];
__device__ __nv_bfloat16 g_wpl[DIM * DIM];

// ---------------- warp-mma helpers (all non-'a' features: sm_80 baseline) ----------------
__device__ __forceinline__ uint32_t smem_u32(const void* p) {
    uint32_t a;
    asm("{ .reg .u64 t; cvta.to.shared.u64 t, %1; cvt.u32.u64 %0, t; }" : "=r"(a) : "l"(p));
    return a;
}
__device__ __forceinline__ void cpasync16(uint32_t s, const void* g) {
    asm volatile("cp.async.cg.shared.global [%0], [%1], 16;" :: "r"(s), "l"(g));
}
#define CP_COMMIT() asm volatile("cp.async.commit_group;" ::: "memory")
#define CP_WAIT1()  asm volatile("cp.async.wait_group 1;" ::: "memory")
#define CP_WAIT0()  asm volatile("cp.async.wait_group 0;" ::: "memory")

__device__ __forceinline__ void ldsm4(uint32_t* r, uint32_t addr) {
    asm volatile("ldmatrix.sync.aligned.m8n8.x4.shared.b16 {%0,%1,%2,%3}, [%4];"
        : "=r"(r[0]), "=r"(r[1]), "=r"(r[2]), "=r"(r[3]) : "r"(addr));
}
__device__ __forceinline__ void mma_bf16(float* c, const uint32_t* a, const uint32_t* b) {
    asm volatile(
        "mma.sync.aligned.m16n8k16.row.col.f32.bf16.bf16.f32 "
        "{%0,%1,%2,%3}, {%4,%5,%6,%7}, {%8,%9}, {%0,%1,%2,%3};"
        : "+f"(c[0]), "+f"(c[1]), "+f"(c[2]), "+f"(c[3])
        : "r"(a[0]), "r"(a[1]), "r"(a[2]), "r"(a[3]), "r"(b[0]), "r"(b[1]));
}

// swizzled smem offset for a 128-row x 32-bf16 (64B) tile packed 2 rows/128B line.
// Guarantees 8 distinct 16B phases across any 8 consecutive rows at fixed chunk.
__device__ __forceinline__ uint32_t swz(uint32_t row, uint32_t c) {
    return (row >> 1) * 128 + ((((row & 1) * 4 + c) ^ ((row >> 1) & 7)) * 16);
}

// ---------------- spectral sigma ----------------
__global__ void sigma_kernel(const float* __restrict__ qkvw,
                             const float* __restrict__ dww,
                             const float* __restrict__ projw,
                             const float* __restrict__ uq,
                             const float* __restrict__ ud,
                             const float* __restrict__ up)
{
    int which = blockIdx.x;
    const float* wm; const float* u; int h, w;
    if (which == 0)      { wm = qkvw;  u = uq; h = C3;  w = DIM; }
    else if (which == 1) { wm = dww;   u = ud; h = C3;  w = 9;   }
    else                 { wm = projw; u = up; h = DIM; w = DIM; }

    __shared__ float v[DIM];
    __shared__ float red[256];
    int tid = threadIdx.x;

    for (int j = tid; j < w; j += 256) {
        float s = 0.f;
        for (int i = 0; i < h; i++) s += wm[i * w + j] * u[i];
        v[j] = s;
    }
    __syncthreads();

    float ss = 0.f;
    for (int j = tid; j < w; j += 256) ss += v[j] * v[j];
    red[tid] = ss; __syncthreads();
    for (int s = 128; s > 0; s >>= 1) { if (tid < s) red[tid] += red[tid + s]; __syncthreads(); }
    float vinv = 1.f / fmaxf(sqrtf(red[0]), EPS);
    __syncthreads();
    for (int j = tid; j < w; j += 256) v[j] *= vinv;
    __syncthreads();

    float ss2 = 0.f;
    for (int i = tid; i < h; i += 256) {
        float s = 0.f;
        for (int j = 0; j < w; j++) s += wm[i * w + j] * v[j];
        ss2 += s * s;
    }
    red[tid] = ss2; __syncthreads();
    for (int s = 128; s > 0; s >>= 1) { if (tid < s) red[tid] += red[tid + s]; __syncthreads(); }
    if (tid == 0) {
        float sq = red[0];
        g_sigma[which] = sq / fmaxf(sqrtf(sq), EPS);
    }
}

__global__ void scale_kernel()
{
    if (threadIdx.x == 0) {
        float s = 1.f;
        s /= (g_sigma[0] + EPS);
        s /= (g_sigma[1] + EPS);
        s /= (g_sigma[2] + EPS);
        g_sigma[3] = s;
    }
}

// ---------------- fp32 -> bf16 hi/lo split (weights, K-major already) ----------------
__global__ __launch_bounds__(256)
void split_w(const float* __restrict__ w, __nv_bfloat16* __restrict__ h,
             __nv_bfloat16* __restrict__ l, int n)
{
    int i = blockIdx.x * 256 + threadIdx.x;
    if (i < n) {
        float v = w[i];
        __nv_bfloat16 hi = __float2bfloat16(v);
        h[i] = hi;
        l[i] = __float2bfloat16(v - __bfloat162float(hi));
    }
}

// ---------------- transpose + split: x [b][c=384][hw] -> xh/xl [b][hw][384] ----------------
__global__ __launch_bounds__(256)
void xpose_split(const float* __restrict__ x, __nv_bfloat16* __restrict__ xh,
                 __nv_bfloat16* __restrict__ xl)
{
    __shared__ float t[32][33];
    int hw0 = blockIdx.x << 5, c0 = blockIdx.y << 5, b = blockIdx.z;
    int tx = threadIdx.x & 31, ty = threadIdx.x >> 5;
#pragma unroll
    for (int i = 0; i < 4; i++)
        t[ty + i * 8][tx] = x[(((long)b * DIM + c0 + ty + i * 8) << 14) + hw0 + tx];
    __syncthreads();
#pragma unroll
    for (int i = 0; i < 4; i++) {
        int n = hw0 + ty + i * 8;
        float v = t[tx][ty + i * 8];
        __nv_bfloat16 hi = __float2bfloat16(v);
        long o = ((long)b * HW + n) * DIM + c0 + tx;
        xh[o] = hi;
        xl[o] = __float2bfloat16(v - __bfloat162float(hi));
    }
}

// ---------------- bf16-split GEMM via mma.sync ----------------
// C[b][m][n] = sum_k A[m][k]*B[b][n][k];  A [Mtot][384] hi/lo, B [b][16384][384] hi/lo.
// Block 128x128x32, 8 warps (2Mx4N), warp tile 64x32, cp.async 2-stage.
// smem per stage: Ah|Al|Bh|Bl tiles of 8KB each = 32KB; 2 stages = 64KB.
#define BG_SMEM 65536
#define KTILES (GK / 32)

__global__ void __launch_bounds__(256)
bgemm(const __nv_bfloat16* __restrict__ Ah, const __nv_bfloat16* __restrict__ Al,
      const __nv_bfloat16* __restrict__ Bh, const __nv_bfloat16* __restrict__ Bl,
      float* __restrict__ C, long strideC, int useScale)
{
    extern __shared__ char smem[];
    uint32_t sb = smem_u32(smem);
    int tid = threadIdx.x, wid = tid >> 5, lane = tid & 31;
    int n0 = blockIdx.x << 7, m0 = blockIdx.y << 7, bz = blockIdx.z;
    int wm = (wid >> 2) * 64;      // warp m offset in block
    int wn = (wid & 3) * 32;       // warp n offset in block

    const __nv_bfloat16* ahp = Ah + (long)m0 * GK;
    const __nv_bfloat16* alp = Al + (long)m0 * GK;
    const __nv_bfloat16* bhp = Bh + (long)bz * HW * DIM + (long)n0 * GK;
    const __nv_bfloat16* blp = Bl + (long)bz * HW * DIM + (long)n0 * GK;
    float* Cb = C + (long)bz * strideC;

    float acc[4][4][4];
#pragma unroll
    for (int i = 0; i < 4; i++)
#pragma unroll
        for (int j = 0; j < 4; j++)
#pragma unroll
            for (int k = 0; k < 4; k++) acc[i][j][k] = 0.f;

    // --- stage loader: 8 cp.async of 16B per thread ---
    // i>>1 selects tile (0=Ah,1=Al,2=Bh,3=Bl); row=(i&1)*64 + tid/4; chunk c = tid&3
#define LOAD_STAGE(kc, stage) do { \
        int _k0 = (kc) << 5; \
        uint32_t _sb = sb + (stage) * 32768; \
        _Pragma("unroll") \
        for (int _i = 0; _i < 8; _i++) { \
            int _tile = _i >> 1; \
            int _row = ((_i & 1) << 6) + (tid >> 2); \
            int _c = tid & 3; \
            const __nv_bfloat16* _gp; \
            if (_tile == 0)      _gp = ahp + (long)_row * GK + _k0 + _c * 8; \
            else if (_tile == 1) _gp = alp + (long)_row * GK + _k0 + _c * 8; \
            else if (_tile == 2) _gp = bhp + (long)_row * GK + _k0 + _c * 8; \
            else                 _gp = blp + (long)_row * GK + _k0 + _c * 8; \
            cpasync16(_sb + _tile * 8192 + swz(_row, _c), _gp); \
        } \
        CP_COMMIT(); \
    } while (0)

    LOAD_STAGE(0, 0);
    LOAD_STAGE(1, 1);

    for (int kc = 0; kc < KTILES; kc++) {
        if (kc < KTILES - 1) CP_WAIT1(); else CP_WAIT0();
        __syncthreads();

        uint32_t st = sb + (kc & 1) * 32768;
#pragma unroll
        for (int ks = 0; ks < 2; ks++) {
            uint32_t bh[4][2], bl[4][2];
#pragma unroll
            for (int p = 0; p < 2; p++) {
                int nrow = wn + p * 16 + (lane & 7) + ((lane >> 4) & 1) * 8;
                int c = ks * 2 + ((lane >> 3) & 1);
                uint32_t r[4];
                ldsm4(r, st + 16384 + swz(nrow, c));
                bh[p * 2][0] = r[0]; bh[p * 2][1] = r[1];
                bh[p * 2 + 1][0] = r[2]; bh[p * 2 + 1][1] = r[3];
                ldsm4(r, st + 24576 + swz(nrow, c));
                bl[p * 2][0] = r[0]; bl[p * 2][1] = r[1];
                bl[p * 2 + 1][0] = r[2]; bl[p * 2 + 1][1] = r[3];
            }
#pragma unroll
            for (int mt = 0; mt < 4; mt++) {
                int arow = wm + mt * 16 + (lane & 7) + ((lane >> 3) & 1) * 8;
                int c = ks * 2 + ((lane >> 4) & 1);
                uint32_t ah[4], al[4];
                ldsm4(ah, st + swz(arow, c));
                ldsm4(al, st + 8192 + swz(arow, c));
#pragma unroll
                for (int nt = 0; nt < 4; nt++) {
                    mma_bf16(acc[mt][nt], ah, bh[nt]);
                    mma_bf16(acc[mt][nt], ah, bl[nt]);
                    mma_bf16(acc[mt][nt], al, bh[nt]);
                }
            }
        }
        __syncthreads();
        if (kc + 2 < KTILES) LOAD_STAGE(kc + 2, kc & 1);
    }

    float sc = useScale ? g_sigma[3] : 1.0f;
#pragma unroll
    for (int mt = 0; mt < 4; mt++) {
        int m = m0 + wm + mt * 16 + (lane >> 2);
#pragma unroll
        for (int nt = 0; nt < 4; nt++) {
            int n = n0 + wn + nt * 8 + (lane & 3) * 2;
            float2 v0 = make_float2(acc[mt][nt][0] * sc, acc[mt][nt][1] * sc);
            float2 v1 = make_float2(acc[mt][nt][2] * sc, acc[mt][nt][3] * sc);
            *(float2*)&Cb[(long)m * HW + n] = v0;
            *(float2*)&Cb[(long)(m + 8) * HW + n] = v1;
        }
    }
#undef LOAD_STAGE
}

// ---------------- 3x3 depthwise conv, pad=1 ----------------
__global__ __launch_bounds__(128)
void dwconv(const float* __restrict__ in, const float* __restrict__ w,
            float* __restrict__ out)
{
    int ych = blockIdx.x * 16;
    int ch = blockIdx.y;
    int b = blockIdx.z;
    const float* ip = in + (((long)b * C3 + ch) << 14);
    float* op = out + (((long)b * C3 + ch) << 14);

    __shared__ float rows[18][130];
    int x = threadIdx.x;
#pragma unroll
    for (int r = 0; r < 18; r++) {
        int yy = ych + r - 1;
        rows[r][x + 1] = (yy >= 0 && yy < 128) ? ip[(yy << 7) + x] : 0.f;
        if (x == 0) { rows[r][0] = 0.f; rows[r][129] = 0.f; }
    }
    float w00 = w[ch * 9 + 0], w01 = w[ch * 9 + 1], w02 = w[ch * 9 + 2];
    float w10 = w[ch * 9 + 3], w11 = w[ch * 9 + 4], w12 = w[ch * 9 + 5];
    float w20 = w[ch * 9 + 6], w21 = w[ch * 9 + 7], w22 = w[ch * 9 + 8];
    __syncthreads();

#pragma unroll
    for (int yo = 0; yo < 16; yo++) {
        float s = rows[yo][x]     * w00 + rows[yo][x + 1]     * w01 + rows[yo][x + 2]     * w02
                + rows[yo + 1][x] * w10 + rows[yo + 1][x + 1] * w11 + rows[yo + 1][x + 2] * w12
                + rows[yo + 2][x] * w20 + rows[yo + 2][x + 1] * w21 + rows[yo + 2][x + 2] * w22;
        op[((ych + yo) << 7) + x] = s;
    }
}

// ---------------- per-(b, channel) inverse L2 norm over spatial dim ----------------
__global__ __launch_bounds__(256)
void norm_kernel(const float* __restrict__ t)
{
    int idx = blockIdx.x;
    int b = idx / (2 * DIM), c = idx % (2 * DIM);
    const float4* p = (const float4*)(t + (((long)b * C3 + c) << 14));
    float ss = 0.f;
    for (int i = threadIdx.x; i < HW / 4; i += 256) {
        float4 v = p[i];
        ss += v.x * v.x + v.y * v.y + v.z * v.z + v.w * v.w;
    }
    __shared__ float red[256];
    red[threadIdx.x] = ss; __syncthreads();
    for (int s = 128; s > 0; s >>= 1) {
        if (threadIdx.x < s) red[threadIdx.x] += red[threadIdx.x + s];
        __syncthreads();
    }
    if (threadIdx.x == 0) g_invnorm[idx] = 1.f / fmaxf(sqrtf(red[0]), EPS);
}

// ---------------- raw attention logits (partial over n-chunks) ----------------
__global__ __launch_bounds__(256)
void attn_s(const float* __restrict__ t)
{
    int bh = blockIdx.y;
    int b = bh >> 3, head = bh & 7;
    int n0 = blockIdx.x * (HW / NCHUNKS);
    const float* qp = t + ((((long)b * C3) + head * CH) << 14);
    const float* kp = t + ((((long)b * C3) + DIM + head * CH) << 14);

    __shared__ float qs[32][49];
    __shared__ float ks[32][49];
    int tid = threadIdx.x;
    int ty = tid >> 4, tx = tid & 15;
    float acc[3][3] = {};

    for (int nt = 0; nt < 32; nt++) {
        int nb = n0 + nt * 32;
        for (int i = tid; i < CH * 32; i += 256) {
            int c = i >> 5, nn = i & 31;
            qs[nn][c] = qp[(c << 14) + nb + nn];
            ks[nn][c] = kp[(c << 14) + nb + nn];
        }
        __syncthreads();
#pragma unroll
        for (int nn = 0; nn < 32; nn++) {
            float a0 = qs[nn][ty * 3], a1 = qs[nn][ty * 3 + 1], a2 = qs[nn][ty * 3 + 2];
            float b0 = ks[nn][tx * 3], b1 = ks[nn][tx * 3 + 1], b2 = ks[nn][tx * 3 + 2];
            acc[0][0] = fmaf(a0, b0, acc[0][0]); acc[0][1] = fmaf(a0, b1, acc[0][1]); acc[0][2] = fmaf(a0, b2, acc[0][2]);
            acc[1][0] = fmaf(a1, b0, acc[1][0]); acc[1][1] = fmaf(a1, b1, acc[1][1]); acc[1][2] = fmaf(a1, b2, acc[1][2]);
            acc[2][0] = fmaf(a2, b0, acc[2][0]); acc[2][1] = fmaf(a2, b1, acc[2][1]); acc[2][2] = fmaf(a2, b2, acc[2][2]);
        }
        __syncthreads();
    }

    float* Sp = g_Spart + ((long)blockIdx.x * 32 + bh) * (CH * CH);
#pragma unroll
    for (int i = 0; i < 3; i++)
#pragma unroll
        for (int j = 0; j < 3; j++)
            Sp[(ty * 3 + i) * CH + tx * 3 + j] = acc[i][j];
}

// ---------------- finalize: reduce partials, scale, clamp, softmax ----------------
__global__ __launch_bounds__(64)
void softmax_kernel(const float* __restrict__ temp)
{
    int blk = blockIdx.x;
    int bh = blk / CH, c = blk % CH;
    int b = bh >> 3, head = bh & 7;
    int d = threadIdx.x;
    __shared__ float sm[64];

    float myv = 0.f, val = -1e30f;
    if (d < CH) {
        float raw = 0.f;
#pragma unroll
        for (int ch = 0; ch < NCHUNKS; ch++)
            raw += g_Spart[((long)ch * 32 + bh) * (CH * CH) + c * CH + d];
        float invq = g_invnorm[b * 2 * DIM + head * CH + c];
        float invk = g_invnorm[b * 2 * DIM + DIM + head * CH + d];
        myv = raw * invq * invk * temp[head];
        myv = fminf(fmaxf(myv, -CLAMPV), CLAMPV);
        val = myv;
    }
    sm[d] = val; __syncthreads();
    for (int s = 32; s > 0; s >>= 1) { if (d < s) sm[d] = fmaxf(sm[d], sm[d + s]); __syncthreads(); }
    float m = sm[0]; __syncthreads();
    float e = (d < CH) ? expf(myv - m) : 0.f;
    sm[d] = e; __syncthreads();
    for (int s = 32; s > 0; s >>= 1) { if (d < s) sm[d] += sm[d + s]; __syncthreads(); }
    if (d < CH) g_S[(long)bh * (CH * CH) + c * CH + d] = e / sm[0];
}

// ---------------- out = attn @ v, written TRANSPOSED as bf16 hi/lo [b][n][384] ----------------
__global__ __launch_bounds__(256)
void attn_o(const float* __restrict__ t,
            __nv_bfloat16* __restrict__ aoh, __nv_bfloat16* __restrict__ aol)
{
    int bh = blockIdx.y;
    int b = bh >> 3, head = bh & 7;
    const float* vp = t + ((((long)b * C3) + 2 * DIM + head * CH) << 14);

    __shared__ float Ss[CH * CH];
    for (int i = threadIdx.x; i < CH * CH; i += 256)
        Ss[i] = g_S[(long)bh * (CH * CH) + i];
    __syncthreads();

    int n = blockIdx.x * 512 + threadIdx.x;
    float acc0[CH], acc1[CH];
#pragma unroll
    for (int c = 0; c < CH; c++) { acc0[c] = 0.f; acc1[c] = 0.f; }

    for (int d = 0; d < CH; d++) {
        float v0 = vp[(d << 14) + n];
        float v1 = vp[(d << 14) + n + 256];
#pragma unroll
        for (int c = 0; c < CH; c++) {
            float s = Ss[c * CH + d];
            acc0[c] = fmaf(s, v0, acc0[c]);
            acc1[c] = fmaf(s, v1, acc1[c]);
        }
    }
    long o0 = ((long)b * HW + n) * DIM + head * CH;
    long o1 = ((long)b * HW + n + 256) * DIM + head * CH;
#pragma unroll
    for (int c = 0; c < CH; c += 2) {
        __nv_bfloat16 h0 = __float2bfloat16(acc0[c]);
        __nv_bfloat16 h1 = __float2bfloat16(acc0[c + 1]);
        *(__nv_bfloat162*)&aoh[o0 + c] = __nv_bfloat162(h0, h1);
        *(__nv_bfloat162*)&aol[o0 + c] = __nv_bfloat162(
            __float2bfloat16(acc0[c] - __bfloat162float(h0)),
            __float2bfloat16(acc0[c + 1] - __bfloat162float(h1)));
        __nv_bfloat16 g0 = __float2bfloat16(acc1[c]);
        __nv_bfloat16 g1 = __float2bfloat16(acc1[c + 1]);
        *(__nv_bfloat162*)&aoh[o1 + c] = __nv_bfloat162(g0, g1);
        *(__nv_bfloat162*)&aol[o1 + c] = __nv_bfloat162(
            __float2bfloat16(acc1[c] - __bfloat162float(g0)),
            __float2bfloat16(acc1[c + 1] - __bfloat162float(g1)));
    }
}

// ---------------- launch ----------------
extern "C" void kernel_launch(void* const* d_in, const int* in_sizes, int n_in,
                              void* d_out, int out_size)
{
    const float* x     = (const float*)d_in[0];
    const float* qkvw  = (const float*)d_in[1];
    const float* dww   = (const float*)d_in[2];
    const float* projw = (const float*)d_in[3];
    const float* temp  = (const float*)d_in[4];
    const float* uq    = (const float*)d_in[5];
    const float* ud    = (const float*)d_in[6];
    const float* up    = (const float*)d_in[7];
    float* out = (float*)d_out;

    float *t0, *t1;
    __nv_bfloat16 *xh, *xl, *aoh, *aol, *wqh, *wql, *wph, *wpl;
    cudaGetSymbolAddress((void**)&t0, g_t0);
    cudaGetSymbolAddress((void**)&t1, g_t1);
    cudaGetSymbolAddress((void**)&xh, g_xh);
    cudaGetSymbolAddress((void**)&xl, g_xl);
    cudaGetSymbolAddress((void**)&aoh, g_aoh);
    cudaGetSymbolAddress((void**)&aol, g_aol);
    cudaGetSymbolAddress((void**)&wqh, g_wqh);
    cudaGetSymbolAddress((void**)&wql, g_wql);
    cudaGetSymbolAddress((void**)&wph, g_wph);
    cudaGetSymbolAddress((void**)&wpl, g_wpl);

    cudaFuncSetAttribute(bgemm, cudaFuncAttributeMaxDynamicSharedMemorySize, BG_SMEM);

    // spectral sigmas + combined output scale (scales cancel elsewhere)
    sigma_kernel<<<3, 256>>>(qkvw, dww, projw, uq, ud, up);
    scale_kernel<<<1, 32>>>();

    // bf16 hi/lo splits: weights (K-major already) and x (transpose+split)
    split_w<<<(C3 * DIM + 255) / 256, 256>>>(qkvw, wqh, wql, C3 * DIM);
    split_w<<<(DIM * DIM + 255) / 256, 256>>>(projw, wph, wpl, DIM * DIM);
    xpose_split<<<dim3(HW / 32, DIM / 32, BATCH), 256>>>(x, xh, xl);

    // qkv 1x1 conv via mma.sync bf16-split GEMM -> t0 [b][1152][hw] fp32
    bgemm<<<dim3(HW / 128, C3 / 128, BATCH), 256, BG_SMEM>>>(
        wqh, wql, xh, xl, t0, (long)C3 * HW, 0);

    // 3x3 depthwise conv
    dwconv<<<dim3(8, C3, BATCH), 128>>>(t0, dww, t1);

    // q/k inverse L2 norms
    norm_kernel<<<BATCH * 2 * DIM, 256>>>(t1);

    // attention logits (partials) + softmax
    attn_s<<<dim3(NCHUNKS, BATCH * HEADS), 256>>>(t1);
    softmax_kernel<<<BATCH * HEADS * CH, 64>>>(temp);

    // out = attn @ v, fused transpose+split to bf16
    attn_o<<<dim3(32, BATCH * HEADS), 256>>>(t1, aoh, aol);

    // proj 1x1 conv via mma.sync bf16-split GEMM, with combined sigma scale
    bgemm<<<dim3(HW / 128, DIM / 128, BATCH), 256, BG_SMEM>>>(
        wph, wpl, aoh, aol, out, (long)DIM * HW, 1);
}

// round 6
// speedup vs baseline: 1.8904x; 1.0330x over previous
#include <cuda_runtime.h>
#include <cuda_bf16.h>
#include <math.h>
#include <stdint.h>

#define BATCH 4
#define DIM 384
#define HEADS 8
#define CH 48            // DIM/HEADS
#define HW 16384         // 128*128
#define C3 1152          // 3*DIM
#define EPS 1e-12f
#define CLAMPV 50.0f
#define NCHUNKS 16
#define GK 384           // GEMM K (always DIM)

// ---------------- device scratch ----------------
__device__ float g_t0[BATCH * C3 * HW];        // qkv GEMM output fp32
__device__ float g_t1[BATCH * C3 * HW];        // depthwise output fp32
__device__ float g_sigma[4];
__device__ float g_invnorm[BATCH * 2 * DIM];
__device__ float g_nsqp[BATCH * 2 * DIM * 8];  // per-block ssq partials from dwconv
__device__ float g_Spart[NCHUNKS * BATCH * HEADS * CH * CH];
__device__ float g_S[BATCH * HEADS * CH * CH];
// bf16 split operands (transposed activations: [b][n=hw][k=384])
__device__ __nv_bfloat16 g_xh[(size_t)BATCH * HW * DIM];
__device__ __nv_bfloat16 g_xl[(size_t)BATCH * HW * DIM];
__device__ __nv_bfloat16 g_aoh[(size_t)BATCH * HW * DIM];
__device__ __nv_bfloat16 g_aol[(size_t)BATCH * HW * DIM];
__device__ __nv_bfloat16 g_wqh[C3 * DIM];
__device__ __nv_bfloat16 g_wql[C3 * DIM];
__device__ __nv_bfloat16 g_wph[DIM * DIM];
__device__ __nv_bfloat16 g_wpl[DIM * DIM];

// ---------------- warp-mma helpers (all non-'a' features: sm_80 baseline) ----------------
__device__ __forceinline__ uint32_t smem_u32(const void* p) {
    uint32_t a;
    asm("{ .reg .u64 t; cvta.to.shared.u64 t, %1; cvt.u32.u64 %0, t; }" : "=r"(a) : "l"(p));
    return a;
}
__device__ __forceinline__ void cpasync16(uint32_t s, const void* g) {
    asm volatile("cp.async.cg.shared.global [%0], [%1], 16;" :: "r"(s), "l"(g));
}
#define CP_COMMIT() asm volatile("cp.async.commit_group;" ::: "memory")
#define CP_WAIT2()  asm volatile("cp.async.wait_group 2;" ::: "memory")
#define CP_WAIT0()  asm volatile("cp.async.wait_group 0;" ::: "memory")

__device__ __forceinline__ void ldsm4(uint32_t* r, uint32_t addr) {
    asm volatile("ldmatrix.sync.aligned.m8n8.x4.shared.b16 {%0,%1,%2,%3}, [%4];"
        : "=r"(r[0]), "=r"(r[1]), "=r"(r[2]), "=r"(r[3]) : "r"(addr));
}
__device__ __forceinline__ void mma_bf16(float* c, const uint32_t* a, const uint32_t* b) {
    asm volatile(
        "mma.sync.aligned.m16n8k16.row.col.f32.bf16.bf16.f32 "
        "{%0,%1,%2,%3}, {%4,%5,%6,%7}, {%8,%9}, {%0,%1,%2,%3};"
        : "+f"(c[0]), "+f"(c[1]), "+f"(c[2]), "+f"(c[3])
        : "r"(a[0]), "r"(a[1]), "r"(a[2]), "r"(a[3]), "r"(b[0]), "r"(b[1]));
}

// swizzled smem offset for an R-row x 32-bf16 (64B) tile packed 2 rows/128B line.
// 8 distinct 16B phases across any 8 consecutive rows at fixed chunk.
__device__ __forceinline__ uint32_t swz(uint32_t row, uint32_t c) {
    return (row >> 1) * 128 + ((((row & 1) * 4 + c) ^ ((row >> 1) & 7)) * 16);
}

// ---------------- spectral sigma ----------------
__global__ void sigma_kernel(const float* __restrict__ qkvw,
                             const float* __restrict__ dww,
                             const float* __restrict__ projw,
                             const float* __restrict__ uq,
                             const float* __restrict__ ud,
                             const float* __restrict__ up)
{
    int which = blockIdx.x;
    const float* wm; const float* u; int h, w;
    if (which == 0)      { wm = qkvw;  u = uq; h = C3;  w = DIM; }
    else if (which == 1) { wm = dww;   u = ud; h = C3;  w = 9;   }
    else                 { wm = projw; u = up; h = DIM; w = DIM; }

    __shared__ float v[DIM];
    __shared__ float red[256];
    int tid = threadIdx.x;

    for (int j = tid; j < w; j += 256) {
        float s = 0.f;
        for (int i = 0; i < h; i++) s += wm[i * w + j] * u[i];
        v[j] = s;
    }
    __syncthreads();

    float ss = 0.f;
    for (int j = tid; j < w; j += 256) ss += v[j] * v[j];
    red[tid] = ss; __syncthreads();
    for (int s = 128; s > 0; s >>= 1) { if (tid < s) red[tid] += red[tid + s]; __syncthreads(); }
    float vinv = 1.f / fmaxf(sqrtf(red[0]), EPS);
    __syncthreads();
    for (int j = tid; j < w; j += 256) v[j] *= vinv;
    __syncthreads();

    float ss2 = 0.f;
    for (int i = tid; i < h; i += 256) {
        float s = 0.f;
        for (int j = 0; j < w; j++) s += wm[i * w + j] * v[j];
        ss2 += s * s;
    }
    red[tid] = ss2; __syncthreads();
    for (int s = 128; s > 0; s >>= 1) { if (tid < s) red[tid] += red[tid + s]; __syncthreads(); }
    if (tid == 0) {
        float sq = red[0];
        g_sigma[which] = sq / fmaxf(sqrtf(sq), EPS);
    }
}

__global__ void scale_kernel()
{
    if (threadIdx.x == 0) {
        float s = 1.f;
        s /= (g_sigma[0] + EPS);
        s /= (g_sigma[1] + EPS);
        s /= (g_sigma[2] + EPS);
        g_sigma[3] = s;
    }
}

// ---------------- fp32 -> bf16 hi/lo split (weights, K-major already) ----------------
__global__ __launch_bounds__(256)
void split_w(const float* __restrict__ w, __nv_bfloat16* __restrict__ h,
             __nv_bfloat16* __restrict__ l, int n)
{
    int i = blockIdx.x * 256 + threadIdx.x;
    if (i < n) {
        float v = w[i];
        __nv_bfloat16 hi = __float2bfloat16(v);
        h[i] = hi;
        l[i] = __float2bfloat16(v - __bfloat162float(hi));
    }
}

// ---------------- transpose + split: x [b][c=384][hw] -> xh/xl [b][hw][384] ----------------
__global__ __launch_bounds__(256)
void xpose_split(const float* __restrict__ x, __nv_bfloat16* __restrict__ xh,
                 __nv_bfloat16* __restrict__ xl)
{
    __shared__ float t[32][33];
    int hw0 = blockIdx.x << 5, c0 = blockIdx.y << 5, b = blockIdx.z;
    int tx = threadIdx.x & 31, ty = threadIdx.x >> 5;
#pragma unroll
    for (int i = 0; i < 4; i++)
        t[ty + i * 8][tx] = x[(((long)b * DIM + c0 + ty + i * 8) << 14) + hw0 + tx];
    __syncthreads();
#pragma unroll
    for (int i = 0; i < 4; i++) {
        int n = hw0 + ty + i * 8;
        float v = t[tx][ty + i * 8];
        __nv_bfloat16 hi = __float2bfloat16(v);
        long o = ((long)b * HW + n) * DIM + c0 + tx;
        xh[o] = hi;
        xl[o] = __float2bfloat16(v - __bfloat162float(hi));
    }
}

// ---------------- bf16-split GEMM via mma.sync ----------------
// C[b][m][n] = sum_k A[m][k]*B[b][n][k];  A [Mtot][384] hi/lo, B [b][16384][384] hi/lo.
// Block 128x256x32, 8 warps (2Mx4N), warp tile 64x64, cp.async 3-stage.
// Stage: Ah|Al (8KB each) + Bh|Bl (16KB each) = 48KB; 3 stages = 144KB.
#define BG_STAGE 49152
#define BG_SMEM (3 * BG_STAGE)
#define KTILES (GK / 32)

__global__ void __launch_bounds__(256)
bgemm(const __nv_bfloat16* __restrict__ Ah, const __nv_bfloat16* __restrict__ Al,
      const __nv_bfloat16* __restrict__ Bh, const __nv_bfloat16* __restrict__ Bl,
      float* __restrict__ C, long strideC, int useScale)
{
    extern __shared__ char smem[];
    uint32_t sb = smem_u32(smem);
    int tid = threadIdx.x, wid = tid >> 5, lane = tid & 31;
    int n0 = blockIdx.x << 8, m0 = blockIdx.y << 7, bz = blockIdx.z;
    int wm = (wid >> 2) * 64;      // warp m offset in block
    int wn = (wid & 3) * 64;       // warp n offset in block

    const __nv_bfloat16* ahp = Ah + (long)m0 * GK;
    const __nv_bfloat16* alp = Al + (long)m0 * GK;
    const __nv_bfloat16* bhp = Bh + (long)bz * HW * DIM + (long)n0 * GK;
    const __nv_bfloat16* blp = Bl + (long)bz * HW * DIM + (long)n0 * GK;
    float* Cb = C + (long)bz * strideC;

    float acc[4][8][4];
#pragma unroll
    for (int i = 0; i < 4; i++)
#pragma unroll
        for (int j = 0; j < 8; j++)
#pragma unroll
            for (int k = 0; k < 4; k++) acc[i][j][k] = 0.f;

    int lrow = tid >> 2, lc = tid & 3;   // loader row/chunk

#define LOAD_STAGE(kc) do { \
        int _k0 = (kc) << 5; \
        uint32_t _sb = sb + ((kc) % 3) * BG_STAGE; \
        _Pragma("unroll") \
        for (int _i = 0; _i < 2; _i++) { \
            int _row = (_i << 6) + lrow; \
            long _go = (long)_row * GK + _k0 + lc * 8; \
            cpasync16(_sb + swz(_row, lc), ahp + _go); \
            cpasync16(_sb + 8192 + swz(_row, lc), alp + _go); \
        } \
        _Pragma("unroll") \
        for (int _i = 0; _i < 4; _i++) { \
            int _row = (_i << 6) + lrow; \
            long _go = (long)_row * GK + _k0 + lc * 8; \
            cpasync16(_sb + 16384 + swz(_row, lc), bhp + _go); \
            cpasync16(_sb + 32768 + swz(_row, lc), blp + _go); \
        } \
        CP_COMMIT(); \
    } while (0)

    LOAD_STAGE(0);
    LOAD_STAGE(1);

    for (int kc = 0; kc < KTILES; kc++) {
        if (kc + 2 < KTILES) { LOAD_STAGE(kc + 2); CP_WAIT2(); }
        else                 { CP_WAIT0(); }
        __syncthreads();

        uint32_t st = sb + (kc % 3) * BG_STAGE;
#pragma unroll
        for (int ks = 0; ks < 2; ks++) {
            uint32_t bh[8][2], bl[8][2];
#pragma unroll
            for (int p = 0; p < 4; p++) {
                int nrow = wn + p * 16 + (lane & 7) + ((lane >> 4) & 1) * 8;
                int c = ks * 2 + ((lane >> 3) & 1);
                uint32_t r[4];
                ldsm4(r, st + 16384 + swz(nrow, c));
                bh[p * 2][0] = r[0]; bh[p * 2][1] = r[1];
                bh[p * 2 + 1][0] = r[2]; bh[p * 2 + 1][1] = r[3];
                ldsm4(r, st + 32768 + swz(nrow, c));
                bl[p * 2][0] = r[0]; bl[p * 2][1] = r[1];
                bl[p * 2 + 1][0] = r[2]; bl[p * 2 + 1][1] = r[3];
            }
#pragma unroll
            for (int mt = 0; mt < 4; mt++) {
                int arow = wm + mt * 16 + (lane & 7) + ((lane >> 3) & 1) * 8;
                int c = ks * 2 + ((lane >> 4) & 1);
                uint32_t ah[4], al[4];
                ldsm4(ah, st + swz(arow, c));
                ldsm4(al, st + 8192 + swz(arow, c));
#pragma unroll
                for (int nt = 0; nt < 8; nt++) {
                    mma_bf16(acc[mt][nt], ah, bh[nt]);
                    mma_bf16(acc[mt][nt], ah, bl[nt]);
                    mma_bf16(acc[mt][nt], al, bh[nt]);
                }
            }
        }
        __syncthreads();
    }

    float sc = useScale ? g_sigma[3] : 1.0f;
#pragma unroll
    for (int mt = 0; mt < 4; mt++) {
        int m = m0 + wm + mt * 16 + (lane >> 2);
#pragma unroll
        for (int nt = 0; nt < 8; nt++) {
            int n = n0 + wn + nt * 8 + (lane & 3) * 2;
            float2 v0 = make_float2(acc[mt][nt][0] * sc, acc[mt][nt][1] * sc);
            float2 v1 = make_float2(acc[mt][nt][2] * sc, acc[mt][nt][3] * sc);
            *(float2*)&Cb[(long)m * HW + n] = v0;
            *(float2*)&Cb[(long)(m + 8) * HW + n] = v1;
        }
    }
#undef LOAD_STAGE
}

// ---------------- 3x3 depthwise conv, pad=1, fused q/k ssq partials ----------------
__global__ __launch_bounds__(128)
void dwconv(const float* __restrict__ in, const float* __restrict__ w,
            float* __restrict__ out)
{
    int ych = blockIdx.x * 16;
    int ch = blockIdx.y;
    int b = blockIdx.z;
    const float* ip = in + (((long)b * C3 + ch) << 14);
    float* op = out + (((long)b * C3 + ch) << 14);

    __shared__ float rows[18][130];
    int x = threadIdx.x;
#pragma unroll
    for (int r = 0; r < 18; r++) {
        int yy = ych + r - 1;
        rows[r][x + 1] = (yy >= 0 && yy < 128) ? ip[(yy << 7) + x] : 0.f;
        if (x == 0) { rows[r][0] = 0.f; rows[r][129] = 0.f; }
    }
    float w00 = w[ch * 9 + 0], w01 = w[ch * 9 + 1], w02 = w[ch * 9 + 2];
    float w10 = w[ch * 9 + 3], w11 = w[ch * 9 + 4], w12 = w[ch * 9 + 5];
    float w20 = w[ch * 9 + 6], w21 = w[ch * 9 + 7], w22 = w[ch * 9 + 8];
    __syncthreads();

    float ssq = 0.f;
#pragma unroll
    for (int yo = 0; yo < 16; yo++) {
        float s = rows[yo][x]     * w00 + rows[yo][x + 1]     * w01 + rows[yo][x + 2]     * w02
                + rows[yo + 1][x] * w10 + rows[yo + 1][x + 1] * w11 + rows[yo + 1][x + 2] * w12
                + rows[yo + 2][x] * w20 + rows[yo + 2][x + 1] * w21 + rows[yo + 2][x + 2] * w22;
        op[((ych + yo) << 7) + x] = s;
        ssq += s * s;
    }

    // ssq partial for q/k channels only (ch < 768)
    if (ch < 2 * DIM) {
        __shared__ float red[128];
        red[x] = ssq; __syncthreads();
        for (int s = 64; s > 0; s >>= 1) {
            if (x < s) red[x] += red[x + s];
            __syncthreads();
        }
        if (x == 0) g_nsqp[((b * 2 * DIM + ch) << 3) + blockIdx.x] = red[0];
    }
}

// reduce 8 partials per (b, q/k channel) -> inverse L2 norm
__global__ __launch_bounds__(256)
void norm_finish()
{
    int i = blockIdx.x * 256 + threadIdx.x;
    if (i < BATCH * 2 * DIM) {
        float s = 0.f;
#pragma unroll
        for (int j = 0; j < 8; j++) s += g_nsqp[(i << 3) + j];
        g_invnorm[i] = 1.f / fmaxf(sqrtf(s), EPS);
    }
}

// ---------------- raw attention logits (partial over n-chunks) ----------------
__global__ __launch_bounds__(256)
void attn_s(const float* __restrict__ t)
{
    int bh = blockIdx.y;
    int b = bh >> 3, head = bh & 7;
    int n0 = blockIdx.x * (HW / NCHUNKS);
    const float* qp = t + ((((long)b * C3) + head * CH) << 14);
    const float* kp = t + ((((long)b * C3) + DIM + head * CH) << 14);

    __shared__ float qs[32][49];
    __shared__ float ks[32][49];
    int tid = threadIdx.x;
    int ty = tid >> 4, tx = tid & 15;
    float acc[3][3] = {};

    for (int nt = 0; nt < 32; nt++) {
        int nb = n0 + nt * 32;
        for (int i = tid; i < CH * 32; i += 256) {
            int c = i >> 5, nn = i & 31;
            qs[nn][c] = qp[(c << 14) + nb + nn];
            ks[nn][c] = kp[(c << 14) + nb + nn];
        }
        __syncthreads();
#pragma unroll
        for (int nn = 0; nn < 32; nn++) {
            float a0 = qs[nn][ty * 3], a1 = qs[nn][ty * 3 + 1], a2 = qs[nn][ty * 3 + 2];
            float b0 = ks[nn][tx * 3], b1 = ks[nn][tx * 3 + 1], b2 = ks[nn][tx * 3 + 2];
            acc[0][0] = fmaf(a0, b0, acc[0][0]); acc[0][1] = fmaf(a0, b1, acc[0][1]); acc[0][2] = fmaf(a0, b2, acc[0][2]);
            acc[1][0] = fmaf(a1, b0, acc[1][0]); acc[1][1] = fmaf(a1, b1, acc[1][1]); acc[1][2] = fmaf(a1, b2, acc[1][2]);
            acc[2][0] = fmaf(a2, b0, acc[2][0]); acc[2][1] = fmaf(a2, b1, acc[2][1]); acc[2][2] = fmaf(a2, b2, acc[2][2]);
        }
        __syncthreads();
    }

    float* Sp = g_Spart + ((long)blockIdx.x * 32 + bh) * (CH * CH);
#pragma unroll
    for (int i = 0; i < 3; i++)
#pragma unroll
        for (int j = 0; j < 3; j++)
            Sp[(ty * 3 + i) * CH + tx * 3 + j] = acc[i][j];
}

// ---------------- finalize: reduce partials, scale, clamp, softmax ----------------
__global__ __launch_bounds__(64)
void softmax_kernel(const float* __restrict__ temp)
{
    int blk = blockIdx.x;
    int bh = blk / CH, c = blk % CH;
    int b = bh >> 3, head = bh & 7;
    int d = threadIdx.x;
    __shared__ float sm[64];

    float myv = 0.f, val = -1e30f;
    if (d < CH) {
        float raw = 0.f;
#pragma unroll
        for (int ch = 0; ch < NCHUNKS; ch++)
            raw += g_Spart[((long)ch * 32 + bh) * (CH * CH) + c * CH + d];
        float invq = g_invnorm[b * 2 * DIM + head * CH + c];
        float invk = g_invnorm[b * 2 * DIM + DIM + head * CH + d];
        myv = raw * invq * invk * temp[head];
        myv = fminf(fmaxf(myv, -CLAMPV), CLAMPV);
        val = myv;
    }
    sm[d] = val; __syncthreads();
    for (int s = 32; s > 0; s >>= 1) { if (d < s) sm[d] = fmaxf(sm[d], sm[d + s]); __syncthreads(); }
    float m = sm[0]; __syncthreads();
    float e = (d < CH) ? expf(myv - m) : 0.f;
    sm[d] = e; __syncthreads();
    for (int s = 32; s > 0; s >>= 1) { if (d < s) sm[d] += sm[d + s]; __syncthreads(); }
    if (d < CH) g_S[(long)bh * (CH * CH) + c * CH + d] = e / sm[0];
}

// ---------------- out = attn @ v, written TRANSPOSED as bf16 hi/lo [b][n][384] ----------------
__global__ __launch_bounds__(256)
void attn_o(const float* __restrict__ t,
            __nv_bfloat16* __restrict__ aoh, __nv_bfloat16* __restrict__ aol)
{
    int bh = blockIdx.y;
    int b = bh >> 3, head = bh & 7;
    const float* vp = t + ((((long)b * C3) + 2 * DIM + head * CH) << 14);

    __shared__ float Ss[CH * CH];
    for (int i = threadIdx.x; i < CH * CH; i += 256)
        Ss[i] = g_S[(long)bh * (CH * CH) + i];
    __syncthreads();

    int n = blockIdx.x * 512 + threadIdx.x;
    float acc0[CH], acc1[CH];
#pragma unroll
    for (int c = 0; c < CH; c++) { acc0[c] = 0.f; acc1[c] = 0.f; }

    for (int d = 0; d < CH; d++) {
        float v0 = vp[(d << 14) + n];
        float v1 = vp[(d << 14) + n + 256];
#pragma unroll
        for (int c = 0; c < CH; c++) {
            float s = Ss[c * CH + d];
            acc0[c] = fmaf(s, v0, acc0[c]);
            acc1[c] = fmaf(s, v1, acc1[c]);
        }
    }
    long o0 = ((long)b * HW + n) * DIM + head * CH;
    long o1 = ((long)b * HW + n + 256) * DIM + head * CH;
#pragma unroll
    for (int c = 0; c < CH; c += 2) {
        __nv_bfloat16 h0 = __float2bfloat16(acc0[c]);
        __nv_bfloat16 h1 = __float2bfloat16(acc0[c + 1]);
        *(__nv_bfloat162*)&aoh[o0 + c] = __nv_bfloat162(h0, h1);
        *(__nv_bfloat162*)&aol[o0 + c] = __nv_bfloat162(
            __float2bfloat16(acc0[c] - __bfloat162float(h0)),
            __float2bfloat16(acc0[c + 1] - __bfloat162float(h1)));
        __nv_bfloat16 g0 = __float2bfloat16(acc1[c]);
        __nv_bfloat16 g1 = __float2bfloat16(acc1[c + 1]);
        *(__nv_bfloat162*)&aoh[o1 + c] = __nv_bfloat162(g0, g1);
        *(__nv_bfloat162*)&aol[o1 + c] = __nv_bfloat162(
            __float2bfloat16(acc1[c] - __bfloat162float(g0)),
            __float2bfloat16(acc1[c + 1] - __bfloat162float(g1)));
    }
}

// ---------------- launch ----------------
extern "C" void kernel_launch(void* const* d_in, const int* in_sizes, int n_in,
                              void* d_out, int out_size)
{
    const float* x     = (const float*)d_in[0];
    const float* qkvw  = (const float*)d_in[1];
    const float* dww   = (const float*)d_in[2];
    const float* projw = (const float*)d_in[3];
    const float* temp  = (const float*)d_in[4];
    const float* uq    = (const float*)d_in[5];
    const float* ud    = (const float*)d_in[6];
    const float* up    = (const float*)d_in[7];
    float* out = (float*)d_out;

    float *t0, *t1;
    __nv_bfloat16 *xh, *xl, *aoh, *aol, *wqh, *wql, *wph, *wpl;
    cudaGetSymbolAddress((void**)&t0, g_t0);
    cudaGetSymbolAddress((void**)&t1, g_t1);
    cudaGetSymbolAddress((void**)&xh, g_xh);
    cudaGetSymbolAddress((void**)&xl, g_xl);
    cudaGetSymbolAddress((void**)&aoh, g_aoh);
    cudaGetSymbolAddress((void**)&aol, g_aol);
    cudaGetSymbolAddress((void**)&wqh, g_wqh);
    cudaGetSymbolAddress((void**)&wql, g_wql);
    cudaGetSymbolAddress((void**)&wph, g_wph);
    cudaGetSymbolAddress((void**)&wpl, g_wpl);

    cudaFuncSetAttribute(bgemm, cudaFuncAttributeMaxDynamicSharedMemorySize, BG_SMEM);

    // spectral sigmas + combined output scale (scales cancel elsewhere)
    sigma_kernel<<<3, 256>>>(qkvw, dww, projw, uq, ud, up);
    scale_kernel<<<1, 32>>>();

    // bf16 hi/lo splits: weights (K-major already) and x (transpose+split)
    split_w<<<(C3 * DIM + 255) / 256, 256>>>(qkvw, wqh, wql, C3 * DIM);
    split_w<<<(DIM * DIM + 255) / 256, 256>>>(projw, wph, wpl, DIM * DIM);
    xpose_split<<<dim3(HW / 32, DIM / 32, BATCH), 256>>>(x, xh, xl);

    // qkv 1x1 conv via mma.sync bf16-split GEMM -> t0 [b][1152][hw] fp32
    bgemm<<<dim3(HW / 256, C3 / 128, BATCH), 256, BG_SMEM>>>(
        wqh, wql, xh, xl, t0, (long)C3 * HW, 0);

    // 3x3 depthwise conv with fused q/k ssq partials
    dwconv<<<dim3(8, C3, BATCH), 128>>>(t0, dww, t1);
    norm_finish<<<(BATCH * 2 * DIM + 255) / 256, 256>>>();

    // attention logits (partials) + softmax
    attn_s<<<dim3(NCHUNKS, BATCH * HEADS), 256>>>(t1);
    softmax_kernel<<<BATCH * HEADS * CH, 64>>>(temp);

    // out = attn @ v, fused transpose+split to bf16
    attn_o<<<dim3(32, BATCH * HEADS), 256>>>(t1, aoh, aol);

    // proj 1x1 conv via mma.sync bf16-split GEMM, with combined sigma scale
    bgemm<<<dim3(HW / 256, DIM / 128, BATCH), 256, BG_SMEM>>>(
        wph, wpl, aoh, aol, out, (long)DIM * HW, 1);
}

// round 7
// speedup vs baseline: 2.3935x; 1.2661x over previous
#include <cuda_runtime.h>
#include <cuda_bf16.h>
#include <math.h>
#include <stdint.h>

#define BATCH 4
#define DIM 384
#define HEADS 8
#define CH 48            // DIM/HEADS
#define HW 16384         // 128*128
#define C3 1152          // 3*DIM
#define EPS 1e-12f
#define CLAMPV 50.0f
#define NCHUNKS 16
#define GK 384           // GEMM K (always DIM)

// ---------------- device scratch ----------------
__device__ float g_t0[BATCH * C3 * HW];        // qkv GEMM output fp32
__device__ float g_t1[BATCH * C3 * HW];        // depthwise output fp32
__device__ float g_sigma[4];
__device__ float g_invnorm[BATCH * 2 * DIM];
__device__ float g_Spart[NCHUNKS * BATCH * HEADS * CH * CH];
__device__ float g_S[BATCH * HEADS * CH * CH];
// sigma pipeline scratch
__device__ float g_vpart[3][8][DIM];
__device__ float g_v[3][DIM];
__device__ float g_wvpart[3][18];
// bf16 split operands (transposed activations: [b][n=hw][k=384])
__device__ __nv_bfloat16 g_xh[(size_t)BATCH * HW * DIM];
__device__ __nv_bfloat16 g_xl[(size_t)BATCH * HW * DIM];
__device__ __nv_bfloat16 g_aoh[(size_t)BATCH * HW * DIM];
__device__ __nv_bfloat16 g_aol[(size_t)BATCH * HW * DIM];
__device__ __nv_bfloat16 g_wqh[C3 * DIM];
__device__ __nv_bfloat16 g_wql[C3 * DIM];
__device__ __nv_bfloat16 g_wph[DIM * DIM];
__device__ __nv_bfloat16 g_wpl[DIM * DIM];

// ---------------- warp-mma helpers (all non-'a' features: sm_80 baseline) ----------------
__device__ __forceinline__ uint32_t smem_u32(const void* p) {
    uint32_t a;
    asm("{ .reg .u64 t; cvta.to.shared.u64 t, %1; cvt.u32.u64 %0, t; }" : "=r"(a) : "l"(p));
    return a;
}
__device__ __forceinline__ void cpasync16(uint32_t s, const void* g) {
    asm volatile("cp.async.cg.shared.global [%0], [%1], 16;" :: "r"(s), "l"(g));
}
#define CP_COMMIT() asm volatile("cp.async.commit_group;" ::: "memory")
#define CP_WAIT2()  asm volatile("cp.async.wait_group 2;" ::: "memory")
#define CP_WAIT0()  asm volatile("cp.async.wait_group 0;" ::: "memory")

__device__ __forceinline__ void ldsm4(uint32_t* r, uint32_t addr) {
    asm volatile("ldmatrix.sync.aligned.m8n8.x4.shared.b16 {%0,%1,%2,%3}, [%4];"
        : "=r"(r[0]), "=r"(r[1]), "=r"(r[2]), "=r"(r[3]) : "r"(addr));
}
__device__ __forceinline__ void mma_bf16(float* c, const uint32_t* a, const uint32_t* b) {
    asm volatile(
        "mma.sync.aligned.m16n8k16.row.col.f32.bf16.bf16.f32 "
        "{%0,%1,%2,%3}, {%4,%5,%6,%7}, {%8,%9}, {%0,%1,%2,%3};"
        : "+f"(c[0]), "+f"(c[1]), "+f"(c[2]), "+f"(c[3])
        : "r"(a[0]), "r"(a[1]), "r"(a[2]), "r"(a[3]), "r"(b[0]), "r"(b[1]));
}

// swizzled smem offset for an R-row x 32-bf16 (64B) tile packed 2 rows/128B line.
__device__ __forceinline__ uint32_t swz(uint32_t row, uint32_t c) {
    return (row >> 1) * 128 + ((((row & 1) * 4 + c) ^ ((row >> 1) & 7)) * 16);
}

// ---------------- sigma pipeline ----------------
// stage 1: partial v = wm^T u over i-chunks. grid (3, 8), block 256
__global__ __launch_bounds__(256)
void sigma_v(const float* __restrict__ qkvw, const float* __restrict__ dww,
             const float* __restrict__ projw, const float* __restrict__ uq,
             const float* __restrict__ ud, const float* __restrict__ up)
{
    int which = blockIdx.x, ic = blockIdx.y;
    const float* wm; const float* u; int h, w;
    if (which == 0)      { wm = qkvw;  u = uq; h = C3;  w = DIM; }
    else if (which == 1) { wm = dww;   u = ud; h = C3;  w = 9;   }
    else                 { wm = projw; u = up; h = DIM; w = DIM; }
    int chunk = h >> 3;
    int i0 = ic * chunk, i1 = i0 + chunk;
    for (int j = threadIdx.x; j < w; j += 256) {
        float s = 0.f;
        for (int i = i0; i < i1; i++) s += wm[i * w + j] * u[i];
        g_vpart[which][ic][j] = s;
    }
}

// stage 2: reduce partials, normalize v. grid 3, block 256
__global__ __launch_bounds__(256)
void sigma_vfin(int dummy)
{
    int which = blockIdx.x;
    int w = (which == 1) ? 9 : DIM;
    int tid = threadIdx.x;
    __shared__ float red[256];
    float ss = 0.f;
    for (int j = tid; j < w; j += 256) {
        float v = 0.f;
#pragma unroll
        for (int ic = 0; ic < 8; ic++) v += g_vpart[which][ic][j];
        g_v[which][j] = v;
        ss += v * v;
    }
    red[tid] = ss; __syncthreads();
    for (int s = 128; s > 0; s >>= 1) { if (tid < s) red[tid] += red[tid + s]; __syncthreads(); }
    float vinv = 1.f / fmaxf(sqrtf(red[0]), EPS);
    for (int j = tid; j < w; j += 256) g_v[which][j] *= vinv;
}

// stage 3: partial ||wm v||^2 over 64-row chunks. grid (3, 18), block 256 (64 rows x 4 segs)
__global__ __launch_bounds__(256)
void sigma_wv(const float* __restrict__ qkvw, const float* __restrict__ dww,
              const float* __restrict__ projw)
{
    int which = blockIdx.x;
    const float* wm; int h, w;
    if (which == 0)      { wm = qkvw;  h = C3;  w = DIM; }
    else if (which == 1) { wm = dww;   h = C3;  w = 9;   }
    else                 { wm = projw; h = DIM; w = DIM; }
    int r = threadIdx.x >> 2, seg = threadIdx.x & 3;
    int i = blockIdx.y * 64 + r;
    if (blockIdx.y * 64 >= h) return;

    float s = 0.f;
    if (i < h) {
        int j0 = seg * (w / 4), j1 = (seg + 1) * (w / 4);
        if (w == 9) { j0 = (seg == 0) ? 0 : 9; j1 = 9; }
        for (int j = j0; j < j1; j++) s += wm[i * w + j] * g_v[which][j];
    }
    s += __shfl_xor_sync(0xffffffff, s, 1);
    s += __shfl_xor_sync(0xffffffff, s, 2);
    float ssq = (seg == 0 && i < h) ? s * s : 0.f;

    __shared__ float red[256];
    red[threadIdx.x] = ssq; __syncthreads();
    for (int st = 128; st > 0; st >>= 1) {
        if (threadIdx.x < st) red[threadIdx.x] += red[threadIdx.x + st];
        __syncthreads();
    }
    if (threadIdx.x == 0) g_wvpart[which][blockIdx.y] = red[0];
}

// stage 4: sigma + combined scale. 1 block
__global__ void scale_kernel()
{
    if (threadIdx.x == 0) {
        float comb = 1.f;
        int np[3] = {18, 18, 6};
        for (int which = 0; which < 3; which++) {
            float s = 0.f;
            for (int j = 0; j < np[which]; j++) s += g_wvpart[which][j];
            float sig = s / fmaxf(sqrtf(s), EPS);
            comb /= (sig + EPS);
        }
        g_sigma[3] = comb;
    }
}

// ---------------- fp32 -> bf16 hi/lo split (weights, K-major already) ----------------
__global__ __launch_bounds__(256)
void split_w(const float* __restrict__ w, __nv_bfloat16* __restrict__ h,
             __nv_bfloat16* __restrict__ l, int n)
{
    int i = blockIdx.x * 256 + threadIdx.x;
    if (i < n) {
        float v = w[i];
        __nv_bfloat16 hi = __float2bfloat16(v);
        h[i] = hi;
        l[i] = __float2bfloat16(v - __bfloat162float(hi));
    }
}

// ---------------- transpose + split: x [b][c=384][hw] -> xh/xl [b][hw][384] ----------------
// tile 64c x 32hw, grid (512, 6, 4), block 256; writes 128B/warp coalesced bf162
__global__ __launch_bounds__(256)
void xpose_split(const float* __restrict__ x, __nv_bfloat16* __restrict__ xh,
                 __nv_bfloat16* __restrict__ xl)
{
    __shared__ float t[64][33];
    int hw0 = blockIdx.x << 5, c0 = blockIdx.y << 6, b = blockIdx.z;
    int tx = threadIdx.x & 31, ty = threadIdx.x >> 5;
#pragma unroll
    for (int i = 0; i < 8; i++) {
        int c = ty + i * 8;
        t[c][tx] = x[(((long)b * DIM + c0 + c) << 14) + hw0 + tx];
    }
    __syncthreads();
#pragma unroll
    for (int i = 0; i < 4; i++) {
        int row = ty * 4 + i;
        float v0 = t[tx * 2][row], v1 = t[tx * 2 + 1][row];
        __nv_bfloat16 h0 = __float2bfloat16(v0);
        __nv_bfloat16 h1 = __float2bfloat16(v1);
        long o = ((long)b * HW + hw0 + row) * DIM + c0 + tx * 2;
        *(__nv_bfloat162*)&xh[o] = __nv_bfloat162(h0, h1);
        *(__nv_bfloat162*)&xl[o] = __nv_bfloat162(
            __float2bfloat16(v0 - __bfloat162float(h0)),
            __float2bfloat16(v1 - __bfloat162float(h1)));
    }
}

// ---------------- bf16-split GEMM via mma.sync ----------------
// Block 128x256x32, 8 warps (2Mx4N), warp tile 64x64, cp.async 3-stage.
// grid (Mtiles, Ntiles=64, BATCH): m fastest so consecutive CTAs share B tile in L2.
#define BG_STAGE 49152
#define BG_SMEM (3 * BG_STAGE)
#define KTILES (GK / 32)

__global__ void __launch_bounds__(256)
bgemm(const __nv_bfloat16* __restrict__ Ah, const __nv_bfloat16* __restrict__ Al,
      const __nv_bfloat16* __restrict__ Bh, const __nv_bfloat16* __restrict__ Bl,
      float* __restrict__ C, long strideC, int useScale)
{
    extern __shared__ char smem[];
    uint32_t sb = smem_u32(smem);
    int tid = threadIdx.x, wid = tid >> 5, lane = tid & 31;
    int m0 = blockIdx.x << 7, n0 = blockIdx.y << 8, bz = blockIdx.z;
    int wm = (wid >> 2) * 64;
    int wn = (wid & 3) * 64;

    const __nv_bfloat16* ahp = Ah + (long)m0 * GK;
    const __nv_bfloat16* alp = Al + (long)m0 * GK;
    const __nv_bfloat16* bhp = Bh + (long)bz * HW * DIM + (long)n0 * GK;
    const __nv_bfloat16* blp = Bl + (long)bz * HW * DIM + (long)n0 * GK;
    float* Cb = C + (long)bz * strideC;

    float acc[4][8][4];
#pragma unroll
    for (int i = 0; i < 4; i++)
#pragma unroll
        for (int j = 0; j < 8; j++)
#pragma unroll
            for (int k = 0; k < 4; k++) acc[i][j][k] = 0.f;

    int lrow = tid >> 2, lc = tid & 3;

#define LOAD_STAGE(kc) do { \
        int _k0 = (kc) << 5; \
        uint32_t _sb = sb + ((kc) % 3) * BG_STAGE; \
        _Pragma("unroll") \
        for (int _i = 0; _i < 2; _i++) { \
            int _row = (_i << 6) + lrow; \
            long _go = (long)_row * GK + _k0 + lc * 8; \
            cpasync16(_sb + swz(_row, lc), ahp + _go); \
            cpasync16(_sb + 8192 + swz(_row, lc), alp + _go); \
        } \
        _Pragma("unroll") \
        for (int _i = 0; _i < 4; _i++) { \
            int _row = (_i << 6) + lrow; \
            long _go = (long)_row * GK + _k0 + lc * 8; \
            cpasync16(_sb + 16384 + swz(_row, lc), bhp + _go); \
            cpasync16(_sb + 32768 + swz(_row, lc), blp + _go); \
        } \
        CP_COMMIT(); \
    } while (0)

    LOAD_STAGE(0);
    LOAD_STAGE(1);

    for (int kc = 0; kc < KTILES; kc++) {
        if (kc + 2 < KTILES) { LOAD_STAGE(kc + 2); CP_WAIT2(); }
        else                 { CP_WAIT0(); }
        __syncthreads();

        uint32_t st = sb + (kc % 3) * BG_STAGE;
#pragma unroll
        for (int ks = 0; ks < 2; ks++) {
            uint32_t bh[8][2], bl[8][2];
#pragma unroll
            for (int p = 0; p < 4; p++) {
                int nrow = wn + p * 16 + (lane & 7) + ((lane >> 4) & 1) * 8;
                int c = ks * 2 + ((lane >> 3) & 1);
                uint32_t r[4];
                ldsm4(r, st + 16384 + swz(nrow, c));
                bh[p * 2][0] = r[0]; bh[p * 2][1] = r[1];
                bh[p * 2 + 1][0] = r[2]; bh[p * 2 + 1][1] = r[3];
                ldsm4(r, st + 32768 + swz(nrow, c));
                bl[p * 2][0] = r[0]; bl[p * 2][1] = r[1];
                bl[p * 2 + 1][0] = r[2]; bl[p * 2 + 1][1] = r[3];
            }
#pragma unroll
            for (int mt = 0; mt < 4; mt++) {
                int arow = wm + mt * 16 + (lane & 7) + ((lane >> 3) & 1) * 8;
                int c = ks * 2 + ((lane >> 4) & 1);
                uint32_t ah[4], al[4];
                ldsm4(ah, st + swz(arow, c));
                ldsm4(al, st + 8192 + swz(arow, c));
#pragma unroll
                for (int nt = 0; nt < 8; nt++) {
                    mma_bf16(acc[mt][nt], ah, bh[nt]);
                    mma_bf16(acc[mt][nt], ah, bl[nt]);
                    mma_bf16(acc[mt][nt], al, bh[nt]);
                }
            }
        }
        __syncthreads();
    }

    float sc = useScale ? g_sigma[3] : 1.0f;
#pragma unroll
    for (int mt = 0; mt < 4; mt++) {
        int m = m0 + wm + mt * 16 + (lane >> 2);
#pragma unroll
        for (int nt = 0; nt < 8; nt++) {
            int n = n0 + wn + nt * 8 + (lane & 3) * 2;
            float2 v0 = make_float2(acc[mt][nt][0] * sc, acc[mt][nt][1] * sc);
            float2 v1 = make_float2(acc[mt][nt][2] * sc, acc[mt][nt][3] * sc);
            *(float2*)&Cb[(long)m * HW + n] = v0;
            *(float2*)&Cb[(long)(m + 8) * HW + n] = v1;
        }
    }
#undef LOAD_STAGE
}

// ---------------- 3x3 depthwise conv, pad=1, register-sliding, fused q/k full norm ----
// grid (1152, 4), block 128: one block covers the full 128x128 image of (b, ch)
__global__ __launch_bounds__(128)
void dwconv(const float* __restrict__ in, const float* __restrict__ w,
            float* __restrict__ out)
{
    int ch = blockIdx.x, b = blockIdx.y;
    const float* ip = in + (((long)b * C3 + ch) << 14);
    float* op = out + (((long)b * C3 + ch) << 14);
    int x = threadIdx.x;

    __shared__ float sr[2][130];
    __shared__ float red[128];

    float w00 = w[ch * 9 + 0], w01 = w[ch * 9 + 1], w02 = w[ch * 9 + 2];
    float w10 = w[ch * 9 + 3], w11 = w[ch * 9 + 4], w12 = w[ch * 9 + 5];
    float w20 = w[ch * 9 + 6], w21 = w[ch * 9 + 7], w22 = w[ch * 9 + 8];

    float l0 = 0.f, m0 = 0.f, r0 = 0.f;
    float l1, m1, r1, l2, m2, r2;

    float vcur = ip[x];                 // row 0
    float vpref = ip[128 + x];          // row 1
    sr[0][x + 1] = vcur;
    if (x == 0) { sr[0][0] = 0.f; sr[0][129] = 0.f; }
    __syncthreads();
    l1 = sr[0][x]; m1 = vcur; r1 = sr[0][x + 2];

    float ssq = 0.f;
    for (int y = 0; y < 128; y++) {
        if (y < 127) {
            int buf = (y + 1) & 1;
            sr[buf][x + 1] = vpref;
            if (x == 0) { sr[buf][0] = 0.f; sr[buf][129] = 0.f; }
            float vnext = (y < 126) ? ip[((y + 2) << 7) + x] : 0.f;
            __syncthreads();
            l2 = sr[buf][x]; m2 = vpref; r2 = sr[buf][x + 2];
            vpref = vnext;
        } else {
            l2 = 0.f; m2 = 0.f; r2 = 0.f;
        }
        float s = l0 * w00 + m0 * w01 + r0 * w02
                + l1 * w10 + m1 * w11 + r1 * w12
                + l2 * w20 + m2 * w21 + r2 * w22;
        op[(y << 7) + x] = s;
        ssq += s * s;
        l0 = l1; m0 = m1; r0 = r1;
        l1 = l2; m1 = m2; r1 = r2;
    }

    if (ch < 2 * DIM) {
        red[x] = ssq; __syncthreads();
        for (int s = 64; s > 0; s >>= 1) {
            if (x < s) red[x] += red[x + s];
            __syncthreads();
        }
        if (x == 0) g_invnorm[b * 2 * DIM + ch] = 1.f / fmaxf(sqrtf(red[0]), EPS);
    }
}

// ---------------- raw attention logits (partial over n-chunks) ----------------
__global__ __launch_bounds__(256)
void attn_s(const float* __restrict__ t)
{
    int bh = blockIdx.y;
    int b = bh >> 3, head = bh & 7;
    int n0 = blockIdx.x * (HW / NCHUNKS);
    const float* qp = t + ((((long)b * C3) + head * CH) << 14);
    const float* kp = t + ((((long)b * C3) + DIM + head * CH) << 14);

    __shared__ float qs[32][49];
    __shared__ float ks[32][49];
    int tid = threadIdx.x;
    int ty = tid >> 4, tx = tid & 15;
    float acc[3][3] = {};

    for (int nt = 0; nt < 32; nt++) {
        int nb = n0 + nt * 32;
        for (int i = tid; i < CH * 32; i += 256) {
            int c = i >> 5, nn = i & 31;
            qs[nn][c] = qp[(c << 14) + nb + nn];
            ks[nn][c] = kp[(c << 14) + nb + nn];
        }
        __syncthreads();
#pragma unroll
        for (int nn = 0; nn < 32; nn++) {
            float a0 = qs[nn][ty * 3], a1 = qs[nn][ty * 3 + 1], a2 = qs[nn][ty * 3 + 2];
            float b0 = ks[nn][tx * 3], b1 = ks[nn][tx * 3 + 1], b2 = ks[nn][tx * 3 + 2];
            acc[0][0] = fmaf(a0, b0, acc[0][0]); acc[0][1] = fmaf(a0, b1, acc[0][1]); acc[0][2] = fmaf(a0, b2, acc[0][2]);
            acc[1][0] = fmaf(a1, b0, acc[1][0]); acc[1][1] = fmaf(a1, b1, acc[1][1]); acc[1][2] = fmaf(a1, b2, acc[1][2]);
            acc[2][0] = fmaf(a2, b0, acc[2][0]); acc[2][1] = fmaf(a2, b1, acc[2][1]); acc[2][2] = fmaf(a2, b2, acc[2][2]);
        }
        __syncthreads();
    }

    float* Sp = g_Spart + ((long)blockIdx.x * 32 + bh) * (CH * CH);
#pragma unroll
    for (int i = 0; i < 3; i++)
#pragma unroll
        for (int j = 0; j < 3; j++)
            Sp[(ty * 3 + i) * CH + tx * 3 + j] = acc[i][j];
}

// ---------------- finalize: reduce partials, scale, clamp, softmax ----------------
__global__ __launch_bounds__(64)
void softmax_kernel(const float* __restrict__ temp)
{
    int blk = blockIdx.x;
    int bh = blk / CH, c = blk % CH;
    int b = bh >> 3, head = bh & 7;
    int d = threadIdx.x;
    __shared__ float sm[64];

    float myv = 0.f, val = -1e30f;
    if (d < CH) {
        float raw = 0.f;
#pragma unroll
        for (int ch = 0; ch < NCHUNKS; ch++)
            raw += g_Spart[((long)ch * 32 + bh) * (CH * CH) + c * CH + d];
        float invq = g_invnorm[b * 2 * DIM + head * CH + c];
        float invk = g_invnorm[b * 2 * DIM + DIM + head * CH + d];
        myv = raw * invq * invk * temp[head];
        myv = fminf(fmaxf(myv, -CLAMPV), CLAMPV);
        val = myv;
    }
    sm[d] = val; __syncthreads();
    for (int s = 32; s > 0; s >>= 1) { if (d < s) sm[d] = fmaxf(sm[d], sm[d + s]); __syncthreads(); }
    float m = sm[0]; __syncthreads();
    float e = (d < CH) ? expf(myv - m) : 0.f;
    sm[d] = e; __syncthreads();
    for (int s = 32; s > 0; s >>= 1) { if (d < s) sm[d] += sm[d + s]; __syncthreads(); }
    if (d < CH) g_S[(long)bh * (CH * CH) + c * CH + d] = e / sm[0];
}

// ---------------- out = attn @ v, written TRANSPOSED as bf16 hi/lo [b][n][384] ----------------
__global__ __launch_bounds__(256)
void attn_o(const float* __restrict__ t,
            __nv_bfloat16* __restrict__ aoh, __nv_bfloat16* __restrict__ aol)
{
    int bh = blockIdx.y;
    int b = bh >> 3, head = bh & 7;
    const float* vp = t + ((((long)b * C3) + 2 * DIM + head * CH) << 14);

    __shared__ float Ss[CH * CH];
    for (int i = threadIdx.x; i < CH * CH; i += 256)
        Ss[i] = g_S[(long)bh * (CH * CH) + i];
    __syncthreads();

    int n = blockIdx.x * 512 + threadIdx.x;
    float acc0[CH], acc1[CH];
#pragma unroll
    for (int c = 0; c < CH; c++) { acc0[c] = 0.f; acc1[c] = 0.f; }

    for (int d = 0; d < CH; d++) {
        float v0 = vp[(d << 14) + n];
        float v1 = vp[(d << 14) + n + 256];
#pragma unroll
        for (int c = 0; c < CH; c++) {
            float s = Ss[c * CH + d];
            acc0[c] = fmaf(s, v0, acc0[c]);
            acc1[c] = fmaf(s, v1, acc1[c]);
        }
    }
    long o0 = ((long)b * HW + n) * DIM + head * CH;
    long o1 = ((long)b * HW + n + 256) * DIM + head * CH;
#pragma unroll
    for (int c = 0; c < CH; c += 2) {
        __nv_bfloat16 h0 = __float2bfloat16(acc0[c]);
        __nv_bfloat16 h1 = __float2bfloat16(acc0[c + 1]);
        *(__nv_bfloat162*)&aoh[o0 + c] = __nv_bfloat162(h0, h1);
        *(__nv_bfloat162*)&aol[o0 + c] = __nv_bfloat162(
            __float2bfloat16(acc0[c] - __bfloat162float(h0)),
            __float2bfloat16(acc0[c + 1] - __bfloat162float(h1)));
        __nv_bfloat16 g0 = __float2bfloat16(acc1[c]);
        __nv_bfloat16 g1 = __float2bfloat16(acc1[c + 1]);
        *(__nv_bfloat162*)&aoh[o1 + c] = __nv_bfloat162(g0, g1);
        *(__nv_bfloat162*)&aol[o1 + c] = __nv_bfloat162(
            __float2bfloat16(acc1[c] - __bfloat162float(g0)),
            __float2bfloat16(acc1[c + 1] - __bfloat162float(g1)));
    }
}

// ---------------- launch ----------------
extern "C" void kernel_launch(void* const* d_in, const int* in_sizes, int n_in,
                              void* d_out, int out_size)
{
    const float* x     = (const float*)d_in[0];
    const float* qkvw  = (const float*)d_in[1];
    const float* dww   = (const float*)d_in[2];
    const float* projw = (const float*)d_in[3];
    const float* temp  = (const float*)d_in[4];
    const float* uq    = (const float*)d_in[5];
    const float* ud    = (const float*)d_in[6];
    const float* up    = (const float*)d_in[7];
    float* out = (float*)d_out;

    float *t0, *t1;
    __nv_bfloat16 *xh, *xl, *aoh, *aol, *wqh, *wql, *wph, *wpl;
    cudaGetSymbolAddress((void**)&t0, g_t0);
    cudaGetSymbolAddress((void**)&t1, g_t1);
    cudaGetSymbolAddress((void**)&xh, g_xh);
    cudaGetSymbolAddress((void**)&xl, g_xl);
    cudaGetSymbolAddress((void**)&aoh, g_aoh);
    cudaGetSymbolAddress((void**)&aol, g_aol);
    cudaGetSymbolAddress((void**)&wqh, g_wqh);
    cudaGetSymbolAddress((void**)&wql, g_wql);
    cudaGetSymbolAddress((void**)&wph, g_wph);
    cudaGetSymbolAddress((void**)&wpl, g_wpl);

    cudaFuncSetAttribute(bgemm, cudaFuncAttributeMaxDynamicSharedMemorySize, BG_SMEM);

    // spectral sigmas (parallel pipeline) + combined output scale
    sigma_v<<<dim3(3, 8), 256>>>(qkvw, dww, projw, uq, ud, up);
    sigma_vfin<<<3, 256>>>(0);
    sigma_wv<<<dim3(3, 18), 256>>>(qkvw, dww, projw);
    scale_kernel<<<1, 32>>>();

    // bf16 hi/lo splits: weights (K-major already) and x (transpose+split)
    split_w<<<(C3 * DIM + 255) / 256, 256>>>(qkvw, wqh, wql, C3 * DIM);
    split_w<<<(DIM * DIM + 255) / 256, 256>>>(projw, wph, wpl, DIM * DIM);
    xpose_split<<<dim3(HW / 32, DIM / 64, BATCH), 256>>>(x, xh, xl);

    // qkv 1x1 conv via mma.sync bf16-split GEMM -> t0 [b][1152][hw] fp32
    bgemm<<<dim3(C3 / 128, HW / 256, BATCH), 256, BG_SMEM>>>(
        wqh, wql, xh, xl, t0, (long)C3 * HW, 0);

    // 3x3 depthwise conv with fused q/k L2 norms
    dwconv<<<dim3(C3, BATCH), 128>>>(t0, dww, t1);

    // attention logits (partials) + softmax
    attn_s<<<dim3(NCHUNKS, BATCH * HEADS), 256>>>(t1);
    softmax_kernel<<<BATCH * HEADS * CH, 64>>>(temp);

    // out = attn @ v, fused transpose+split to bf16
    attn_o<<<dim3(32, BATCH * HEADS), 256>>>(t1, aoh, aol);

    // proj 1x1 conv via mma.sync bf16-split GEMM, with combined sigma scale
    bgemm<<<dim3(DIM / 128, HW / 256, BATCH), 256, BG_SMEM>>>(
        wph, wpl, aoh, aol, out, (long)DIM * HW, 1);
}

// round 8
// speedup vs baseline: 2.5862x; 1.0805x over previous
#include <cuda_runtime.h>
#include <cuda_bf16.h>
#include <math.h>
#include <stdint.h>

#define BATCH 4
#define DIM 384
#define HEADS 8
#define CH 48            // DIM/HEADS
#define HW 16384         // 128*128
#define C3 1152          // 3*DIM
#define EPS 1e-12f
#define CLAMPV 50.0f
#define NCHUNKS 16
#define GK 384           // GEMM K (always DIM)

// ---------------- device scratch ----------------
__device__ float g_t0[BATCH * C3 * HW];        // qkv GEMM output fp32
__device__ float g_t1[BATCH * C3 * HW];        // depthwise output fp32
__device__ float g_sigma[4];
__device__ float g_invnorm[BATCH * 2 * DIM];
__device__ float g_Spart[NCHUNKS * BATCH * HEADS * CH * CH];
__device__ float g_S[BATCH * HEADS * CH * CH];
// sigma pipeline scratch
__device__ float g_vpart[3][8][DIM];
__device__ float g_v[3][DIM];
__device__ float g_wvpart[3][18];
// bf16 split operands (transposed activations: [b][n=hw][k=384])
__device__ __nv_bfloat16 g_xh[(size_t)BATCH * HW * DIM];
__device__ __nv_bfloat16 g_xl[(size_t)BATCH * HW * DIM];
__device__ __nv_bfloat16 g_aoh[(size_t)BATCH * HW * DIM];
__device__ __nv_bfloat16 g_aol[(size_t)BATCH * HW * DIM];
__device__ __nv_bfloat16 g_wqh[C3 * DIM];
__device__ __nv_bfloat16 g_wql[C3 * DIM];
__device__ __nv_bfloat16 g_wph[DIM * DIM];
__device__ __nv_bfloat16 g_wpl[DIM * DIM];

// ---------------- warp-mma helpers (all non-'a' features: sm_80 baseline) ----------------
__device__ __forceinline__ uint32_t smem_u32(const void* p) {
    uint32_t a;
    asm("{ .reg .u64 t; cvta.to.shared.u64 t, %1; cvt.u32.u64 %0, t; }" : "=r"(a) : "l"(p));
    return a;
}
__device__ __forceinline__ void cpasync16(uint32_t s, const void* g) {
    asm volatile("cp.async.cg.shared.global [%0], [%1], 16;" :: "r"(s), "l"(g));
}
#define CP_COMMIT() asm volatile("cp.async.commit_group;" ::: "memory")
#define CP_WAIT2()  asm volatile("cp.async.wait_group 2;" ::: "memory")
#define CP_WAIT0()  asm volatile("cp.async.wait_group 0;" ::: "memory")

__device__ __forceinline__ void ldsm4(uint32_t* r, uint32_t addr) {
    asm volatile("ldmatrix.sync.aligned.m8n8.x4.shared.b16 {%0,%1,%2,%3}, [%4];"
        : "=r"(r[0]), "=r"(r[1]), "=r"(r[2]), "=r"(r[3]) : "r"(addr));
}
__device__ __forceinline__ void mma_bf16(float* c, const uint32_t* a, const uint32_t* b) {
    asm volatile(
        "mma.sync.aligned.m16n8k16.row.col.f32.bf16.bf16.f32 "
        "{%0,%1,%2,%3}, {%4,%5,%6,%7}, {%8,%9}, {%0,%1,%2,%3};"
        : "+f"(c[0]), "+f"(c[1]), "+f"(c[2]), "+f"(c[3])
        : "r"(a[0]), "r"(a[1]), "r"(a[2]), "r"(a[3]), "r"(b[0]), "r"(b[1]));
}

// swizzled smem offset for an R-row x 32-bf16 (64B) tile packed 2 rows/128B line.
__device__ __forceinline__ uint32_t swz(uint32_t row, uint32_t c) {
    return (row >> 1) * 128 + ((((row & 1) * 4 + c) ^ ((row >> 1) & 7)) * 16);
}
// swizzle for natural 128B rows (64 bf16 per row), chunk c in 16B units
__device__ __forceinline__ uint32_t swz128(uint32_t row, uint32_t c) {
    return row * 128 + ((c ^ (row & 7)) * 16);
}

// ---------------- sigma pipeline ----------------
__global__ __launch_bounds__(256)
void sigma_v(const float* __restrict__ qkvw, const float* __restrict__ dww,
             const float* __restrict__ projw, const float* __restrict__ uq,
             const float* __restrict__ ud, const float* __restrict__ up)
{
    int which = blockIdx.x, ic = blockIdx.y;
    const float* wm; const float* u; int h, w;
    if (which == 0)      { wm = qkvw;  u = uq; h = C3;  w = DIM; }
    else if (which == 1) { wm = dww;   u = ud; h = C3;  w = 9;   }
    else                 { wm = projw; u = up; h = DIM; w = DIM; }
    int chunk = h >> 3;
    int i0 = ic * chunk, i1 = i0 + chunk;
    for (int j = threadIdx.x; j < w; j += 256) {
        float s = 0.f;
        for (int i = i0; i < i1; i++) s += wm[i * w + j] * u[i];
        g_vpart[which][ic][j] = s;
    }
}

__global__ __launch_bounds__(256)
void sigma_vfin(int dummy)
{
    int which = blockIdx.x;
    int w = (which == 1) ? 9 : DIM;
    int tid = threadIdx.x;
    __shared__ float red[256];
    float ss = 0.f;
    for (int j = tid; j < w; j += 256) {
        float v = 0.f;
#pragma unroll
        for (int ic = 0; ic < 8; ic++) v += g_vpart[which][ic][j];
        g_v[which][j] = v;
        ss += v * v;
    }
    red[tid] = ss; __syncthreads();
    for (int s = 128; s > 0; s >>= 1) { if (tid < s) red[tid] += red[tid + s]; __syncthreads(); }
    float vinv = 1.f / fmaxf(sqrtf(red[0]), EPS);
    for (int j = tid; j < w; j += 256) g_v[which][j] *= vinv;
}

__global__ __launch_bounds__(256)
void sigma_wv(const float* __restrict__ qkvw, const float* __restrict__ dww,
              const float* __restrict__ projw)
{
    int which = blockIdx.x;
    const float* wm; int h, w;
    if (which == 0)      { wm = qkvw;  h = C3;  w = DIM; }
    else if (which == 1) { wm = dww;   h = C3;  w = 9;   }
    else                 { wm = projw; h = DIM; w = DIM; }
    int r = threadIdx.x >> 2, seg = threadIdx.x & 3;
    int i = blockIdx.y * 64 + r;
    if (blockIdx.y * 64 >= h) return;

    float s = 0.f;
    if (i < h) {
        int j0 = seg * (w / 4), j1 = (seg + 1) * (w / 4);
        if (w == 9) { j0 = (seg == 0) ? 0 : 9; j1 = 9; }
        for (int j = j0; j < j1; j++) s += wm[i * w + j] * g_v[which][j];
    }
    s += __shfl_xor_sync(0xffffffff, s, 1);
    s += __shfl_xor_sync(0xffffffff, s, 2);
    float ssq = (seg == 0 && i < h) ? s * s : 0.f;

    __shared__ float red[256];
    red[threadIdx.x] = ssq; __syncthreads();
    for (int st = 128; st > 0; st >>= 1) {
        if (threadIdx.x < st) red[threadIdx.x] += red[threadIdx.x + st];
        __syncthreads();
    }
    if (threadIdx.x == 0) g_wvpart[which][blockIdx.y] = red[0];
}

__global__ void scale_kernel()
{
    if (threadIdx.x == 0) {
        float comb = 1.f;
        int np[3] = {18, 18, 6};
        for (int which = 0; which < 3; which++) {
            float s = 0.f;
            for (int j = 0; j < np[which]; j++) s += g_wvpart[which][j];
            float sig = s / fmaxf(sqrtf(s), EPS);
            comb /= (sig + EPS);
        }
        g_sigma[3] = comb;
    }
}

// ---------------- fp32 -> bf16 hi/lo split (weights, K-major already) ----------------
__global__ __launch_bounds__(256)
void split_w(const float* __restrict__ w, __nv_bfloat16* __restrict__ h,
             __nv_bfloat16* __restrict__ l, int n)
{
    int i = blockIdx.x * 256 + threadIdx.x;
    if (i < n) {
        float v = w[i];
        __nv_bfloat16 hi = __float2bfloat16(v);
        h[i] = hi;
        l[i] = __float2bfloat16(v - __bfloat162float(hi));
    }
}

// ---------------- transpose + split: x [b][c=384][hw] -> xh/xl [b][hw][384] ----------------
__global__ __launch_bounds__(256)
void xpose_split(const float* __restrict__ x, __nv_bfloat16* __restrict__ xh,
                 __nv_bfloat16* __restrict__ xl)
{
    __shared__ float t[64][33];
    int hw0 = blockIdx.x << 5, c0 = blockIdx.y << 6, b = blockIdx.z;
    int tx = threadIdx.x & 31, ty = threadIdx.x >> 5;
#pragma unroll
    for (int i = 0; i < 8; i++) {
        int c = ty + i * 8;
        t[c][tx] = x[(((long)b * DIM + c0 + c) << 14) + hw0 + tx];
    }
    __syncthreads();
#pragma unroll
    for (int i = 0; i < 4; i++) {
        int row = ty * 4 + i;
        float v0 = t[tx * 2][row], v1 = t[tx * 2 + 1][row];
        __nv_bfloat16 h0 = __float2bfloat16(v0);
        __nv_bfloat16 h1 = __float2bfloat16(v1);
        long o = ((long)b * HW + hw0 + row) * DIM + c0 + tx * 2;
        *(__nv_bfloat162*)&xh[o] = __nv_bfloat162(h0, h1);
        *(__nv_bfloat162*)&xl[o] = __nv_bfloat162(
            __float2bfloat16(v0 - __bfloat162float(h0)),
            __float2bfloat16(v1 - __bfloat162float(h1)));
    }
}

// ---------------- bf16-split GEMM via mma.sync ----------------
#define BG_STAGE 49152
#define BG_SMEM (3 * BG_STAGE)
#define KTILES (GK / 32)

__global__ void __launch_bounds__(256)
bgemm(const __nv_bfloat16* __restrict__ Ah, const __nv_bfloat16* __restrict__ Al,
      const __nv_bfloat16* __restrict__ Bh, const __nv_bfloat16* __restrict__ Bl,
      float* __restrict__ C, long strideC, int useScale)
{
    extern __shared__ char smem[];
    uint32_t sb = smem_u32(smem);
    int tid = threadIdx.x, wid = tid >> 5, lane = tid & 31;
    int m0 = blockIdx.x << 7, n0 = blockIdx.y << 8, bz = blockIdx.z;
    int wm = (wid >> 2) * 64;
    int wn = (wid & 3) * 64;

    const __nv_bfloat16* ahp = Ah + (long)m0 * GK;
    const __nv_bfloat16* alp = Al + (long)m0 * GK;
    const __nv_bfloat16* bhp = Bh + (long)bz * HW * DIM + (long)n0 * GK;
    const __nv_bfloat16* blp = Bl + (long)bz * HW * DIM + (long)n0 * GK;
    float* Cb = C + (long)bz * strideC;

    float acc[4][8][4];
#pragma unroll
    for (int i = 0; i < 4; i++)
#pragma unroll
        for (int j = 0; j < 8; j++)
#pragma unroll
            for (int k = 0; k < 4; k++) acc[i][j][k] = 0.f;

    int lrow = tid >> 2, lc = tid & 3;

#define LOAD_STAGE(kc) do { \
        int _k0 = (kc) << 5; \
        uint32_t _sb = sb + ((kc) % 3) * BG_STAGE; \
        _Pragma("unroll") \
        for (int _i = 0; _i < 2; _i++) { \
            int _row = (_i << 6) + lrow; \
            long _go = (long)_row * GK + _k0 + lc * 8; \
            cpasync16(_sb + swz(_row, lc), ahp + _go); \
            cpasync16(_sb + 8192 + swz(_row, lc), alp + _go); \
        } \
        _Pragma("unroll") \
        for (int _i = 0; _i < 4; _i++) { \
            int _row = (_i << 6) + lrow; \
            long _go = (long)_row * GK + _k0 + lc * 8; \
            cpasync16(_sb + 16384 + swz(_row, lc), bhp + _go); \
            cpasync16(_sb + 32768 + swz(_row, lc), blp + _go); \
        } \
        CP_COMMIT(); \
    } while (0)

    LOAD_STAGE(0);
    LOAD_STAGE(1);

    for (int kc = 0; kc < KTILES; kc++) {
        if (kc + 2 < KTILES) { LOAD_STAGE(kc + 2); CP_WAIT2(); }
        else                 { CP_WAIT0(); }
        __syncthreads();

        uint32_t st = sb + (kc % 3) * BG_STAGE;
#pragma unroll
        for (int ks = 0; ks < 2; ks++) {
            uint32_t bh[8][2], bl[8][2];
#pragma unroll
            for (int p = 0; p < 4; p++) {
                int nrow = wn + p * 16 + (lane & 7) + ((lane >> 4) & 1) * 8;
                int c = ks * 2 + ((lane >> 3) & 1);
                uint32_t r[4];
                ldsm4(r, st + 16384 + swz(nrow, c));
                bh[p * 2][0] = r[0]; bh[p * 2][1] = r[1];
                bh[p * 2 + 1][0] = r[2]; bh[p * 2 + 1][1] = r[3];
                ldsm4(r, st + 32768 + swz(nrow, c));
                bl[p * 2][0] = r[0]; bl[p * 2][1] = r[1];
                bl[p * 2 + 1][0] = r[2]; bl[p * 2 + 1][1] = r[3];
            }
#pragma unroll
            for (int mt = 0; mt < 4; mt++) {
                int arow = wm + mt * 16 + (lane & 7) + ((lane >> 3) & 1) * 8;
                int c = ks * 2 + ((lane >> 4) & 1);
                uint32_t ah[4], al[4];
                ldsm4(ah, st + swz(arow, c));
                ldsm4(al, st + 8192 + swz(arow, c));
#pragma unroll
                for (int nt = 0; nt < 8; nt++) {
                    mma_bf16(acc[mt][nt], ah, bh[nt]);
                    mma_bf16(acc[mt][nt], ah, bl[nt]);
                    mma_bf16(acc[mt][nt], al, bh[nt]);
                }
            }
        }
        __syncthreads();
    }

    float sc = useScale ? g_sigma[3] : 1.0f;
#pragma unroll
    for (int mt = 0; mt < 4; mt++) {
        int m = m0 + wm + mt * 16 + (lane >> 2);
#pragma unroll
        for (int nt = 0; nt < 8; nt++) {
            int n = n0 + wn + nt * 8 + (lane & 3) * 2;
            float2 v0 = make_float2(acc[mt][nt][0] * sc, acc[mt][nt][1] * sc);
            float2 v1 = make_float2(acc[mt][nt][2] * sc, acc[mt][nt][3] * sc);
            *(float2*)&Cb[(long)m * HW + n] = v0;
            *(float2*)&Cb[(long)(m + 8) * HW + n] = v1;
        }
    }
#undef LOAD_STAGE
}

// ---------------- 3x3 depthwise conv, pad=1, register-sliding, fused q/k full norm ----
__global__ __launch_bounds__(128)
void dwconv(const float* __restrict__ in, const float* __restrict__ w,
            float* __restrict__ out)
{
    int ch = blockIdx.x, b = blockIdx.y;
    const float* ip = in + (((long)b * C3 + ch) << 14);
    float* op = out + (((long)b * C3 + ch) << 14);
    int x = threadIdx.x;

    __shared__ float sr[2][130];
    __shared__ float red[128];

    float w00 = w[ch * 9 + 0], w01 = w[ch * 9 + 1], w02 = w[ch * 9 + 2];
    float w10 = w[ch * 9 + 3], w11 = w[ch * 9 + 4], w12 = w[ch * 9 + 5];
    float w20 = w[ch * 9 + 6], w21 = w[ch * 9 + 7], w22 = w[ch * 9 + 8];

    float l0 = 0.f, m0 = 0.f, r0 = 0.f;
    float l1, m1, r1, l2, m2, r2;

    float vcur = ip[x];
    float vpref = ip[128 + x];
    sr[0][x + 1] = vcur;
    if (x == 0) { sr[0][0] = 0.f; sr[0][129] = 0.f; }
    __syncthreads();
    l1 = sr[0][x]; m1 = vcur; r1 = sr[0][x + 2];

    float ssq = 0.f;
    for (int y = 0; y < 128; y++) {
        if (y < 127) {
            int buf = (y + 1) & 1;
            sr[buf][x + 1] = vpref;
            if (x == 0) { sr[buf][0] = 0.f; sr[buf][129] = 0.f; }
            float vnext = (y < 126) ? ip[((y + 2) << 7) + x] : 0.f;
            __syncthreads();
            l2 = sr[buf][x]; m2 = vpref; r2 = sr[buf][x + 2];
            vpref = vnext;
        } else {
            l2 = 0.f; m2 = 0.f; r2 = 0.f;
        }
        float s = l0 * w00 + m0 * w01 + r0 * w02
                + l1 * w10 + m1 * w11 + r1 * w12
                + l2 * w20 + m2 * w21 + r2 * w22;
        op[(y << 7) + x] = s;
        ssq += s * s;
        l0 = l1; m0 = m1; r0 = r1;
        l1 = l2; m1 = m2; r1 = r2;
    }

    if (ch < 2 * DIM) {
        red[x] = ssq; __syncthreads();
        for (int s = 64; s > 0; s >>= 1) {
            if (x < s) red[x] += red[x + s];
            __syncthreads();
        }
        if (x == 0) g_invnorm[b * 2 * DIM + ch] = 1.f / fmaxf(sqrtf(red[0]), EPS);
    }
}

// ---------------- attention logits via mma.sync (bf16 3-term split) ----------------
// S[48x48] partial over n-chunk of 1024. grid (NCHUNKS, 32), block 96 (3 warps).
// Stages q,k fp32 -> bf16 hi/lo in smem, k-chunks of 64; warp w owns m-tile w (16 rows).
__global__ __launch_bounds__(96)
void attn_s(const float* __restrict__ t)
{
    int bh = blockIdx.y;
    int b = bh >> 3, head = bh & 7;
    int nb = blockIdx.x * (HW / NCHUNKS);   // 1024
    const float* qp = t + ((((long)b * C3) + head * CH) << 14);
    const float* kp = t + ((((long)b * C3) + DIM + head * CH) << 14);

    __shared__ __align__(16) char smem[4 * 48 * 128];  // qh | ql | kh | kl, 6KB each
    uint32_t sb = smem_u32(smem);
    int tid = threadIdx.x, w = tid >> 5, lane = tid & 31;

    float acc[6][4];
#pragma unroll
    for (int i = 0; i < 6; i++)
#pragma unroll
        for (int j = 0; j < 4; j++) acc[i][j] = 0.f;

    for (int kc = 0; kc < 16; kc++) {
        int off = nb + kc * 64 + lane * 2;
        // stage: each warp loads 16 rows of q and k (64 fp32/row as float2/lane)
        uint32_t so = ((lane >> 2) ^ 0) * 0;  // placeholder to keep compiler quiet
#pragma unroll
        for (int i = 0; i < 16; i++) {
            int c = i * 3 + w;
            uint32_t sw = swz128(c, lane >> 2) + (lane & 3) * 4;
            float2 vq = *(const float2*)&qp[((long)c << 14) + off];
            __nv_bfloat16 qh0 = __float2bfloat16(vq.x);
            __nv_bfloat16 qh1 = __float2bfloat16(vq.y);
            *(__nv_bfloat162*)(smem + sw) = __nv_bfloat162(qh0, qh1);
            *(__nv_bfloat162*)(smem + 6144 + sw) = __nv_bfloat162(
                __float2bfloat16(vq.x - __bfloat162float(qh0)),
                __float2bfloat16(vq.y - __bfloat162float(qh1)));
            float2 vk = *(const float2*)&kp[((long)c << 14) + off];
            __nv_bfloat16 kh0 = __float2bfloat16(vk.x);
            __nv_bfloat16 kh1 = __float2bfloat16(vk.y);
            *(__nv_bfloat162*)(smem + 12288 + sw) = __nv_bfloat162(kh0, kh1);
            *(__nv_bfloat162*)(smem + 18432 + sw) = __nv_bfloat162(
                __float2bfloat16(vk.x - __bfloat162float(kh0)),
                __float2bfloat16(vk.y - __bfloat162float(kh1)));
        }
        (void)so;
        __syncthreads();

#pragma unroll
        for (int ks = 0; ks < 4; ks++) {
            int ar = w * 16 + (lane & 7) + ((lane >> 3) & 1) * 8;
            int ac = ks * 2 + ((lane >> 4) & 1);
            uint32_t ah[4], al[4];
            ldsm4(ah, sb + swz128(ar, ac));
            ldsm4(al, sb + 6144 + swz128(ar, ac));

            uint32_t bhf[6][2], blf[6][2];
            int br = (lane & 7) + ((lane >> 4) & 1) * 8;
            int bc = ks * 2 + ((lane >> 3) & 1);
#pragma unroll
            for (int p = 0; p < 3; p++) {
                uint32_t r[4];
                ldsm4(r, sb + 12288 + swz128(p * 16 + br, bc));
                bhf[p * 2][0] = r[0]; bhf[p * 2][1] = r[1];
                bhf[p * 2 + 1][0] = r[2]; bhf[p * 2 + 1][1] = r[3];
                ldsm4(r, sb + 18432 + swz128(p * 16 + br, bc));
                blf[p * 2][0] = r[0]; blf[p * 2][1] = r[1];
                blf[p * 2 + 1][0] = r[2]; blf[p * 2 + 1][1] = r[3];
            }
#pragma unroll
            for (int nt = 0; nt < 6; nt++) {
                mma_bf16(acc[nt], ah, bhf[nt]);
                mma_bf16(acc[nt], ah, blf[nt]);
                mma_bf16(acc[nt], al, bhf[nt]);
            }
        }
        __syncthreads();
    }

    float* Sp = g_Spart + ((long)blockIdx.x * 32 + bh) * (CH * CH);
    int c0 = w * 16 + (lane >> 2);
#pragma unroll
    for (int nt = 0; nt < 6; nt++) {
        int d = nt * 8 + (lane & 3) * 2;
        *(float2*)&Sp[c0 * CH + d] = make_float2(acc[nt][0], acc[nt][1]);
        *(float2*)&Sp[(c0 + 8) * CH + d] = make_float2(acc[nt][2], acc[nt][3]);
    }
}

// ---------------- finalize: reduce partials, scale, clamp, softmax ----------------
__global__ __launch_bounds__(64)
void softmax_kernel(const float* __restrict__ temp)
{
    int blk = blockIdx.x;
    int bh = blk / CH, c = blk % CH;
    int b = bh >> 3, head = bh & 7;
    int d = threadIdx.x;
    __shared__ float sm[64];

    float myv = 0.f, val = -1e30f;
    if (d < CH) {
        float raw = 0.f;
#pragma unroll
        for (int ch = 0; ch < NCHUNKS; ch++)
            raw += g_Spart[((long)ch * 32 + bh) * (CH * CH) + c * CH + d];
        float invq = g_invnorm[b * 2 * DIM + head * CH + c];
        float invk = g_invnorm[b * 2 * DIM + DIM + head * CH + d];
        myv = raw * invq * invk * temp[head];
        myv = fminf(fmaxf(myv, -CLAMPV), CLAMPV);
        val = myv;
    }
    sm[d] = val; __syncthreads();
    for (int s = 32; s > 0; s >>= 1) { if (d < s) sm[d] = fmaxf(sm[d], sm[d + s]); __syncthreads(); }
    float m = sm[0]; __syncthreads();
    float e = (d < CH) ? expf(myv - m) : 0.f;
    sm[d] = e; __syncthreads();
    for (int s = 32; s > 0; s >>= 1) { if (d < s) sm[d] += sm[d + s]; __syncthreads(); }
    if (d < CH) g_S[(long)bh * (CH * CH) + c * CH + d] = e / sm[0];
}

// ---------------- out = attn @ v, written TRANSPOSED as bf16 hi/lo [b][n][384] ----------------
__global__ __launch_bounds__(256)
void attn_o(const float* __restrict__ t,
            __nv_bfloat16* __restrict__ aoh, __nv_bfloat16* __restrict__ aol)
{
    int bh = blockIdx.y;
    int b = bh >> 3, head = bh & 7;
    const float* vp = t + ((((long)b * C3) + 2 * DIM + head * CH) << 14);

    __shared__ float Ss[CH * CH];
    for (int i = threadIdx.x; i < CH * CH; i += 256)
        Ss[i] = g_S[(long)bh * (CH * CH) + i];
    __syncthreads();

    int n = blockIdx.x * 512 + threadIdx.x;
    float acc0[CH], acc1[CH];
#pragma unroll
    for (int c = 0; c < CH; c++) { acc0[c] = 0.f; acc1[c] = 0.f; }

    for (int d = 0; d < CH; d++) {
        float v0 = vp[(d << 14) + n];
        float v1 = vp[(d << 14) + n + 256];
#pragma unroll
        for (int c = 0; c < CH; c++) {
            float s = Ss[c * CH + d];
            acc0[c] = fmaf(s, v0, acc0[c]);
            acc1[c] = fmaf(s, v1, acc1[c]);
        }
    }
    long o0 = ((long)b * HW + n) * DIM + head * CH;
    long o1 = ((long)b * HW + n + 256) * DIM + head * CH;
#pragma unroll
    for (int c = 0; c < CH; c += 2) {
        __nv_bfloat16 h0 = __float2bfloat16(acc0[c]);
        __nv_bfloat16 h1 = __float2bfloat16(acc0[c + 1]);
        *(__nv_bfloat162*)&aoh[o0 + c] = __nv_bfloat162(h0, h1);
        *(__nv_bfloat162*)&aol[o0 + c] = __nv_bfloat162(
            __float2bfloat16(acc0[c] - __bfloat162float(h0)),
            __float2bfloat16(acc0[c + 1] - __bfloat162float(h1)));
        __nv_bfloat16 g0 = __float2bfloat16(acc1[c]);
        __nv_bfloat16 g1 = __float2bfloat16(acc1[c + 1]);
        *(__nv_bfloat162*)&aoh[o1 + c] = __nv_bfloat162(g0, g1);
        *(__nv_bfloat162*)&aol[o1 + c] = __nv_bfloat162(
            __float2bfloat16(acc1[c] - __bfloat162float(g0)),
            __float2bfloat16(acc1[c + 1] - __bfloat162float(g1)));
    }
}

// ---------------- launch ----------------
extern "C" void kernel_launch(void* const* d_in, const int* in_sizes, int n_in,
                              void* d_out, int out_size)
{
    const float* x     = (const float*)d_in[0];
    const float* qkvw  = (const float*)d_in[1];
    const float* dww   = (const float*)d_in[2];
    const float* projw = (const float*)d_in[3];
    const float* temp  = (const float*)d_in[4];
    const float* uq    = (const float*)d_in[5];
    const float* ud    = (const float*)d_in[6];
    const float* up    = (const float*)d_in[7];
    float* out = (float*)d_out;

    float *t0, *t1;
    __nv_bfloat16 *xh, *xl, *aoh, *aol, *wqh, *wql, *wph, *wpl;
    cudaGetSymbolAddress((void**)&t0, g_t0);
    cudaGetSymbolAddress((void**)&t1, g_t1);
    cudaGetSymbolAddress((void**)&xh, g_xh);
    cudaGetSymbolAddress((void**)&xl, g_xl);
    cudaGetSymbolAddress((void**)&aoh, g_aoh);
    cudaGetSymbolAddress((void**)&aol, g_aol);
    cudaGetSymbolAddress((void**)&wqh, g_wqh);
    cudaGetSymbolAddress((void**)&wql, g_wql);
    cudaGetSymbolAddress((void**)&wph, g_wph);
    cudaGetSymbolAddress((void**)&wpl, g_wpl);

    cudaFuncSetAttribute(bgemm, cudaFuncAttributeMaxDynamicSharedMemorySize, BG_SMEM);

    // spectral sigmas (parallel pipeline) + combined output scale
    sigma_v<<<dim3(3, 8), 256>>>(qkvw, dww, projw, uq, ud, up);
    sigma_vfin<<<3, 256>>>(0);
    sigma_wv<<<dim3(3, 18), 256>>>(qkvw, dww, projw);
    scale_kernel<<<1, 32>>>();

    // bf16 hi/lo splits: weights (K-major already) and x (transpose+split)
    split_w<<<(C3 * DIM + 255) / 256, 256>>>(qkvw, wqh, wql, C3 * DIM);
    split_w<<<(DIM * DIM + 255) / 256, 256>>>(projw, wph, wpl, DIM * DIM);
    xpose_split<<<dim3(HW / 32, DIM / 64, BATCH), 256>>>(x, xh, xl);

    // qkv 1x1 conv via mma.sync bf16-split GEMM -> t0 [b][1152][hw] fp32
    bgemm<<<dim3(C3 / 128, HW / 256, BATCH), 256, BG_SMEM>>>(
        wqh, wql, xh, xl, t0, (long)C3 * HW, 0);

    // 3x3 depthwise conv with fused q/k L2 norms
    dwconv<<<dim3(C3, BATCH), 128>>>(t0, dww, t1);

    // attention logits via mma (partials) + softmax
    attn_s<<<dim3(NCHUNKS, BATCH * HEADS), 96>>>(t1);
    softmax_kernel<<<BATCH * HEADS * CH, 64>>>(temp);

    // out = attn @ v, fused transpose+split to bf16
    attn_o<<<dim3(32, BATCH * HEADS), 256>>>(t1, aoh, aol);

    // proj 1x1 conv via mma.sync bf16-split GEMM, with combined sigma scale
    bgemm<<<dim3(DIM / 128, HW / 256, BATCH), 256, BG_SMEM>>>(
        wph, wpl, aoh, aol, out, (long)DIM * HW, 1);
}

// round 9
// speedup vs baseline: 3.2286x; 1.2484x over previous
#include <cuda_runtime.h>
#include <cuda_fp16.h>
#include <math.h>
#include <stdint.h>

#define BATCH 4
#define DIM 384
#define HEADS 8
#define CH 48            // DIM/HEADS
#define HW 16384         // 128*128
#define C3 1152          // 3*DIM
#define EPS 1e-12f
#define CLAMPV 50.0f
#define NCHUNKS 16
#define GK 384           // GEMM K (always DIM)

// ---------------- device scratch ----------------
__device__ float g_t0[BATCH * C3 * HW];        // qkv GEMM output fp32
__device__ float g_t1[BATCH * C3 * HW];        // depthwise output fp32
__device__ float g_sigma[4];
__device__ float g_invnorm[BATCH * 2 * DIM];
__device__ float g_Spart[NCHUNKS * BATCH * HEADS * CH * CH];
__device__ float g_S[BATCH * HEADS * CH * CH];
// sigma pipeline scratch
__device__ float g_vpart[3][8][DIM];
__device__ float g_v[3][DIM];
__device__ float g_wvpart[3][18];
// fp16 operands (transposed activations hi-only: [b][n=hw][k=384]; weights hi/lo)
__device__ __half g_xh[(size_t)BATCH * HW * DIM];
__device__ __half g_aoh[(size_t)BATCH * HW * DIM];
__device__ __half g_wqh[C3 * DIM];
__device__ __half g_wql[C3 * DIM];
__device__ __half g_wph[DIM * DIM];
__device__ __half g_wpl[DIM * DIM];

// ---------------- warp-mma helpers (all non-'a' features: sm_80 baseline) ----------------
__device__ __forceinline__ uint32_t smem_u32(const void* p) {
    uint32_t a;
    asm("{ .reg .u64 t; cvta.to.shared.u64 t, %1; cvt.u32.u64 %0, t; }" : "=r"(a) : "l"(p));
    return a;
}
__device__ __forceinline__ void cpasync16(uint32_t s, const void* g) {
    asm volatile("cp.async.cg.shared.global [%0], [%1], 16;" :: "r"(s), "l"(g));
}
#define CP_COMMIT() asm volatile("cp.async.commit_group;" ::: "memory")
#define CP_WAIT2()  asm volatile("cp.async.wait_group 2;" ::: "memory")
#define CP_WAIT0()  asm volatile("cp.async.wait_group 0;" ::: "memory")

__device__ __forceinline__ void ldsm4(uint32_t* r, uint32_t addr) {
    asm volatile("ldmatrix.sync.aligned.m8n8.x4.shared.b16 {%0,%1,%2,%3}, [%4];"
        : "=r"(r[0]), "=r"(r[1]), "=r"(r[2]), "=r"(r[3]) : "r"(addr));
}
__device__ __forceinline__ void mma_f16(float* c, const uint32_t* a, const uint32_t* b) {
    asm volatile(
        "mma.sync.aligned.m16n8k16.row.col.f32.f16.f16.f32 "
        "{%0,%1,%2,%3}, {%4,%5,%6,%7}, {%8,%9}, {%0,%1,%2,%3};"
        : "+f"(c[0]), "+f"(c[1]), "+f"(c[2]), "+f"(c[3])
        : "r"(a[0]), "r"(a[1]), "r"(a[2]), "r"(a[3]), "r"(b[0]), "r"(b[1]));
}

// swizzled smem offset for an R-row x 32-f16 (64B) tile packed 2 rows/128B line.
__device__ __forceinline__ uint32_t swz(uint32_t row, uint32_t c) {
    return (row >> 1) * 128 + ((((row & 1) * 4 + c) ^ ((row >> 1) & 7)) * 16);
}
// swizzle for natural 128B rows (64 f16 per row), chunk c in 16B units
__device__ __forceinline__ uint32_t swz128(uint32_t row, uint32_t c) {
    return row * 128 + ((c ^ (row & 7)) * 16);
}

// ---------------- sigma pipeline ----------------
__global__ __launch_bounds__(256)
void sigma_v(const float* __restrict__ qkvw, const float* __restrict__ dww,
             const float* __restrict__ projw, const float* __restrict__ uq,
             const float* __restrict__ ud, const float* __restrict__ up)
{
    int which = blockIdx.x, ic = blockIdx.y;
    const float* wm; const float* u; int h, w;
    if (which == 0)      { wm = qkvw;  u = uq; h = C3;  w = DIM; }
    else if (which == 1) { wm = dww;   u = ud; h = C3;  w = 9;   }
    else                 { wm = projw; u = up; h = DIM; w = DIM; }
    int chunk = h >> 3;
    int i0 = ic * chunk, i1 = i0 + chunk;
    for (int j = threadIdx.x; j < w; j += 256) {
        float s = 0.f;
        for (int i = i0; i < i1; i++) s += wm[i * w + j] * u[i];
        g_vpart[which][ic][j] = s;
    }
}

__global__ __launch_bounds__(256)
void sigma_vfin(int dummy)
{
    int which = blockIdx.x;
    int w = (which == 1) ? 9 : DIM;
    int tid = threadIdx.x;
    __shared__ float red[256];
    float ss = 0.f;
    for (int j = tid; j < w; j += 256) {
        float v = 0.f;
#pragma unroll
        for (int ic = 0; ic < 8; ic++) v += g_vpart[which][ic][j];
        g_v[which][j] = v;
        ss += v * v;
    }
    red[tid] = ss; __syncthreads();
    for (int s = 128; s > 0; s >>= 1) { if (tid < s) red[tid] += red[tid + s]; __syncthreads(); }
    float vinv = 1.f / fmaxf(sqrtf(red[0]), EPS);
    for (int j = tid; j < w; j += 256) g_v[which][j] *= vinv;
}

__global__ __launch_bounds__(256)
void sigma_wv(const float* __restrict__ qkvw, const float* __restrict__ dww,
              const float* __restrict__ projw)
{
    int which = blockIdx.x;
    const float* wm; int h, w;
    if (which == 0)      { wm = qkvw;  h = C3;  w = DIM; }
    else if (which == 1) { wm = dww;   h = C3;  w = 9;   }
    else                 { wm = projw; h = DIM; w = DIM; }
    int r = threadIdx.x >> 2, seg = threadIdx.x & 3;
    int i = blockIdx.y * 64 + r;
    if (blockIdx.y * 64 >= h) return;

    float s = 0.f;
    if (i < h) {
        int j0 = seg * (w / 4), j1 = (seg + 1) * (w / 4);
        if (w == 9) { j0 = (seg == 0) ? 0 : 9; j1 = 9; }
        for (int j = j0; j < j1; j++) s += wm[i * w + j] * g_v[which][j];
    }
    s += __shfl_xor_sync(0xffffffff, s, 1);
    s += __shfl_xor_sync(0xffffffff, s, 2);
    float ssq = (seg == 0 && i < h) ? s * s : 0.f;

    __shared__ float red[256];
    red[threadIdx.x] = ssq; __syncthreads();
    for (int st = 128; st > 0; st >>= 1) {
        if (threadIdx.x < st) red[threadIdx.x] += red[threadIdx.x + st];
        __syncthreads();
    }
    if (threadIdx.x == 0) g_wvpart[which][blockIdx.y] = red[0];
}

__global__ void scale_kernel()
{
    if (threadIdx.x == 0) {
        float comb = 1.f;
        int np[3] = {18, 18, 6};
        for (int which = 0; which < 3; which++) {
            float s = 0.f;
            for (int j = 0; j < np[which]; j++) s += g_wvpart[which][j];
            float sig = s / fmaxf(sqrtf(s), EPS);
            comb /= (sig + EPS);
        }
        g_sigma[3] = comb;
    }
}

// ---------------- fp32 -> fp16 hi/lo split (weights, K-major already) ----------------
__global__ __launch_bounds__(256)
void split_w(const float* __restrict__ w, __half* __restrict__ h,
             __half* __restrict__ l, int n)
{
    int i = blockIdx.x * 256 + threadIdx.x;
    if (i < n) {
        float v = w[i];
        __half hi = __float2half_rn(v);
        h[i] = hi;
        l[i] = __float2half_rn(v - __half2float(hi));
    }
}

// ---------------- transpose + convert: x [b][c=384][hw] -> xh fp16 [b][hw][384] ----------------
__global__ __launch_bounds__(256)
void xpose_split(const float* __restrict__ x, __half* __restrict__ xh)
{
    __shared__ float t[64][33];
    int hw0 = blockIdx.x << 5, c0 = blockIdx.y << 6, b = blockIdx.z;
    int tx = threadIdx.x & 31, ty = threadIdx.x >> 5;
#pragma unroll
    for (int i = 0; i < 8; i++) {
        int c = ty + i * 8;
        t[c][tx] = x[(((long)b * DIM + c0 + c) << 14) + hw0 + tx];
    }
    __syncthreads();
#pragma unroll
    for (int i = 0; i < 4; i++) {
        int row = ty * 4 + i;
        float v0 = t[tx * 2][row], v1 = t[tx * 2 + 1][row];
        long o = ((long)b * HW + hw0 + row) * DIM + c0 + tx * 2;
        *(__half2*)&xh[o] = __halves2half2(__float2half_rn(v0), __float2half_rn(v1));
    }
}

// ---------------- fp16 2-term GEMM via mma.sync ----------------
// C = (Ah+Al) * Bh; A [Mtot][384] fp16 hi/lo, B [b][16384][384] fp16 hi.
// Block 128x256x32, 8 warps (2Mx4N), warp tile 64x64, cp.async 3-stage.
// Stage: Ah|Al (8KB each) + Bh (16KB) = 32KB; 3 stages = 96KB.
#define BG_STAGE 32768
#define BG_SMEM (3 * BG_STAGE)
#define KTILES (GK / 32)

__global__ void __launch_bounds__(256)
bgemm(const __half* __restrict__ Ah, const __half* __restrict__ Al,
      const __half* __restrict__ Bh,
      float* __restrict__ C, long strideC, int useScale)
{
    extern __shared__ char smem[];
    uint32_t sb = smem_u32(smem);
    int tid = threadIdx.x, wid = tid >> 5, lane = tid & 31;
    int m0 = blockIdx.x << 7, n0 = blockIdx.y << 8, bz = blockIdx.z;
    int wm = (wid >> 2) * 64;
    int wn = (wid & 3) * 64;

    const __half* ahp = Ah + (long)m0 * GK;
    const __half* alp = Al + (long)m0 * GK;
    const __half* bhp = Bh + (long)bz * HW * DIM + (long)n0 * GK;
    float* Cb = C + (long)bz * strideC;

    float acc[4][8][4];
#pragma unroll
    for (int i = 0; i < 4; i++)
#pragma unroll
        for (int j = 0; j < 8; j++)
#pragma unroll
            for (int k = 0; k < 4; k++) acc[i][j][k] = 0.f;

    int lrow = tid >> 2, lc = tid & 3;

#define LOAD_STAGE(kc) do { \
        int _k0 = (kc) << 5; \
        uint32_t _sb = sb + ((kc) % 3) * BG_STAGE; \
        _Pragma("unroll") \
        for (int _i = 0; _i < 2; _i++) { \
            int _row = (_i << 6) + lrow; \
            long _go = (long)_row * GK + _k0 + lc * 8; \
            cpasync16(_sb + swz(_row, lc), ahp + _go); \
            cpasync16(_sb + 8192 + swz(_row, lc), alp + _go); \
        } \
        _Pragma("unroll") \
        for (int _i = 0; _i < 4; _i++) { \
            int _row = (_i << 6) + lrow; \
            long _go = (long)_row * GK + _k0 + lc * 8; \
            cpasync16(_sb + 16384 + swz(_row, lc), bhp + _go); \
        } \
        CP_COMMIT(); \
    } while (0)

    LOAD_STAGE(0);
    LOAD_STAGE(1);

    for (int kc = 0; kc < KTILES; kc++) {
        if (kc + 2 < KTILES) { LOAD_STAGE(kc + 2); CP_WAIT2(); }
        else                 { CP_WAIT0(); }
        __syncthreads();

        uint32_t st = sb + (kc % 3) * BG_STAGE;
#pragma unroll
        for (int ks = 0; ks < 2; ks++) {
            uint32_t bh[8][2];
#pragma unroll
            for (int p = 0; p < 4; p++) {
                int nrow = wn + p * 16 + (lane & 7) + ((lane >> 4) & 1) * 8;
                int c = ks * 2 + ((lane >> 3) & 1);
                uint32_t r[4];
                ldsm4(r, st + 16384 + swz(nrow, c));
                bh[p * 2][0] = r[0]; bh[p * 2][1] = r[1];
                bh[p * 2 + 1][0] = r[2]; bh[p * 2 + 1][1] = r[3];
            }
#pragma unroll
            for (int mt = 0; mt < 4; mt++) {
                int arow = wm + mt * 16 + (lane & 7) + ((lane >> 3) & 1) * 8;
                int c = ks * 2 + ((lane >> 4) & 1);
                uint32_t ah[4], al[4];
                ldsm4(ah, st + swz(arow, c));
                ldsm4(al, st + 8192 + swz(arow, c));
#pragma unroll
                for (int nt = 0; nt < 8; nt++) {
                    mma_f16(acc[mt][nt], ah, bh[nt]);
                    mma_f16(acc[mt][nt], al, bh[nt]);
                }
            }
        }
        __syncthreads();
    }

    float sc = useScale ? g_sigma[3] : 1.0f;
#pragma unroll
    for (int mt = 0; mt < 4; mt++) {
        int m = m0 + wm + mt * 16 + (lane >> 2);
#pragma unroll
        for (int nt = 0; nt < 8; nt++) {
            int n = n0 + wn + nt * 8 + (lane & 3) * 2;
            float2 v0 = make_float2(acc[mt][nt][0] * sc, acc[mt][nt][1] * sc);
            float2 v1 = make_float2(acc[mt][nt][2] * sc, acc[mt][nt][3] * sc);
            *(float2*)&Cb[(long)m * HW + n] = v0;
            *(float2*)&Cb[(long)(m + 8) * HW + n] = v1;
        }
    }
#undef LOAD_STAGE
}

// ---------------- 3x3 depthwise conv, pad=1, register-sliding, fused q/k full norm ----
__global__ __launch_bounds__(128)
void dwconv(const float* __restrict__ in, const float* __restrict__ w,
            float* __restrict__ out)
{
    int ch = blockIdx.x, b = blockIdx.y;
    const float* ip = in + (((long)b * C3 + ch) << 14);
    float* op = out + (((long)b * C3 + ch) << 14);
    int x = threadIdx.x;

    __shared__ float sr[2][130];
    __shared__ float red[128];

    float w00 = w[ch * 9 + 0], w01 = w[ch * 9 + 1], w02 = w[ch * 9 + 2];
    float w10 = w[ch * 9 + 3], w11 = w[ch * 9 + 4], w12 = w[ch * 9 + 5];
    float w20 = w[ch * 9 + 6], w21 = w[ch * 9 + 7], w22 = w[ch * 9 + 8];

    float l0 = 0.f, m0 = 0.f, r0 = 0.f;
    float l1, m1, r1, l2, m2, r2;

    float vcur = ip[x];
    float vpref = ip[128 + x];
    sr[0][x + 1] = vcur;
    if (x == 0) { sr[0][0] = 0.f; sr[0][129] = 0.f; }
    __syncthreads();
    l1 = sr[0][x]; m1 = vcur; r1 = sr[0][x + 2];

    float ssq = 0.f;
    for (int y = 0; y < 128; y++) {
        if (y < 127) {
            int buf = (y + 1) & 1;
            sr[buf][x + 1] = vpref;
            if (x == 0) { sr[buf][0] = 0.f; sr[buf][129] = 0.f; }
            float vnext = (y < 126) ? ip[((y + 2) << 7) + x] : 0.f;
            __syncthreads();
            l2 = sr[buf][x]; m2 = vpref; r2 = sr[buf][x + 2];
            vpref = vnext;
        } else {
            l2 = 0.f; m2 = 0.f; r2 = 0.f;
        }
        float s = l0 * w00 + m0 * w01 + r0 * w02
                + l1 * w10 + m1 * w11 + r1 * w12
                + l2 * w20 + m2 * w21 + r2 * w22;
        op[(y << 7) + x] = s;
        ssq += s * s;
        l0 = l1; m0 = m1; r0 = r1;
        l1 = l2; m1 = m2; r1 = r2;
    }

    if (ch < 2 * DIM) {
        red[x] = ssq; __syncthreads();
        for (int s = 64; s > 0; s >>= 1) {
            if (x < s) red[x] += red[x + s];
            __syncthreads();
        }
        if (x == 0) g_invnorm[b * 2 * DIM + ch] = 1.f / fmaxf(sqrtf(red[0]), EPS);
    }
}

// ---------------- attention logits via mma.sync (fp16 2-term: q split, k hi) ----------------
// S[48x48] partial over n-chunk of 1024. grid (NCHUNKS, 32), block 96 (3 warps).
__global__ __launch_bounds__(96)
void attn_s(const float* __restrict__ t)
{
    int bh = blockIdx.y;
    int b = bh >> 3, head = bh & 7;
    int nb = blockIdx.x * (HW / NCHUNKS);   // 1024
    const float* qp = t + ((((long)b * C3) + head * CH) << 14);
    const float* kp = t + ((((long)b * C3) + DIM + head * CH) << 14);

    __shared__ __align__(16) char smem[3 * 48 * 128];  // qh | ql | kh, 6KB each
    uint32_t sb = smem_u32(smem);
    int tid = threadIdx.x, w = tid >> 5, lane = tid & 31;

    float acc[6][4];
#pragma unroll
    for (int i = 0; i < 6; i++)
#pragma unroll
        for (int j = 0; j < 4; j++) acc[i][j] = 0.f;

    for (int kc = 0; kc < 16; kc++) {
        int off = nb + kc * 64 + lane * 2;
#pragma unroll
        for (int i = 0; i < 16; i++) {
            int c = i * 3 + w;
            uint32_t sw = swz128(c, lane >> 2) + (lane & 3) * 4;
            float2 vq = *(const float2*)&qp[((long)c << 14) + off];
            __half qh0 = __float2half_rn(vq.x);
            __half qh1 = __float2half_rn(vq.y);
            *(__half2*)(smem + sw) = __halves2half2(qh0, qh1);
            *(__half2*)(smem + 6144 + sw) = __halves2half2(
                __float2half_rn(vq.x - __half2float(qh0)),
                __float2half_rn(vq.y - __half2float(qh1)));
            float2 vk = *(const float2*)&kp[((long)c << 14) + off];
            *(__half2*)(smem + 12288 + sw) = __halves2half2(
                __float2half_rn(vk.x), __float2half_rn(vk.y));
        }
        __syncthreads();

#pragma unroll
        for (int ks = 0; ks < 4; ks++) {
            int ar = w * 16 + (lane & 7) + ((lane >> 3) & 1) * 8;
            int ac = ks * 2 + ((lane >> 4) & 1);
            uint32_t ah[4], al[4];
            ldsm4(ah, sb + swz128(ar, ac));
            ldsm4(al, sb + 6144 + swz128(ar, ac));

            uint32_t bhf[6][2];
            int br = (lane & 7) + ((lane >> 4) & 1) * 8;
            int bc = ks * 2 + ((lane >> 3) & 1);
#pragma unroll
            for (int p = 0; p < 3; p++) {
                uint32_t r[4];
                ldsm4(r, sb + 12288 + swz128(p * 16 + br, bc));
                bhf[p * 2][0] = r[0]; bhf[p * 2][1] = r[1];
                bhf[p * 2 + 1][0] = r[2]; bhf[p * 2 + 1][1] = r[3];
            }
#pragma unroll
            for (int nt = 0; nt < 6; nt++) {
                mma_f16(acc[nt], ah, bhf[nt]);
                mma_f16(acc[nt], al, bhf[nt]);
            }
        }
        __syncthreads();
    }

    float* Sp = g_Spart + ((long)blockIdx.x * 32 + bh) * (CH * CH);
    int c0 = w * 16 + (lane >> 2);
#pragma unroll
    for (int nt = 0; nt < 6; nt++) {
        int d = nt * 8 + (lane & 3) * 2;
        *(float2*)&Sp[c0 * CH + d] = make_float2(acc[nt][0], acc[nt][1]);
        *(float2*)&Sp[(c0 + 8) * CH + d] = make_float2(acc[nt][2], acc[nt][3]);
    }
}

// ---------------- finalize: reduce partials, scale, clamp, softmax ----------------
__global__ __launch_bounds__(64)
void softmax_kernel(const float* __restrict__ temp)
{
    int blk = blockIdx.x;
    int bh = blk / CH, c = blk % CH;
    int b = bh >> 3, head = bh & 7;
    int d = threadIdx.x;
    __shared__ float sm[64];

    float myv = 0.f, val = -1e30f;
    if (d < CH) {
        float raw = 0.f;
#pragma unroll
        for (int ch = 0; ch < NCHUNKS; ch++)
            raw += g_Spart[((long)ch * 32 + bh) * (CH * CH) + c * CH + d];
        float invq = g_invnorm[b * 2 * DIM + head * CH + c];
        float invk = g_invnorm[b * 2 * DIM + DIM + head * CH + d];
        myv = raw * invq * invk * temp[head];
        myv = fminf(fmaxf(myv, -CLAMPV), CLAMPV);
        val = myv;
    }
    sm[d] = val; __syncthreads();
    for (int s = 32; s > 0; s >>= 1) { if (d < s) sm[d] = fmaxf(sm[d], sm[d + s]); __syncthreads(); }
    float m = sm[0]; __syncthreads();
    float e = (d < CH) ? expf(myv - m) : 0.f;
    sm[d] = e; __syncthreads();
    for (int s = 32; s > 0; s >>= 1) { if (d < s) sm[d] += sm[d + s]; __syncthreads(); }
    if (d < CH) g_S[(long)bh * (CH * CH) + c * CH + d] = e / sm[0];
}

// ---------------- out = attn @ v, written TRANSPOSED as fp16 [b][n][384] ----------------
__global__ __launch_bounds__(256)
void attn_o(const float* __restrict__ t, __half* __restrict__ aoh)
{
    int bh = blockIdx.y;
    int b = bh >> 3, head = bh & 7;
    const float* vp = t + ((((long)b * C3) + 2 * DIM + head * CH) << 14);

    __shared__ float Ss[CH * CH];
    for (int i = threadIdx.x; i < CH * CH; i += 256)
        Ss[i] = g_S[(long)bh * (CH * CH) + i];
    __syncthreads();

    int n = blockIdx.x * 512 + threadIdx.x;
    float acc0[CH], acc1[CH];
#pragma unroll
    for (int c = 0; c < CH; c++) { acc0[c] = 0.f; acc1[c] = 0.f; }

    for (int d = 0; d < CH; d++) {
        float v0 = vp[(d << 14) + n];
        float v1 = vp[(d << 14) + n + 256];
#pragma unroll
        for (int c = 0; c < CH; c++) {
            float s = Ss[c * CH + d];
            acc0[c] = fmaf(s, v0, acc0[c]);
            acc1[c] = fmaf(s, v1, acc1[c]);
        }
    }
    long o0 = ((long)b * HW + n) * DIM + head * CH;
    long o1 = ((long)b * HW + n + 256) * DIM + head * CH;
#pragma unroll
    for (int c = 0; c < CH; c += 2) {
        *(__half2*)&aoh[o0 + c] = __halves2half2(
            __float2half_rn(acc0[c]), __float2half_rn(acc0[c + 1]));
        *(__half2*)&aoh[o1 + c] = __halves2half2(
            __float2half_rn(acc1[c]), __float2half_rn(acc1[c + 1]));
    }
}

// ---------------- launch ----------------
extern "C" void kernel_launch(void* const* d_in, const int* in_sizes, int n_in,
                              void* d_out, int out_size)
{
    const float* x     = (const float*)d_in[0];
    const float* qkvw  = (const float*)d_in[1];
    const float* dww   = (const float*)d_in[2];
    const float* projw = (const float*)d_in[3];
    const float* temp  = (const float*)d_in[4];
    const float* uq    = (const float*)d_in[5];
    const float* ud    = (const float*)d_in[6];
    const float* up    = (const float*)d_in[7];
    float* out = (float*)d_out;

    float *t0, *t1;
    __half *xh, *aoh, *wqh, *wql, *wph, *wpl;
    cudaGetSymbolAddress((void**)&t0, g_t0);
    cudaGetSymbolAddress((void**)&t1, g_t1);
    cudaGetSymbolAddress((void**)&xh, g_xh);
    cudaGetSymbolAddress((void**)&aoh, g_aoh);
    cudaGetSymbolAddress((void**)&wqh, g_wqh);
    cudaGetSymbolAddress((void**)&wql, g_wql);
    cudaGetSymbolAddress((void**)&wph, g_wph);
    cudaGetSymbolAddress((void**)&wpl, g_wpl);

    cudaFuncSetAttribute(bgemm, cudaFuncAttributeMaxDynamicSharedMemorySize, BG_SMEM);

    // spectral sigmas (parallel pipeline) + combined output scale
    sigma_v<<<dim3(3, 8), 256>>>(qkvw, dww, projw, uq, ud, up);
    sigma_vfin<<<3, 256>>>(0);
    sigma_wv<<<dim3(3, 18), 256>>>(qkvw, dww, projw);
    scale_kernel<<<1, 32>>>();

    // fp16 splits: weights hi/lo; x transpose+convert (hi only)
    split_w<<<(C3 * DIM + 255) / 256, 256>>>(qkvw, wqh, wql, C3 * DIM);
    split_w<<<(DIM * DIM + 255) / 256, 256>>>(projw, wph, wpl, DIM * DIM);
    xpose_split<<<dim3(HW / 32, DIM / 64, BATCH), 256>>>(x, xh);

    // qkv 1x1 conv via fp16 2-term GEMM -> t0 [b][1152][hw] fp32
    bgemm<<<dim3(C3 / 128, HW / 256, BATCH), 256, BG_SMEM>>>(
        wqh, wql, xh, t0, (long)C3 * HW, 0);

    // 3x3 depthwise conv with fused q/k L2 norms
    dwconv<<<dim3(C3, BATCH), 128>>>(t0, dww, t1);

    // attention logits via mma (partials) + softmax
    attn_s<<<dim3(NCHUNKS, BATCH * HEADS), 96>>>(t1);
    softmax_kernel<<<BATCH * HEADS * CH, 64>>>(temp);

    // out = attn @ v, fused transpose+convert to fp16
    attn_o<<<dim3(32, BATCH * HEADS), 256>>>(t1, aoh);

    // proj 1x1 conv via fp16 2-term GEMM, with combined sigma scale
    bgemm<<<dim3(DIM / 128, HW / 256, BATCH), 256, BG_SMEM>>>(
        wph, wpl, aoh, out, (long)DIM * HW, 1);
}

// round 10
// speedup vs baseline: 3.3995x; 1.0529x over previous
#include <cuda_runtime.h>
#include <cuda_fp16.h>
#include <math.h>
#include <stdint.h>

#define BATCH 4
#define DIM 384
#define HEADS 8
#define CH 48            // DIM/HEADS
#define HW 16384         // 128*128
#define C3 1152          // 3*DIM
#define EPS 1e-12f
#define CLAMPV 50.0f
#define NCHUNKS 16
#define GK 384           // GEMM K (always DIM)

// ---------------- device scratch ----------------
__device__ __half g_t0h[(size_t)BATCH * C3 * HW];   // qkv GEMM output fp16
__device__ __half g_t1h[(size_t)BATCH * C3 * HW];   // depthwise output fp16
__device__ float g_sigma[4];
__device__ float g_invnorm[BATCH * 2 * DIM];
__device__ float g_Spart[NCHUNKS * BATCH * HEADS * CH * CH];
__device__ float g_S[BATCH * HEADS * CH * CH];
// sigma pipeline scratch
__device__ float g_vpart[3][8][DIM];
__device__ float g_v[3][DIM];
__device__ float g_wvpart[3][18];
// fp16 operands (transposed activations hi-only: [b][n=hw][k=384]; weights hi/lo)
__device__ __half g_xh[(size_t)BATCH * HW * DIM];
__device__ __half g_aoh[(size_t)BATCH * HW * DIM];
__device__ __half g_wqh[C3 * DIM];
__device__ __half g_wql[C3 * DIM];
__device__ __half g_wph[DIM * DIM];
__device__ __half g_wpl[DIM * DIM];

// ---------------- warp-mma helpers ----------------
__device__ __forceinline__ uint32_t smem_u32(const void* p) {
    uint32_t a;
    asm("{ .reg .u64 t; cvta.to.shared.u64 t, %1; cvt.u32.u64 %0, t; }" : "=r"(a) : "l"(p));
    return a;
}
__device__ __forceinline__ void cpasync16(uint32_t s, const void* g) {
    asm volatile("cp.async.cg.shared.global [%0], [%1], 16;" :: "r"(s), "l"(g));
}
#define CP_COMMIT() asm volatile("cp.async.commit_group;" ::: "memory")
#define CP_WAIT2()  asm volatile("cp.async.wait_group 2;" ::: "memory")
#define CP_WAIT1()  asm volatile("cp.async.wait_group 1;" ::: "memory")
#define CP_WAIT0()  asm volatile("cp.async.wait_group 0;" ::: "memory")

__device__ __forceinline__ void ldsm4(uint32_t* r, uint32_t addr) {
    asm volatile("ldmatrix.sync.aligned.m8n8.x4.shared.b16 {%0,%1,%2,%3}, [%4];"
        : "=r"(r[0]), "=r"(r[1]), "=r"(r[2]), "=r"(r[3]) : "r"(addr));
}
__device__ __forceinline__ void mma_f16(float* c, const uint32_t* a, const uint32_t* b) {
    asm volatile(
        "mma.sync.aligned.m16n8k16.row.col.f32.f16.f16.f32 "
        "{%0,%1,%2,%3}, {%4,%5,%6,%7}, {%8,%9}, {%0,%1,%2,%3};"
        : "+f"(c[0]), "+f"(c[1]), "+f"(c[2]), "+f"(c[3])
        : "r"(a[0]), "r"(a[1]), "r"(a[2]), "r"(a[3]), "r"(b[0]), "r"(b[1]));
}

// swizzled smem offset for an R-row x 32-f16 (64B) tile packed 2 rows/128B line.
__device__ __forceinline__ uint32_t swz(uint32_t row, uint32_t c) {
    return (row >> 1) * 128 + ((((row & 1) * 4 + c) ^ ((row >> 1) & 7)) * 16);
}
// swizzle for natural 128B rows (64 f16 per row), chunk c in 16B units
__device__ __forceinline__ uint32_t swz128(uint32_t row, uint32_t c) {
    return row * 128 + ((c ^ (row & 7)) * 16);
}

// ---------------- sigma pipeline ----------------
__global__ __launch_bounds__(256)
void sigma_v(const float* __restrict__ qkvw, const float* __restrict__ dww,
             const float* __restrict__ projw, const float* __restrict__ uq,
             const float* __restrict__ ud, const float* __restrict__ up)
{
    int which = blockIdx.x, ic = blockIdx.y;
    const float* wm; const float* u; int h, w;
    if (which == 0)      { wm = qkvw;  u = uq; h = C3;  w = DIM; }
    else if (which == 1) { wm = dww;   u = ud; h = C3;  w = 9;   }
    else                 { wm = projw; u = up; h = DIM; w = DIM; }
    int chunk = h >> 3;
    int i0 = ic * chunk, i1 = i0 + chunk;
    for (int j = threadIdx.x; j < w; j += 256) {
        float s = 0.f;
        for (int i = i0; i < i1; i++) s += wm[i * w + j] * u[i];
        g_vpart[which][ic][j] = s;
    }
}

__global__ __launch_bounds__(256)
void sigma_vfin(int dummy)
{
    int which = blockIdx.x;
    int w = (which == 1) ? 9 : DIM;
    int tid = threadIdx.x;
    __shared__ float red[256];
    float ss = 0.f;
    for (int j = tid; j < w; j += 256) {
        float v = 0.f;
#pragma unroll
        for (int ic = 0; ic < 8; ic++) v += g_vpart[which][ic][j];
        g_v[which][j] = v;
        ss += v * v;
    }
    red[tid] = ss; __syncthreads();
    for (int s = 128; s > 0; s >>= 1) { if (tid < s) red[tid] += red[tid + s]; __syncthreads(); }
    float vinv = 1.f / fmaxf(sqrtf(red[0]), EPS);
    for (int j = tid; j < w; j += 256) g_v[which][j] *= vinv;
}

__global__ __launch_bounds__(256)
void sigma_wv(const float* __restrict__ qkvw, const float* __restrict__ dww,
              const float* __restrict__ projw)
{
    int which = blockIdx.x;
    const float* wm; int h, w;
    if (which == 0)      { wm = qkvw;  h = C3;  w = DIM; }
    else if (which == 1) { wm = dww;   h = C3;  w = 9;   }
    else                 { wm = projw; h = DIM; w = DIM; }
    int r = threadIdx.x >> 2, seg = threadIdx.x & 3;
    int i = blockIdx.y * 64 + r;
    if (blockIdx.y * 64 >= h) return;

    float s = 0.f;
    if (i < h) {
        int j0 = seg * (w / 4), j1 = (seg + 1) * (w / 4);
        if (w == 9) { j0 = (seg == 0) ? 0 : 9; j1 = 9; }
        for (int j = j0; j < j1; j++) s += wm[i * w + j] * g_v[which][j];
    }
    s += __shfl_xor_sync(0xffffffff, s, 1);
    s += __shfl_xor_sync(0xffffffff, s, 2);
    float ssq = (seg == 0 && i < h) ? s * s : 0.f;

    __shared__ float red[256];
    red[threadIdx.x] = ssq; __syncthreads();
    for (int st = 128; st > 0; st >>= 1) {
        if (threadIdx.x < st) red[threadIdx.x] += red[threadIdx.x + st];
        __syncthreads();
    }
    if (threadIdx.x == 0) g_wvpart[which][blockIdx.y] = red[0];
}

__global__ void scale_kernel()
{
    if (threadIdx.x == 0) {
        float comb = 1.f;
        int np[3] = {18, 18, 6};
        for (int which = 0; which < 3; which++) {
            float s = 0.f;
            for (int j = 0; j < np[which]; j++) s += g_wvpart[which][j];
            float sig = s / fmaxf(sqrtf(s), EPS);
            comb /= (sig + EPS);
        }
        g_sigma[3] = comb;
    }
}

// ---------------- fp32 -> fp16 hi/lo split of BOTH weight matrices ----------------
__global__ __launch_bounds__(256)
void split_w2(const float* __restrict__ qkvw, const float* __restrict__ projw,
              __half* __restrict__ qh, __half* __restrict__ ql,
              __half* __restrict__ ph, __half* __restrict__ pl)
{
    int i = blockIdx.x * 256 + threadIdx.x;
    if (i < C3 * DIM) {
        float v = qkvw[i];
        __half hi = __float2half_rn(v);
        qh[i] = hi;
        ql[i] = __float2half_rn(v - __half2float(hi));
    } else if (i < C3 * DIM + DIM * DIM) {
        int j = i - C3 * DIM;
        float v = projw[j];
        __half hi = __float2half_rn(v);
        ph[j] = hi;
        pl[j] = __float2half_rn(v - __half2float(hi));
    }
}

// ---------------- transpose + convert: x [b][c=384][hw] -> xh fp16 [b][hw][384] ----------------
__global__ __launch_bounds__(256)
void xpose_split(const float* __restrict__ x, __half* __restrict__ xh)
{
    __shared__ float t[64][33];
    int hw0 = blockIdx.x << 5, c0 = blockIdx.y << 6, b = blockIdx.z;
    int tx = threadIdx.x & 31, ty = threadIdx.x >> 5;
#pragma unroll
    for (int i = 0; i < 8; i++) {
        int c = ty + i * 8;
        t[c][tx] = x[(((long)b * DIM + c0 + c) << 14) + hw0 + tx];
    }
    __syncthreads();
#pragma unroll
    for (int i = 0; i < 4; i++) {
        int row = ty * 4 + i;
        float v0 = t[tx * 2][row], v1 = t[tx * 2 + 1][row];
        long o = ((long)b * HW + hw0 + row) * DIM + c0 + tx * 2;
        *(__half2*)&xh[o] = __halves2half2(__float2half_rn(v0), __float2half_rn(v1));
    }
}

// ---------------- fp16 2-term GEMM via mma.sync ----------------
// C = (Ah+Al)*Bh.  mode 0: write __half output (no scale). mode 1: write fp32 with sigma scale.
#define BG_STAGE 32768
#define BG_SMEM (3 * BG_STAGE)
#define KTILES (GK / 32)

__global__ void __launch_bounds__(256)
bgemm(const __half* __restrict__ Ah, const __half* __restrict__ Al,
      const __half* __restrict__ Bh,
      float* __restrict__ C, __half* __restrict__ Ch, long strideC, int mode)
{
    extern __shared__ char smem[];
    uint32_t sb = smem_u32(smem);
    int tid = threadIdx.x, wid = tid >> 5, lane = tid & 31;
    int m0 = blockIdx.x << 7, n0 = blockIdx.y << 8, bz = blockIdx.z;
    int wm = (wid >> 2) * 64;
    int wn = (wid & 3) * 64;

    const __half* ahp = Ah + (long)m0 * GK;
    const __half* alp = Al + (long)m0 * GK;
    const __half* bhp = Bh + (long)bz * HW * DIM + (long)n0 * GK;

    float acc[4][8][4];
#pragma unroll
    for (int i = 0; i < 4; i++)
#pragma unroll
        for (int j = 0; j < 8; j++)
#pragma unroll
            for (int k = 0; k < 4; k++) acc[i][j][k] = 0.f;

    int lrow = tid >> 2, lc = tid & 3;

#define LOAD_STAGE(kc) do { \
        int _k0 = (kc) << 5; \
        uint32_t _sb = sb + ((kc) % 3) * BG_STAGE; \
        _Pragma("unroll") \
        for (int _i = 0; _i < 2; _i++) { \
            int _row = (_i << 6) + lrow; \
            long _go = (long)_row * GK + _k0 + lc * 8; \
            cpasync16(_sb + swz(_row, lc), ahp + _go); \
            cpasync16(_sb + 8192 + swz(_row, lc), alp + _go); \
        } \
        _Pragma("unroll") \
        for (int _i = 0; _i < 4; _i++) { \
            int _row = (_i << 6) + lrow; \
            long _go = (long)_row * GK + _k0 + lc * 8; \
            cpasync16(_sb + 16384 + swz(_row, lc), bhp + _go); \
        } \
        CP_COMMIT(); \
    } while (0)

    LOAD_STAGE(0);
    LOAD_STAGE(1);

    for (int kc = 0; kc < KTILES; kc++) {
        if (kc + 2 < KTILES) { LOAD_STAGE(kc + 2); CP_WAIT2(); }
        else                 { CP_WAIT0(); }
        __syncthreads();

        uint32_t st = sb + (kc % 3) * BG_STAGE;
#pragma unroll
        for (int ks = 0; ks < 2; ks++) {
            uint32_t bh[8][2];
#pragma unroll
            for (int p = 0; p < 4; p++) {
                int nrow = wn + p * 16 + (lane & 7) + ((lane >> 4) & 1) * 8;
                int c = ks * 2 + ((lane >> 3) & 1);
                uint32_t r[4];
                ldsm4(r, st + 16384 + swz(nrow, c));
                bh[p * 2][0] = r[0]; bh[p * 2][1] = r[1];
                bh[p * 2 + 1][0] = r[2]; bh[p * 2 + 1][1] = r[3];
            }
#pragma unroll
            for (int mt = 0; mt < 4; mt++) {
                int arow = wm + mt * 16 + (lane & 7) + ((lane >> 3) & 1) * 8;
                int c = ks * 2 + ((lane >> 4) & 1);
                uint32_t ah[4], al[4];
                ldsm4(ah, st + swz(arow, c));
                ldsm4(al, st + 8192 + swz(arow, c));
#pragma unroll
                for (int nt = 0; nt < 8; nt++) {
                    mma_f16(acc[mt][nt], ah, bh[nt]);
                    mma_f16(acc[mt][nt], al, bh[nt]);
                }
            }
        }
        __syncthreads();
    }

    if (mode == 0) {
        __half* Cb = Ch + (long)bz * strideC;
#pragma unroll
        for (int mt = 0; mt < 4; mt++) {
            int m = m0 + wm + mt * 16 + (lane >> 2);
#pragma unroll
            for (int nt = 0; nt < 8; nt++) {
                int n = n0 + wn + nt * 8 + (lane & 3) * 2;
                *(__half2*)&Cb[(long)m * HW + n] = __halves2half2(
                    __float2half_rn(acc[mt][nt][0]), __float2half_rn(acc[mt][nt][1]));
                *(__half2*)&Cb[(long)(m + 8) * HW + n] = __halves2half2(
                    __float2half_rn(acc[mt][nt][2]), __float2half_rn(acc[mt][nt][3]));
            }
        }
    } else {
        float sc = g_sigma[3];
        float* Cb = C + (long)bz * strideC;
#pragma unroll
        for (int mt = 0; mt < 4; mt++) {
            int m = m0 + wm + mt * 16 + (lane >> 2);
#pragma unroll
            for (int nt = 0; nt < 8; nt++) {
                int n = n0 + wn + nt * 8 + (lane & 3) * 2;
                float2 v0 = make_float2(acc[mt][nt][0] * sc, acc[mt][nt][1] * sc);
                float2 v1 = make_float2(acc[mt][nt][2] * sc, acc[mt][nt][3] * sc);
                *(float2*)&Cb[(long)m * HW + n] = v0;
                *(float2*)&Cb[(long)(m + 8) * HW + n] = v1;
            }
        }
    }
#undef LOAD_STAGE
}

// ---------------- 3x3 depthwise conv (fp16 I/O, fp32 math), fused q/k norm ----------------
__global__ __launch_bounds__(128)
void dwconv(const __half* __restrict__ in, const float* __restrict__ w,
            __half* __restrict__ out)
{
    int ch = blockIdx.x, b = blockIdx.y;
    const __half* ip = in + (((long)b * C3 + ch) << 14);
    __half* op = out + (((long)b * C3 + ch) << 14);
    int x = threadIdx.x;

    __shared__ float sr[2][130];
    __shared__ float red[128];

    float w00 = w[ch * 9 + 0], w01 = w[ch * 9 + 1], w02 = w[ch * 9 + 2];
    float w10 = w[ch * 9 + 3], w11 = w[ch * 9 + 4], w12 = w[ch * 9 + 5];
    float w20 = w[ch * 9 + 6], w21 = w[ch * 9 + 7], w22 = w[ch * 9 + 8];

    float l0 = 0.f, m0 = 0.f, r0 = 0.f;
    float l1, m1, r1, l2, m2, r2;

    float vcur = __half2float(ip[x]);
    float vpref = __half2float(ip[128 + x]);
    sr[0][x + 1] = vcur;
    if (x == 0) { sr[0][0] = 0.f; sr[0][129] = 0.f; }
    __syncthreads();
    l1 = sr[0][x]; m1 = vcur; r1 = sr[0][x + 2];

    float ssq = 0.f;
    for (int y = 0; y < 128; y++) {
        if (y < 127) {
            int buf = (y + 1) & 1;
            sr[buf][x + 1] = vpref;
            if (x == 0) { sr[buf][0] = 0.f; sr[buf][129] = 0.f; }
            float vnext = (y < 126) ? __half2float(ip[((y + 2) << 7) + x]) : 0.f;
            __syncthreads();
            l2 = sr[buf][x]; m2 = vpref; r2 = sr[buf][x + 2];
            vpref = vnext;
        } else {
            l2 = 0.f; m2 = 0.f; r2 = 0.f;
        }
        float s = l0 * w00 + m0 * w01 + r0 * w02
                + l1 * w10 + m1 * w11 + r1 * w12
                + l2 * w20 + m2 * w21 + r2 * w22;
        op[(y << 7) + x] = __float2half_rn(s);
        ssq += s * s;
        l0 = l1; m0 = m1; r0 = r1;
        l1 = l2; m1 = m2; r1 = r2;
    }

    if (ch < 2 * DIM) {
        red[x] = ssq; __syncthreads();
        for (int s = 64; s > 0; s >>= 1) {
            if (x < s) red[x] += red[x + s];
            __syncthreads();
        }
        if (x == 0) g_invnorm[b * 2 * DIM + ch] = 1.f / fmaxf(sqrtf(red[0]), EPS);
    }
}

// ---------------- attention logits via mma.sync (fp16 hi, 1-term, cp.async staged) -------
// S[48x48] partial over n-chunk of 1024. grid (NCHUNKS, 32), block 96 (3 warps).
// smem: 2 buffers x 96 rows (48 q + 48 k) x 128B = 24KB
__global__ __launch_bounds__(96)
void attn_s(const __half* __restrict__ t)
{
    int bh = blockIdx.y;
    int b = bh >> 3, head = bh & 7;
    int nb = blockIdx.x * (HW / NCHUNKS);   // 1024
    const __half* qp = t + ((((long)b * C3) + head * CH) << 14);
    const __half* kp = t + ((((long)b * C3) + DIM + head * CH) << 14);

    __shared__ __align__(16) char smem[2 * 96 * 128];
    uint32_t sb = smem_u32(smem);
    int tid = threadIdx.x, w = tid >> 5, lane = tid & 31;

    float acc[6][4];
#pragma unroll
    for (int i = 0; i < 6; i++)
#pragma unroll
        for (int j = 0; j < 4; j++) acc[i][j] = 0.f;

#define AS_LOAD(kc) do { \
        int _off = nb + (kc) * 64; \
        uint32_t _sb = sb + ((kc) & 1) * 12288; \
        _Pragma("unroll") \
        for (int _i = 0; _i < 8; _i++) { \
            int _g = _i * 96 + tid; \
            int _row = _g >> 3, _c = _g & 7; \
            const __half* _src = (_row < 48) \
                ? qp + (((long)_row) << 14) + _off + _c * 8 \
                : kp + (((long)(_row - 48)) << 14) + _off + _c * 8; \
            cpasync16(_sb + swz128(_row, _c), _src); \
        } \
        CP_COMMIT(); \
    } while (0)

    AS_LOAD(0);
    for (int kc = 0; kc < 16; kc++) {
        if (kc < 15) { AS_LOAD(kc + 1); CP_WAIT1(); }
        else         { CP_WAIT0(); }
        __syncthreads();

        uint32_t st = sb + (kc & 1) * 12288;
#pragma unroll
        for (int ks = 0; ks < 4; ks++) {
            int ar = w * 16 + (lane & 7) + ((lane >> 3) & 1) * 8;
            int ac = ks * 2 + ((lane >> 4) & 1);
            uint32_t ah[4];
            ldsm4(ah, st + swz128(ar, ac));

            uint32_t bhf[6][2];
            int br = (lane & 7) + ((lane >> 4) & 1) * 8;
            int bc = ks * 2 + ((lane >> 3) & 1);
#pragma unroll
            for (int p = 0; p < 3; p++) {
                uint32_t r[4];
                ldsm4(r, st + swz128(48 + p * 16 + br, bc));
                bhf[p * 2][0] = r[0]; bhf[p * 2][1] = r[1];
                bhf[p * 2 + 1][0] = r[2]; bhf[p * 2 + 1][1] = r[3];
            }
#pragma unroll
            for (int nt = 0; nt < 6; nt++)
                mma_f16(acc[nt], ah, bhf[nt]);
        }
        __syncthreads();
    }
#undef AS_LOAD

    float* Sp = g_Spart + ((long)blockIdx.x * 32 + bh) * (CH * CH);
    int c0 = w * 16 + (lane >> 2);
#pragma unroll
    for (int nt = 0; nt < 6; nt++) {
        int d = nt * 8 + (lane & 3) * 2;
        *(float2*)&Sp[c0 * CH + d] = make_float2(acc[nt][0], acc[nt][1]);
        *(float2*)&Sp[(c0 + 8) * CH + d] = make_float2(acc[nt][2], acc[nt][3]);
    }
}

// ---------------- finalize: reduce partials, scale, clamp, softmax ----------------
__global__ __launch_bounds__(64)
void softmax_kernel(const float* __restrict__ temp)
{
    int blk = blockIdx.x;
    int bh = blk / CH, c = blk % CH;
    int b = bh >> 3, head = bh & 7;
    int d = threadIdx.x;
    __shared__ float sm[64];

    float myv = 0.f, val = -1e30f;
    if (d < CH) {
        float raw = 0.f;
#pragma unroll
        for (int ch = 0; ch < NCHUNKS; ch++)
            raw += g_Spart[((long)ch * 32 + bh) * (CH * CH) + c * CH + d];
        float invq = g_invnorm[b * 2 * DIM + head * CH + c];
        float invk = g_invnorm[b * 2 * DIM + DIM + head * CH + d];
        myv = raw * invq * invk * temp[head];
        myv = fminf(fmaxf(myv, -CLAMPV), CLAMPV);
        val = myv;
    }
    sm[d] = val; __syncthreads();
    for (int s = 32; s > 0; s >>= 1) { if (d < s) sm[d] = fmaxf(sm[d], sm[d + s]); __syncthreads(); }
    float m = sm[0]; __syncthreads();
    float e = (d < CH) ? expf(myv - m) : 0.f;
    sm[d] = e; __syncthreads();
    for (int s = 32; s > 0; s >>= 1) { if (d < s) sm[d] += sm[d + s]; __syncthreads(); }
    if (d < CH) g_S[(long)bh * (CH * CH) + c * CH + d] = e / sm[0];
}

// ---------------- out = attn @ v (v fp16), written TRANSPOSED as fp16 [b][n][384] --------
__global__ __launch_bounds__(256)
void attn_o(const __half* __restrict__ t, __half* __restrict__ aoh)
{
    int bh = blockIdx.y;
    int b = bh >> 3, head = bh & 7;
    const __half* vp = t + ((((long)b * C3) + 2 * DIM + head * CH) << 14);

    __shared__ float Ss[CH * CH];
    for (int i = threadIdx.x; i < CH * CH; i += 256)
        Ss[i] = g_S[(long)bh * (CH * CH) + i];
    __syncthreads();

    int n = blockIdx.x * 512 + threadIdx.x;
    float acc0[CH], acc1[CH];
#pragma unroll
    for (int c = 0; c < CH; c++) { acc0[c] = 0.f; acc1[c] = 0.f; }

    for (int d = 0; d < CH; d++) {
        float v0 = __half2float(vp[(d << 14) + n]);
        float v1 = __half2float(vp[(d << 14) + n + 256]);
#pragma unroll
        for (int c = 0; c < CH; c++) {
            float s = Ss[c * CH + d];
            acc0[c] = fmaf(s, v0, acc0[c]);
            acc1[c] = fmaf(s, v1, acc1[c]);
        }
    }
    long o0 = ((long)b * HW + n) * DIM + head * CH;
    long o1 = ((long)b * HW + n + 256) * DIM + head * CH;
#pragma unroll
    for (int c = 0; c < CH; c += 2) {
        *(__half2*)&aoh[o0 + c] = __halves2half2(
            __float2half_rn(acc0[c]), __float2half_rn(acc0[c + 1]));
        *(__half2*)&aoh[o1 + c] = __halves2half2(
            __float2half_rn(acc1[c]), __float2half_rn(acc1[c + 1]));
    }
}

// ---------------- launch ----------------
extern "C" void kernel_launch(void* const* d_in, const int* in_sizes, int n_in,
                              void* d_out, int out_size)
{
    const float* x     = (const float*)d_in[0];
    const float* qkvw  = (const float*)d_in[1];
    const float* dww   = (const float*)d_in[2];
    const float* projw = (const float*)d_in[3];
    const float* temp  = (const float*)d_in[4];
    const float* uq    = (const float*)d_in[5];
    const float* ud    = (const float*)d_in[6];
    const float* up    = (const float*)d_in[7];
    float* out = (float*)d_out;

    __half *t0h, *t1h, *xh, *aoh, *wqh, *wql, *wph, *wpl;
    cudaGetSymbolAddress((void**)&t0h, g_t0h);
    cudaGetSymbolAddress((void**)&t1h, g_t1h);
    cudaGetSymbolAddress((void**)&xh, g_xh);
    cudaGetSymbolAddress((void**)&aoh, g_aoh);
    cudaGetSymbolAddress((void**)&wqh, g_wqh);
    cudaGetSymbolAddress((void**)&wql, g_wql);
    cudaGetSymbolAddress((void**)&wph, g_wph);
    cudaGetSymbolAddress((void**)&wpl, g_wpl);

    cudaFuncSetAttribute(bgemm, cudaFuncAttributeMaxDynamicSharedMemorySize, BG_SMEM);

    // spectral sigmas (parallel pipeline) + combined output scale
    sigma_v<<<dim3(3, 8), 256>>>(qkvw, dww, projw, uq, ud, up);
    sigma_vfin<<<3, 256>>>(0);
    sigma_wv<<<dim3(3, 18), 256>>>(qkvw, dww, projw);
    scale_kernel<<<1, 32>>>();

    // fp16 splits: both weights in one kernel; x transpose+convert (hi only)
    split_w2<<<(C3 * DIM + DIM * DIM + 255) / 256, 256>>>(qkvw, projw, wqh, wql, wph, wpl);
    xpose_split<<<dim3(HW / 32, DIM / 64, BATCH), 256>>>(x, xh);

    // qkv 1x1 conv via fp16 2-term GEMM -> t0h fp16 [b][1152][hw]
    bgemm<<<dim3(C3 / 128, HW / 256, BATCH), 256, BG_SMEM>>>(
        wqh, wql, xh, nullptr, t0h, (long)C3 * HW, 0);

    // 3x3 depthwise conv (fp16 I/O, fp32 math) with fused q/k L2 norms
    dwconv<<<dim3(C3, BATCH), 128>>>(t0h, dww, t1h);

    // attention logits via mma (partials) + softmax
    attn_s<<<dim3(NCHUNKS, BATCH * HEADS), 96>>>(t1h);
    softmax_kernel<<<BATCH * HEADS * CH, 64>>>(temp);

    // out = attn @ v, fused transpose+convert to fp16
    attn_o<<<dim3(32, BATCH * HEADS), 256>>>(t1h, aoh);

    // proj 1x1 conv via fp16 2-term GEMM, fp32 out with combined sigma scale
    bgemm<<<dim3(DIM / 128, HW / 256, BATCH), 256, BG_SMEM>>>(
        wph, wpl, aoh, out, nullptr, (long)DIM * HW, 1);
}

// round 11
// speedup vs baseline: 4.0230x; 1.1834x over previous
#include <cuda_runtime.h>
#include <cuda_fp16.h>
#include <math.h>
#include <stdint.h>

#define BATCH 4
#define DIM 384
#define HEADS 8
#define CH 48            // DIM/HEADS
#define HW 16384         // 128*128
#define C3 1152          // 3*DIM
#define EPS 1e-12f
#define CLAMPV 50.0f
#define NCHUNKS 16
#define GK 384           // GEMM K (always DIM)

// ---------------- device scratch ----------------
__device__ __half g_t0h[(size_t)BATCH * C3 * HW];   // qkv GEMM output fp16
__device__ __half g_t1h[(size_t)BATCH * C3 * HW];   // depthwise output fp16
__device__ float g_sigma[4];
__device__ float g_invnorm[BATCH * 2 * DIM];
__device__ float g_Spart[NCHUNKS * BATCH * HEADS * CH * CH];
__device__ float g_S[BATCH * HEADS * CH * CH];
// sigma pipeline scratch
__device__ float g_vpart[3][8][DIM];
__device__ float g_wvpart[3][18];
__device__ float g_vssq[3];
// fp16 operands (transposed activations: [b][n=hw][k=384]; weights hi-only)
__device__ __half g_xh[(size_t)BATCH * HW * DIM];
__device__ __half g_aoh[(size_t)BATCH * HW * DIM];
__device__ __half g_wqh[C3 * DIM];
__device__ __half g_wph[DIM * DIM];

// ---------------- warp-mma helpers ----------------
__device__ __forceinline__ uint32_t smem_u32(const void* p) {
    uint32_t a;
    asm("{ .reg .u64 t; cvta.to.shared.u64 t, %1; cvt.u32.u64 %0, t; }" : "=r"(a) : "l"(p));
    return a;
}
__device__ __forceinline__ void cpasync16(uint32_t s, const void* g) {
    asm volatile("cp.async.cg.shared.global [%0], [%1], 16;" :: "r"(s), "l"(g));
}
#define CP_COMMIT() asm volatile("cp.async.commit_group;" ::: "memory")
#define CP_WAIT2()  asm volatile("cp.async.wait_group 2;" ::: "memory")
#define CP_WAIT1()  asm volatile("cp.async.wait_group 1;" ::: "memory")
#define CP_WAIT0()  asm volatile("cp.async.wait_group 0;" ::: "memory")

__device__ __forceinline__ void ldsm4(uint32_t* r, uint32_t addr) {
    asm volatile("ldmatrix.sync.aligned.m8n8.x4.shared.b16 {%0,%1,%2,%3}, [%4];"
        : "=r"(r[0]), "=r"(r[1]), "=r"(r[2]), "=r"(r[3]) : "r"(addr));
}
__device__ __forceinline__ void mma_f16(float* c, const uint32_t* a, const uint32_t* b) {
    asm volatile(
        "mma.sync.aligned.m16n8k16.row.col.f32.f16.f16.f32 "
        "{%0,%1,%2,%3}, {%4,%5,%6,%7}, {%8,%9}, {%0,%1,%2,%3};"
        : "+f"(c[0]), "+f"(c[1]), "+f"(c[2]), "+f"(c[3])
        : "r"(a[0]), "r"(a[1]), "r"(a[2]), "r"(a[3]), "r"(b[0]), "r"(b[1]));
}

// swizzled smem offset for an R-row x 32-f16 (64B) tile packed 2 rows/128B line.
__device__ __forceinline__ uint32_t swz(uint32_t row, uint32_t c) {
    return (row >> 1) * 128 + ((((row & 1) * 4 + c) ^ ((row >> 1) & 7)) * 16);
}
// swizzle for natural 128B rows (64 f16 per row), chunk c in 16B units
__device__ __forceinline__ uint32_t swz128(uint32_t row, uint32_t c) {
    return row * 128 + ((c ^ (row & 7)) * 16);
}

// ---------------- sigma pipeline ----------------
// stage 1: partial v = wm^T u over i-chunks. grid (3, 8), block 256
__global__ __launch_bounds__(256)
void sigma_v(const float* __restrict__ qkvw, const float* __restrict__ dww,
             const float* __restrict__ projw, const float* __restrict__ uq,
             const float* __restrict__ ud, const float* __restrict__ up)
{
    int which = blockIdx.x, ic = blockIdx.y;
    const float* wm; const float* u; int h, w;
    if (which == 0)      { wm = qkvw;  u = uq; h = C3;  w = DIM; }
    else if (which == 1) { wm = dww;   u = ud; h = C3;  w = 9;   }
    else                 { wm = projw; u = up; h = DIM; w = DIM; }
    int chunk = h >> 3;
    int i0 = ic * chunk, i1 = i0 + chunk;
    for (int j = threadIdx.x; j < w; j += 256) {
        float s = 0.f;
        for (int i = i0; i < i1; i++) s += wm[i * w + j] * u[i];
        g_vpart[which][ic][j] = s;
    }
}

// stage 2: partials of ||wm v||^2 with UNNORMALIZED v (sigma = ||Wv|| / max(||v||,eps)).
// grid (3, 18), block 256 (64 rows x 4 segs). Block y==0 also emits ||v||^2.
__global__ __launch_bounds__(256)
void sigma_wv(const float* __restrict__ qkvw, const float* __restrict__ dww,
              const float* __restrict__ projw)
{
    int which = blockIdx.x;
    const float* wm; int h, w;
    if (which == 0)      { wm = qkvw;  h = C3;  w = DIM; }
    else if (which == 1) { wm = dww;   h = C3;  w = 9;   }
    else                 { wm = projw; h = DIM; w = DIM; }
    if (blockIdx.y * 64 >= h) return;

    __shared__ float v[DIM];
    __shared__ float red[256];
    int tid = threadIdx.x;

    // reconstruct v = sum of 8 partials
    for (int j = tid; j < w; j += 256) {
        float s = 0.f;
#pragma unroll
        for (int ic = 0; ic < 8; ic++) s += g_vpart[which][ic][j];
        v[j] = s;
    }
    __syncthreads();

    if (blockIdx.y == 0 && tid < 32) {
        float ss = 0.f;
        for (int j = tid; j < w; j += 32) ss += v[j] * v[j];
#pragma unroll
        for (int o = 16; o > 0; o >>= 1) ss += __shfl_xor_sync(0xffffffff, ss, o);
        if (tid == 0) g_vssq[which] = ss;
    }

    int r = tid >> 2, seg = tid & 3;
    int i = blockIdx.y * 64 + r;
    float s = 0.f;
    if (i < h) {
        int j0 = seg * (w / 4), j1 = (seg + 1) * (w / 4);
        if (w == 9) { j0 = (seg == 0) ? 0 : 9; j1 = 9; }
        for (int j = j0; j < j1; j++) s += wm[i * w + j] * v[j];
    }
    s += __shfl_xor_sync(0xffffffff, s, 1);
    s += __shfl_xor_sync(0xffffffff, s, 2);
    float ssq = (seg == 0 && i < h) ? s * s : 0.f;

    red[tid] = ssq; __syncthreads();
    for (int st = 128; st > 0; st >>= 1) {
        if (tid < st) red[tid] += red[tid + st];
        __syncthreads();
    }
    if (tid == 0) g_wvpart[which][blockIdx.y] = red[0];
}

// stage 3: sigma + combined scale. 1 block
__global__ void scale_kernel()
{
    if (threadIdx.x == 0) {
        float comb = 1.f;
        int np[3] = {18, 18, 6};
        for (int which = 0; which < 3; which++) {
            float wv = 0.f;
            for (int j = 0; j < np[which]; j++) wv += g_wvpart[which][j];
            float mv = fmaxf(sqrtf(g_vssq[which]), EPS);
            float s2 = wv / (mv * mv);                 // = ||W v_hat||^2
            float sig = s2 / fmaxf(sqrtf(s2), EPS);    // = ||W v_hat||
            comb /= (sig + EPS);
        }
        g_sigma[3] = comb;
    }
}

// ---------------- fp32 -> fp16 convert of BOTH weight matrices (hi only) ----------------
__global__ __launch_bounds__(256)
void conv_w(const float* __restrict__ qkvw, const float* __restrict__ projw,
            __half* __restrict__ qh, __half* __restrict__ ph)
{
    int i = blockIdx.x * 256 + threadIdx.x;
    if (i < C3 * DIM) {
        qh[i] = __float2half_rn(qkvw[i]);
    } else if (i < C3 * DIM + DIM * DIM) {
        int j = i - C3 * DIM;
        ph[j] = __float2half_rn(projw[j]);
    }
}

// ---------------- transpose + convert: x [b][c=384][hw] -> xh fp16 [b][hw][384] ----------------
__global__ __launch_bounds__(256)
void xpose_split(const float* __restrict__ x, __half* __restrict__ xh)
{
    __shared__ float t[64][33];
    int hw0 = blockIdx.x << 5, c0 = blockIdx.y << 6, b = blockIdx.z;
    int tx = threadIdx.x & 31, ty = threadIdx.x >> 5;
#pragma unroll
    for (int i = 0; i < 8; i++) {
        int c = ty + i * 8;
        t[c][tx] = x[(((long)b * DIM + c0 + c) << 14) + hw0 + tx];
    }
    __syncthreads();
#pragma unroll
    for (int i = 0; i < 4; i++) {
        int row = ty * 4 + i;
        float v0 = t[tx * 2][row], v1 = t[tx * 2 + 1][row];
        long o = ((long)b * HW + hw0 + row) * DIM + c0 + tx * 2;
        *(__half2*)&xh[o] = __halves2half2(__float2half_rn(v0), __float2half_rn(v1));
    }
}

// ---------------- fp16 1-term GEMM via mma.sync ----------------
// C = Ah * Bh.  mode 0: write __half output (no scale). mode 1: fp32 out with sigma scale.
// Block 128x256x32, 8 warps (2Mx4N), warp tile 64x64, cp.async 3-stage.
// Stage: Ah (8KB) + Bh (16KB) = 24KB; 3 stages = 72KB.
#define BG_STAGE 24576
#define BG_SMEM (3 * BG_STAGE)
#define KTILES (GK / 32)

__global__ void __launch_bounds__(256)
bgemm(const __half* __restrict__ Ah, const __half* __restrict__ Bh,
      float* __restrict__ C, __half* __restrict__ Ch, long strideC, int mode)
{
    extern __shared__ char smem[];
    uint32_t sb = smem_u32(smem);
    int tid = threadIdx.x, wid = tid >> 5, lane = tid & 31;
    int m0 = blockIdx.x << 7, n0 = blockIdx.y << 8, bz = blockIdx.z;
    int wm = (wid >> 2) * 64;
    int wn = (wid & 3) * 64;

    const __half* ahp = Ah + (long)m0 * GK;
    const __half* bhp = Bh + (long)bz * HW * DIM + (long)n0 * GK;

    float acc[4][8][4];
#pragma unroll
    for (int i = 0; i < 4; i++)
#pragma unroll
        for (int j = 0; j < 8; j++)
#pragma unroll
            for (int k = 0; k < 4; k++) acc[i][j][k] = 0.f;

    int lrow = tid >> 2, lc = tid & 3;

#define LOAD_STAGE(kc) do { \
        int _k0 = (kc) << 5; \
        uint32_t _sb = sb + ((kc) % 3) * BG_STAGE; \
        _Pragma("unroll") \
        for (int _i = 0; _i < 2; _i++) { \
            int _row = (_i << 6) + lrow; \
            cpasync16(_sb + swz(_row, lc), ahp + (long)_row * GK + _k0 + lc * 8); \
        } \
        _Pragma("unroll") \
        for (int _i = 0; _i < 4; _i++) { \
            int _row = (_i << 6) + lrow; \
            cpasync16(_sb + 8192 + swz(_row, lc), bhp + (long)_row * GK + _k0 + lc * 8); \
        } \
        CP_COMMIT(); \
    } while (0)

    LOAD_STAGE(0);
    LOAD_STAGE(1);

    for (int kc = 0; kc < KTILES; kc++) {
        if (kc + 2 < KTILES) { LOAD_STAGE(kc + 2); CP_WAIT2(); }
        else                 { CP_WAIT0(); }
        __syncthreads();

        uint32_t st = sb + (kc % 3) * BG_STAGE;
#pragma unroll
        for (int ks = 0; ks < 2; ks++) {
            uint32_t bh[8][2];
#pragma unroll
            for (int p = 0; p < 4; p++) {
                int nrow = wn + p * 16 + (lane & 7) + ((lane >> 4) & 1) * 8;
                int c = ks * 2 + ((lane >> 3) & 1);
                uint32_t r[4];
                ldsm4(r, st + 8192 + swz(nrow, c));
                bh[p * 2][0] = r[0]; bh[p * 2][1] = r[1];
                bh[p * 2 + 1][0] = r[2]; bh[p * 2 + 1][1] = r[3];
            }
#pragma unroll
            for (int mt = 0; mt < 4; mt++) {
                int arow = wm + mt * 16 + (lane & 7) + ((lane >> 3) & 1) * 8;
                int c = ks * 2 + ((lane >> 4) & 1);
                uint32_t ah[4];
                ldsm4(ah, st + swz(arow, c));
#pragma unroll
                for (int nt = 0; nt < 8; nt++)
                    mma_f16(acc[mt][nt], ah, bh[nt]);
            }
        }
        __syncthreads();
    }

    if (mode == 0) {
        __half* Cb = Ch + (long)bz * strideC;
#pragma unroll
        for (int mt = 0; mt < 4; mt++) {
            int m = m0 + wm + mt * 16 + (lane >> 2);
#pragma unroll
            for (int nt = 0; nt < 8; nt++) {
                int n = n0 + wn + nt * 8 + (lane & 3) * 2;
                *(__half2*)&Cb[(long)m * HW + n] = __halves2half2(
                    __float2half_rn(acc[mt][nt][0]), __float2half_rn(acc[mt][nt][1]));
                *(__half2*)&Cb[(long)(m + 8) * HW + n] = __halves2half2(
                    __float2half_rn(acc[mt][nt][2]), __float2half_rn(acc[mt][nt][3]));
            }
        }
    } else {
        float sc = g_sigma[3];
        float* Cb = C + (long)bz * strideC;
#pragma unroll
        for (int mt = 0; mt < 4; mt++) {
            int m = m0 + wm + mt * 16 + (lane >> 2);
#pragma unroll
            for (int nt = 0; nt < 8; nt++) {
                int n = n0 + wn + nt * 8 + (lane & 3) * 2;
                float2 v0 = make_float2(acc[mt][nt][0] * sc, acc[mt][nt][1] * sc);
                float2 v1 = make_float2(acc[mt][nt][2] * sc, acc[mt][nt][3] * sc);
                *(float2*)&Cb[(long)m * HW + n] = v0;
                *(float2*)&Cb[(long)(m + 8) * HW + n] = v1;
            }
        }
    }
#undef LOAD_STAGE
}

// ---------------- 3x3 depthwise conv (fp16 I/O, fp32 math), fused q/k norm ----------------
__global__ __launch_bounds__(128)
void dwconv(const __half* __restrict__ in, const float* __restrict__ w,
            __half* __restrict__ out)
{
    int ch = blockIdx.x, b = blockIdx.y;
    const __half* ip = in + (((long)b * C3 + ch) << 14);
    __half* op = out + (((long)b * C3 + ch) << 14);
    int x = threadIdx.x;

    __shared__ float sr[2][130];
    __shared__ float red[128];

    float w00 = w[ch * 9 + 0], w01 = w[ch * 9 + 1], w02 = w[ch * 9 + 2];
    float w10 = w[ch * 9 + 3], w11 = w[ch * 9 + 4], w12 = w[ch * 9 + 5];
    float w20 = w[ch * 9 + 6], w21 = w[ch * 9 + 7], w22 = w[ch * 9 + 8];

    float l0 = 0.f, m0 = 0.f, r0 = 0.f;
    float l1, m1, r1, l2, m2, r2;

    float vcur = __half2float(ip[x]);
    float vpref = __half2float(ip[128 + x]);
    sr[0][x + 1] = vcur;
    if (x == 0) { sr[0][0] = 0.f; sr[0][129] = 0.f; }
    __syncthreads();
    l1 = sr[0][x]; m1 = vcur; r1 = sr[0][x + 2];

    float ssq = 0.f;
    for (int y = 0; y < 128; y++) {
        if (y < 127) {
            int buf = (y + 1) & 1;
            sr[buf][x + 1] = vpref;
            if (x == 0) { sr[buf][0] = 0.f; sr[buf][129] = 0.f; }
            float vnext = (y < 126) ? __half2float(ip[((y + 2) << 7) + x]) : 0.f;
            __syncthreads();
            l2 = sr[buf][x]; m2 = vpref; r2 = sr[buf][x + 2];
            vpref = vnext;
        } else {
            l2 = 0.f; m2 = 0.f; r2 = 0.f;
        }
        float s = l0 * w00 + m0 * w01 + r0 * w02
                + l1 * w10 + m1 * w11 + r1 * w12
                + l2 * w20 + m2 * w21 + r2 * w22;
        op[(y << 7) + x] = __float2half_rn(s);
        ssq += s * s;
        l0 = l1; m0 = m1; r0 = r1;
        l1 = l2; m1 = m2; r1 = r2;
    }

    if (ch < 2 * DIM) {
        red[x] = ssq; __syncthreads();
        for (int s = 64; s > 0; s >>= 1) {
            if (x < s) red[x] += red[x + s];
            __syncthreads();
        }
        if (x == 0) g_invnorm[b * 2 * DIM + ch] = 1.f / fmaxf(sqrtf(red[0]), EPS);
    }
}

// ---------------- attention logits via mma.sync (fp16, cp.async staged) -------
// S[48x48] partial over n-chunk of 1024. grid (NCHUNKS, 32), block 96 (3 warps).
__global__ __launch_bounds__(96)
void attn_s(const __half* __restrict__ t)
{
    int bh = blockIdx.y;
    int b = bh >> 3, head = bh & 7;
    int nb = blockIdx.x * (HW / NCHUNKS);   // 1024
    const __half* qp = t + ((((long)b * C3) + head * CH) << 14);
    const __half* kp = t + ((((long)b * C3) + DIM + head * CH) << 14);

    __shared__ __align__(16) char smem[2 * 96 * 128];
    uint32_t sb = smem_u32(smem);
    int tid = threadIdx.x, w = tid >> 5, lane = tid & 31;

    float acc[6][4];
#pragma unroll
    for (int i = 0; i < 6; i++)
#pragma unroll
        for (int j = 0; j < 4; j++) acc[i][j] = 0.f;

#define AS_LOAD(kc) do { \
        int _off = nb + (kc) * 64; \
        uint32_t _sb = sb + ((kc) & 1) * 12288; \
        _Pragma("unroll") \
        for (int _i = 0; _i < 8; _i++) { \
            int _g = _i * 96 + tid; \
            int _row = _g >> 3, _c = _g & 7; \
            const __half* _src = (_row < 48) \
                ? qp + (((long)_row) << 14) + _off + _c * 8 \
                : kp + (((long)(_row - 48)) << 14) + _off + _c * 8; \
            cpasync16(_sb + swz128(_row, _c), _src); \
        } \
        CP_COMMIT(); \
    } while (0)

    AS_LOAD(0);
    for (int kc = 0; kc < 16; kc++) {
        if (kc < 15) { AS_LOAD(kc + 1); CP_WAIT1(); }
        else         { CP_WAIT0(); }
        __syncthreads();

        uint32_t st = sb + (kc & 1) * 12288;
#pragma unroll
        for (int ks = 0; ks < 4; ks++) {
            int ar = w * 16 + (lane & 7) + ((lane >> 3) & 1) * 8;
            int ac = ks * 2 + ((lane >> 4) & 1);
            uint32_t ah[4];
            ldsm4(ah, st + swz128(ar, ac));

            uint32_t bhf[6][2];
            int br = (lane & 7) + ((lane >> 4) & 1) * 8;
            int bc = ks * 2 + ((lane >> 3) & 1);
#pragma unroll
            for (int p = 0; p < 3; p++) {
                uint32_t r[4];
                ldsm4(r, st + swz128(48 + p * 16 + br, bc));
                bhf[p * 2][0] = r[0]; bhf[p * 2][1] = r[1];
                bhf[p * 2 + 1][0] = r[2]; bhf[p * 2 + 1][1] = r[3];
            }
#pragma unroll
            for (int nt = 0; nt < 6; nt++)
                mma_f16(acc[nt], ah, bhf[nt]);
        }
        __syncthreads();
    }
#undef AS_LOAD

    float* Sp = g_Spart + ((long)blockIdx.x * 32 + bh) * (CH * CH);
    int c0 = w * 16 + (lane >> 2);
#pragma unroll
    for (int nt = 0; nt < 6; nt++) {
        int d = nt * 8 + (lane & 3) * 2;
        *(float2*)&Sp[c0 * CH + d] = make_float2(acc[nt][0], acc[nt][1]);
        *(float2*)&Sp[(c0 + 8) * CH + d] = make_float2(acc[nt][2], acc[nt][3]);
    }
}

// ---------------- finalize: reduce partials, scale, clamp, softmax ----------------
__global__ __launch_bounds__(64)
void softmax_kernel(const float* __restrict__ temp)
{
    int blk = blockIdx.x;
    int bh = blk / CH, c = blk % CH;
    int b = bh >> 3, head = bh & 7;
    int d = threadIdx.x;
    __shared__ float sm[64];

    float myv = 0.f, val = -1e30f;
    if (d < CH) {
        float raw = 0.f;
#pragma unroll
        for (int ch = 0; ch < NCHUNKS; ch++)
            raw += g_Spart[((long)ch * 32 + bh) * (CH * CH) + c * CH + d];
        float invq = g_invnorm[b * 2 * DIM + head * CH + c];
        float invk = g_invnorm[b * 2 * DIM + DIM + head * CH + d];
        myv = raw * invq * invk * temp[head];
        myv = fminf(fmaxf(myv, -CLAMPV), CLAMPV);
        val = myv;
    }
    sm[d] = val; __syncthreads();
    for (int s = 32; s > 0; s >>= 1) { if (d < s) sm[d] = fmaxf(sm[d], sm[d + s]); __syncthreads(); }
    float m = sm[0]; __syncthreads();
    float e = (d < CH) ? expf(myv - m) : 0.f;
    sm[d] = e; __syncthreads();
    for (int s = 32; s > 0; s >>= 1) { if (d < s) sm[d] += sm[d + s]; __syncthreads(); }
    if (d < CH) g_S[(long)bh * (CH * CH) + c * CH + d] = e / sm[0];
}

// ---------------- out = attn @ v (v fp16), written TRANSPOSED as fp16 [b][n][384] --------
__global__ __launch_bounds__(256)
void attn_o(const __half* __restrict__ t, __half* __restrict__ aoh)
{
    int bh = blockIdx.y;
    int b = bh >> 3, head = bh & 7;
    const __half* vp = t + ((((long)b * C3) + 2 * DIM + head * CH) << 14);

    __shared__ float Ss[CH * CH];
    for (int i = threadIdx.x; i < CH * CH; i += 256)
        Ss[i] = g_S[(long)bh * (CH * CH) + i];
    __syncthreads();

    int n = blockIdx.x * 512 + threadIdx.x;
    float acc0[CH], acc1[CH];
#pragma unroll
    for (int c = 0; c < CH; c++) { acc0[c] = 0.f; acc1[c] = 0.f; }

    for (int d = 0; d < CH; d++) {
        float v0 = __half2float(vp[(d << 14) + n]);
        float v1 = __half2float(vp[(d << 14) + n + 256]);
#pragma unroll
        for (int c = 0; c < CH; c++) {
            float s = Ss[c * CH + d];
            acc0[c] = fmaf(s, v0, acc0[c]);
            acc1[c] = fmaf(s, v1, acc1[c]);
        }
    }
    long o0 = ((long)b * HW + n) * DIM + head * CH;
    long o1 = ((long)b * HW + n + 256) * DIM + head * CH;
#pragma unroll
    for (int c = 0; c < CH; c += 2) {
        *(__half2*)&aoh[o0 + c] = __halves2half2(
            __float2half_rn(acc0[c]), __float2half_rn(acc0[c + 1]));
        *(__half2*)&aoh[o1 + c] = __halves2half2(
            __float2half_rn(acc1[c]), __float2half_rn(acc1[c + 1]));
    }
}

// ---------------- launch ----------------
extern "C" void kernel_launch(void* const* d_in, const int* in_sizes, int n_in,
                              void* d_out, int out_size)
{
    const float* x     = (const float*)d_in[0];
    const float* qkvw  = (const float*)d_in[1];
    const float* dww   = (const float*)d_in[2];
    const float* projw = (const float*)d_in[3];
    const float* temp  = (const float*)d_in[4];
    const float* uq    = (const float*)d_in[5];
    const float* ud    = (const float*)d_in[6];
    const float* up    = (const float*)d_in[7];
    float* out = (float*)d_out;

    __half *t0h, *t1h, *xh, *aoh, *wqh, *wph;
    cudaGetSymbolAddress((void**)&t0h, g_t0h);
    cudaGetSymbolAddress((void**)&t1h, g_t1h);
    cudaGetSymbolAddress((void**)&xh, g_xh);
    cudaGetSymbolAddress((void**)&aoh, g_aoh);
    cudaGetSymbolAddress((void**)&wqh, g_wqh);
    cudaGetSymbolAddress((void**)&wph, g_wph);

    cudaFuncSetAttribute(bgemm, cudaFuncAttributeMaxDynamicSharedMemorySize, BG_SMEM);

    // weight convert + x transpose first (GEMM inputs), sigma pipeline after
    conv_w<<<(C3 * DIM + DIM * DIM + 255) / 256, 256>>>(qkvw, projw, wqh, wph);
    xpose_split<<<dim3(HW / 32, DIM / 64, BATCH), 256>>>(x, xh);

    // spectral sigmas (3-stage pipeline; only needed by proj epilogue)
    sigma_v<<<dim3(3, 8), 256>>>(qkvw, dww, projw, uq, ud, up);
    sigma_wv<<<dim3(3, 18), 256>>>(qkvw, dww, projw);
    scale_kernel<<<1, 32>>>();

    // qkv 1x1 conv via fp16 GEMM -> t0h fp16 [b][1152][hw]
    bgemm<<<dim3(C3 / 128, HW / 256, BATCH), 256, BG_SMEM>>>(
        wqh, xh, nullptr, t0h, (long)C3 * HW, 0);

    // 3x3 depthwise conv (fp16 I/O, fp32 math) with fused q/k L2 norms
    dwconv<<<dim3(C3, BATCH), 128>>>(t0h, dww, t1h);

    // attention logits via mma (partials) + softmax
    attn_s<<<dim3(NCHUNKS, BATCH * HEADS), 96>>>(t1h);
    softmax_kernel<<<BATCH * HEADS * CH, 64>>>(temp);

    // out = attn @ v, fused transpose+convert to fp16
    attn_o<<<dim3(32, BATCH * HEADS), 256>>>(t1h, aoh);

    // proj 1x1 conv via fp16 GEMM, fp32 out with combined sigma scale
    bgemm<<<dim3(DIM / 128, HW / 256, BATCH), 256, BG_SMEM>>>(
        wph, aoh, out, nullptr, (long)DIM * HW, 1);
}

// round 13
// speedup vs baseline: 4.7185x; 1.1729x over previous
#include <cuda_runtime.h>
#include <cuda_fp16.h>
#include <math.h>
#include <stdint.h>

#define BATCH 4
#define DIM 384
#define HEADS 8
#define CH 48            // DIM/HEADS
#define HW 16384         // 128*128
#define C3 1152          // 3*DIM
#define EPS 1e-12f
#define CLAMPV 50.0f
#define NCHUNKS 16
#define GK 384           // GEMM K (always DIM)

// ---------------- device scratch ----------------
__device__ __half g_t0h[(size_t)BATCH * C3 * HW];   // qkv GEMM output fp16
__device__ __half g_t1h[(size_t)BATCH * C3 * HW];   // depthwise output fp16
__device__ float g_sigma[4];
__device__ float g_invnorm[BATCH * 2 * DIM];
__device__ float g_Spart[NCHUNKS * BATCH * HEADS * CH * CH];
__device__ float g_S[BATCH * HEADS * CH * CH];
// sigma pipeline scratch
__device__ float g_vpart[3][8][DIM];
__device__ float g_wvpart[3][18];
__device__ float g_vssq[3];
// fp16 operands
__device__ __half g_x16[(size_t)BATCH * DIM * HW];  // x converted, natural [b][c][hw]
__device__ __half g_wqh[C3 * DIM];                  // qkv weights fp16 [m][k]
__device__ __half g_wp2[(size_t)BATCH * DIM * DIM]; // W' = wp @ blockdiag(S), per batch

// ---------------- warp-mma helpers ----------------
__device__ __forceinline__ uint32_t smem_u32(const void* p) {
    uint32_t a;
    asm("{ .reg .u64 t; cvta.to.shared.u64 t, %1; cvt.u32.u64 %0, t; }" : "=r"(a) : "l"(p));
    return a;
}
__device__ __forceinline__ void cpasync16(uint32_t s, const void* g) {
    asm volatile("cp.async.cg.shared.global [%0], [%1], 16;" :: "r"(s), "l"(g));
}
#define CP_COMMIT() asm volatile("cp.async.commit_group;" ::: "memory")
#define CP_WAIT2()  asm volatile("cp.async.wait_group 2;" ::: "memory")
#define CP_WAIT1()  asm volatile("cp.async.wait_group 1;" ::: "memory")
#define CP_WAIT0()  asm volatile("cp.async.wait_group 0;" ::: "memory")

__device__ __forceinline__ void ldsm4(uint32_t* r, uint32_t addr) {
    asm volatile("ldmatrix.sync.aligned.m8n8.x4.shared.b16 {%0,%1,%2,%3}, [%4];"
        : "=r"(r[0]), "=r"(r[1]), "=r"(r[2]), "=r"(r[3]) : "r"(addr));
}
__device__ __forceinline__ void ldsm4t(uint32_t* r, uint32_t addr) {
    asm volatile("ldmatrix.sync.aligned.m8n8.x4.trans.shared.b16 {%0,%1,%2,%3}, [%4];"
        : "=r"(r[0]), "=r"(r[1]), "=r"(r[2]), "=r"(r[3]) : "r"(addr));
}
__device__ __forceinline__ void mma_f16(float* c, const uint32_t* a, const uint32_t* b) {
    asm volatile(
        "mma.sync.aligned.m16n8k16.row.col.f32.f16.f16.f32 "
        "{%0,%1,%2,%3}, {%4,%5,%6,%7}, {%8,%9}, {%0,%1,%2,%3};"
        : "+f"(c[0]), "+f"(c[1]), "+f"(c[2]), "+f"(c[3])
        : "r"(a[0]), "r"(a[1]), "r"(a[2]), "r"(a[3]), "r"(b[0]), "r"(b[1]));
}

// A-tile swizzle: R rows x 32 f16 (64B) packed 2 rows per 128B line.
__device__ __forceinline__ uint32_t swz(uint32_t row, uint32_t c) {
    return (row >> 1) * 128 + ((((row & 1) * 4 + c) ^ ((row >> 1) & 7)) * 16);
}
// natural 128B rows (64 f16 per row), chunk c in 16B units
__device__ __forceinline__ uint32_t swz128(uint32_t row, uint32_t c) {
    return row * 128 + ((c ^ (row & 7)) * 16);
}
// B-tile (k-rows of 256 f16 = 512B): XOR 16B-chunk within each 128B window by row&7
__device__ __forceinline__ uint32_t bswz(uint32_t row, uint32_t chunk) {
    return row * 512 + (((chunk) & 24u) | (((chunk) & 7u) ^ ((row) & 7u))) * 16;
}

// ---------------- sigma pipeline ----------------
__global__ __launch_bounds__(256)
void sigma_v(const float* __restrict__ qkvw, const float* __restrict__ dww,
             const float* __restrict__ projw, const float* __restrict__ uq,
             const float* __restrict__ ud, const float* __restrict__ up)
{
    int which = blockIdx.x, ic = blockIdx.y;
    const float* wm; const float* u; int h, w;
    if (which == 0)      { wm = qkvw;  u = uq; h = C3;  w = DIM; }
    else if (which == 1) { wm = dww;   u = ud; h = C3;  w = 9;   }
    else                 { wm = projw; u = up; h = DIM; w = DIM; }
    int chunk = h >> 3;
    int i0 = ic * chunk, i1 = i0 + chunk;
    for (int j = threadIdx.x; j < w; j += 256) {
        float s = 0.f;
        for (int i = i0; i < i1; i++) s += wm[i * w + j] * u[i];
        g_vpart[which][ic][j] = s;
    }
}

__global__ __launch_bounds__(256)
void sigma_wv(const float* __restrict__ qkvw, const float* __restrict__ dww,
              const float* __restrict__ projw)
{
    int which = blockIdx.x;
    const float* wm; int h, w;
    if (which == 0)      { wm = qkvw;  h = C3;  w = DIM; }
    else if (which == 1) { wm = dww;   h = C3;  w = 9;   }
    else                 { wm = projw; h = DIM; w = DIM; }
    if (blockIdx.y * 64 >= h) return;

    __shared__ float v[DIM];
    __shared__ float red[256];
    int tid = threadIdx.x;

    for (int j = tid; j < w; j += 256) {
        float s = 0.f;
#pragma unroll
        for (int ic = 0; ic < 8; ic++) s += g_vpart[which][ic][j];
        v[j] = s;
    }
    __syncthreads();

    if (blockIdx.y == 0 && tid < 32) {
        float ss = 0.f;
        for (int j = tid; j < w; j += 32) ss += v[j] * v[j];
#pragma unroll
        for (int o = 16; o > 0; o >>= 1) ss += __shfl_xor_sync(0xffffffff, ss, o);
        if (tid == 0) g_vssq[which] = ss;
    }

    int r = tid >> 2, seg = tid & 3;
    int i = blockIdx.y * 64 + r;
    float s = 0.f;
    if (i < h) {
        int j0 = seg * (w / 4), j1 = (seg + 1) * (w / 4);
        if (w == 9) { j0 = (seg == 0) ? 0 : 9; j1 = 9; }
        for (int j = j0; j < j1; j++) s += wm[i * w + j] * v[j];
    }
    s += __shfl_xor_sync(0xffffffff, s, 1);
    s += __shfl_xor_sync(0xffffffff, s, 2);
    float ssq = (seg == 0 && i < h) ? s * s : 0.f;

    red[tid] = ssq; __syncthreads();
    for (int st = 128; st > 0; st >>= 1) {
        if (tid < st) red[tid] += red[tid + st];
        __syncthreads();
    }
    if (tid == 0) g_wvpart[which][blockIdx.y] = red[0];
}

__global__ void scale_kernel()
{
    if (threadIdx.x == 0) {
        float comb = 1.f;
        int np[3] = {18, 18, 6};
        for (int which = 0; which < 3; which++) {
            float wv = 0.f;
            for (int j = 0; j < np[which]; j++) wv += g_wvpart[which][j];
            float mv = fmaxf(sqrtf(g_vssq[which]), EPS);
            float s2 = wv / (mv * mv);
            float sig = s2 / fmaxf(sqrtf(s2), EPS);
            comb /= (sig + EPS);
        }
        g_sigma[3] = comb;
    }
}

// ---------------- qkv weights fp32->fp16 ----------------
__global__ __launch_bounds__(256)
void conv_w(const float* __restrict__ qkvw, __half* __restrict__ qh)
{
    int i = blockIdx.x * 256 + threadIdx.x;
    if (i < C3 * DIM) qh[i] = __float2half_rn(qkvw[i]);
}

// ---------------- x fp32 -> fp16, same layout ----------------
__global__ __launch_bounds__(256)
void convert_x(const float* __restrict__ x, __half* __restrict__ x16)
{
    long i = ((long)blockIdx.x * 256 + threadIdx.x) * 4;
    if (i < (long)BATCH * DIM * HW) {
        float4 v = *(const float4*)&x[i];
        __half2 h[2];
        h[0] = __halves2half2(__float2half_rn(v.x), __float2half_rn(v.y));
        h[1] = __halves2half2(__float2half_rn(v.z), __float2half_rn(v.w));
        *(uint2*)&x16[i] = *(const uint2*)h;
    }
}

// ---------------- W' = wp @ blockdiag(S): grid (HEADS, BATCH), block 256 ----------------
__global__ __launch_bounds__(256)
void wprime(const float* __restrict__ projw, __half* __restrict__ wp2)
{
    int head = blockIdx.x, b = blockIdx.y;
    int bh = b * HEADS + head;
    __shared__ float S[CH][CH];
    for (int i = threadIdx.x; i < CH * CH; i += 256)
        S[i / CH][i % CH] = g_S[(long)bh * CH * CH + i];
    __syncthreads();

    int h0 = head * CH;
    // W'[o][h0+d] = sum_c wp[o][h0+c] * S[c][d]
    for (int idx = threadIdx.x; idx < DIM * CH; idx += 256) {
        int o = idx / CH, d = idx % CH;
        const float* wr = projw + (long)o * DIM + h0;
        float s = 0.f;
#pragma unroll 8
        for (int c = 0; c < CH; c++) s += wr[c] * S[c][d];
        wp2[((long)b * DIM + o) * DIM + h0 + d] = __float2half_rn(s);
    }
}

// ---------------- fp16 GEMM, B consumed in natural [K][N] layout (trans ldmatrix) ------
// C[m][n] = sum_k A[m][k] * B[k][n].  mode 0: fp16 out. mode 1: fp32 out * sigma.
// Block 128x256x32, 8 warps (2Mx4N), warp tile 64x64, cp.async 3-stage.
// Stage: A (8KB, swz rows) + B (16KB, 32 k-rows x 512B, bswz) = 24KB; 3 stages.
#define BG_STAGE 24576
#define BG_SMEM (3 * BG_STAGE)
#define KTILES (GK / 32)

__global__ void __launch_bounds__(256)
bgemmT(const __half* __restrict__ A, long strideA,
       const __half* __restrict__ B, long strideB,
       float* __restrict__ C, __half* __restrict__ Ch, long strideC, int mode)
{
    extern __shared__ char smem[];
    uint32_t sb = smem_u32(smem);
    int tid = threadIdx.x, wid = tid >> 5, lane = tid & 31;
    int m0 = blockIdx.x << 7, n0 = blockIdx.y << 8, bz = blockIdx.z;
    int wm = (wid >> 2) * 64;
    int wn = (wid & 3) * 64;

    const __half* ap = A + (long)bz * strideA + (long)m0 * GK;
    const __half* bp = B + (long)bz * strideB + n0;

    float acc[4][8][4];
#pragma unroll
    for (int i = 0; i < 4; i++)
#pragma unroll
        for (int j = 0; j < 8; j++)
#pragma unroll
            for (int k = 0; k < 4; k++) acc[i][j][k] = 0.f;

    int arow_l = tid >> 2, ac_l = tid & 3;       // A loader
    int brow_l = tid >> 3, bc_l = tid & 7;       // B loader

#define LOAD_STAGE(kc) do { \
        int _k0 = (kc) << 5; \
        uint32_t _sb = sb + ((kc) % 3) * BG_STAGE; \
        _Pragma("unroll") \
        for (int _i = 0; _i < 2; _i++) { \
            int _row = (_i << 6) + arow_l; \
            cpasync16(_sb + swz(_row, ac_l), ap + (long)_row * GK + _k0 + ac_l * 8); \
        } \
        _Pragma("unroll") \
        for (int _i = 0; _i < 4; _i++) { \
            int _ch = bc_l + _i * 8; \
            cpasync16(_sb + 8192 + bswz(brow_l, _ch), \
                      bp + (long)(_k0 + brow_l) * HW + _ch * 8); \
        } \
        CP_COMMIT(); \
    } while (0)

    LOAD_STAGE(0);
    LOAD_STAGE(1);

    for (int kc = 0; kc < KTILES; kc++) {
        if (kc + 2 < KTILES) { LOAD_STAGE(kc + 2); CP_WAIT2(); }
        else                 { CP_WAIT0(); }
        __syncthreads();

        uint32_t st = sb + (kc % 3) * BG_STAGE;
#pragma unroll
        for (int ks = 0; ks < 2; ks++) {
            uint32_t bh[8][2];
#pragma unroll
            for (int p = 0; p < 4; p++) {
                // trans ldmatrix: lane -> k-row, 16B col at n offset
                int row = ks * 16 + (lane & 7) + ((lane >> 3) & 1) * 8;
                int nh = wn + p * 16 + ((lane >> 4) & 1) * 8;
                uint32_t r[4];
                ldsm4t(r, st + 8192 + bswz(row, nh >> 3));
                bh[p * 2][0] = r[0]; bh[p * 2][1] = r[1];
                bh[p * 2 + 1][0] = r[2]; bh[p * 2 + 1][1] = r[3];
            }
#pragma unroll
            for (int mt = 0; mt < 4; mt++) {
                int ar = wm + mt * 16 + (lane & 7) + ((lane >> 3) & 1) * 8;
                int ac = ks * 2 + ((lane >> 4) & 1);
                uint32_t ah[4];
                ldsm4(ah, st + swz(ar, ac));
#pragma unroll
                for (int nt = 0; nt < 8; nt++)
                    mma_f16(acc[mt][nt], ah, bh[nt]);
            }
        }
        __syncthreads();
    }

    if (mode == 0) {
        __half* Cb = Ch + (long)bz * strideC;
#pragma unroll
        for (int mt = 0; mt < 4; mt++) {
            int m = m0 + wm + mt * 16 + (lane >> 2);
#pragma unroll
            for (int nt = 0; nt < 8; nt++) {
                int n = n0 + wn + nt * 8 + (lane & 3) * 2;
                *(__half2*)&Cb[(long)m * HW + n] = __halves2half2(
                    __float2half_rn(acc[mt][nt][0]), __float2half_rn(acc[mt][nt][1]));
                *(__half2*)&Cb[(long)(m + 8) * HW + n] = __halves2half2(
                    __float2half_rn(acc[mt][nt][2]), __float2half_rn(acc[mt][nt][3]));
            }
        }
    } else {
        float sc = g_sigma[3];
        float* Cb = C + (long)bz * strideC;
#pragma unroll
        for (int mt = 0; mt < 4; mt++) {
            int m = m0 + wm + mt * 16 + (lane >> 2);
#pragma unroll
            for (int nt = 0; nt < 8; nt++) {
                int n = n0 + wn + nt * 8 + (lane & 3) * 2;
                float2 v0 = make_float2(acc[mt][nt][0] * sc, acc[mt][nt][1] * sc);
                float2 v1 = make_float2(acc[mt][nt][2] * sc, acc[mt][nt][3] * sc);
                *(float2*)&Cb[(long)m * HW + n] = v0;
                *(float2*)&Cb[(long)(m + 8) * HW + n] = v1;
            }
        }
    }
#undef LOAD_STAGE
}

// ---------------- 3x3 depthwise conv (fp16 I/O, fp32 math), fused q/k norm ----------------
__global__ __launch_bounds__(128)
void dwconv(const __half* __restrict__ in, const float* __restrict__ w,
            __half* __restrict__ out)
{
    int ch = blockIdx.x, b = blockIdx.y;
    const __half* ip = in + (((long)b * C3 + ch) << 14);
    __half* op = out + (((long)b * C3 + ch) << 14);
    int x = threadIdx.x;

    __shared__ float sr[2][130];
    __shared__ float red[128];

    float w00 = w[ch * 9 + 0], w01 = w[ch * 9 + 1], w02 = w[ch * 9 + 2];
    float w10 = w[ch * 9 + 3], w11 = w[ch * 9 + 4], w12 = w[ch * 9 + 5];
    float w20 = w[ch * 9 + 6], w21 = w[ch * 9 + 7], w22 = w[ch * 9 + 8];

    float l0 = 0.f, m0 = 0.f, r0 = 0.f;
    float l1, m1, r1, l2, m2, r2;

    float vcur = __half2float(ip[x]);
    float vpref = __half2float(ip[128 + x]);
    sr[0][x + 1] = vcur;
    if (x == 0) { sr[0][0] = 0.f; sr[0][129] = 0.f; }
    __syncthreads();
    l1 = sr[0][x]; m1 = vcur; r1 = sr[0][x + 2];

    float ssq = 0.f;
    for (int y = 0; y < 128; y++) {
        if (y < 127) {
            int buf = (y + 1) & 1;
            sr[buf][x + 1] = vpref;
            if (x == 0) { sr[buf][0] = 0.f; sr[buf][129] = 0.f; }
            float vnext = (y < 126) ? __half2float(ip[((y + 2) << 7) + x]) : 0.f;
            __syncthreads();
            l2 = sr[buf][x]; m2 = vpref; r2 = sr[buf][x + 2];
            vpref = vnext;
        } else {
            l2 = 0.f; m2 = 0.f; r2 = 0.f;
        }
        float s = l0 * w00 + m0 * w01 + r0 * w02
                + l1 * w10 + m1 * w11 + r1 * w12
                + l2 * w20 + m2 * w21 + r2 * w22;
        op[(y << 7) + x] = __float2half_rn(s);
        ssq += s * s;
        l0 = l1; m0 = m1; r0 = r1;
        l1 = l2; m1 = m2; r1 = r2;
    }

    if (ch < 2 * DIM) {
        red[x] = ssq; __syncthreads();
        for (int s = 64; s > 0; s >>= 1) {
            if (x < s) red[x] += red[x + s];
            __syncthreads();
        }
        if (x == 0) g_invnorm[b * 2 * DIM + ch] = 1.f / fmaxf(sqrtf(red[0]), EPS);
    }
}

// ---------------- attention logits via mma.sync (fp16, cp.async staged) -------
__global__ __launch_bounds__(96)
void attn_s(const __half* __restrict__ t)
{
    int bh = blockIdx.y;
    int b = bh >> 3, head = bh & 7;
    int nb = blockIdx.x * (HW / NCHUNKS);   // 1024
    const __half* qp = t + ((((long)b * C3) + head * CH) << 14);
    const __half* kp = t + ((((long)b * C3) + DIM + head * CH) << 14);

    __shared__ __align__(16) char smem[2 * 96 * 128];
    uint32_t sb = smem_u32(smem);
    int tid = threadIdx.x, w = tid >> 5, lane = tid & 31;

    float acc[6][4];
#pragma unroll
    for (int i = 0; i < 6; i++)
#pragma unroll
        for (int j = 0; j < 4; j++) acc[i][j] = 0.f;

#define AS_LOAD(kc) do { \
        int _off = nb + (kc) * 64; \
        uint32_t _sb = sb + ((kc) & 1) * 12288; \
        _Pragma("unroll") \
        for (int _i = 0; _i < 8; _i++) { \
            int _g = _i * 96 + tid; \
            int _row = _g >> 3, _c = _g & 7; \
            const __half* _src = (_row < 48) \
                ? qp + (((long)_row) << 14) + _off + _c * 8 \
                : kp + (((long)(_row - 48)) << 14) + _off + _c * 8; \
            cpasync16(_sb + swz128(_row, _c), _src); \
        } \
        CP_COMMIT(); \
    } while (0)

    AS_LOAD(0);
    for (int kc = 0; kc < 16; kc++) {
        if (kc < 15) { AS_LOAD(kc + 1); CP_WAIT1(); }
        else         { CP_WAIT0(); }
        __syncthreads();

        uint32_t st = sb + (kc & 1) * 12288;
#pragma unroll
        for (int ks = 0; ks < 4; ks++) {
            int ar = w * 16 + (lane & 7) + ((lane >> 3) & 1) * 8;
            int ac = ks * 2 + ((lane >> 4) & 1);
            uint32_t ah[4];
            ldsm4(ah, st + swz128(ar, ac));

            uint32_t bhf[6][2];
            int br = (lane & 7) + ((lane >> 4) & 1) * 8;
            int bc = ks * 2 + ((lane >> 3) & 1);
#pragma unroll
            for (int p = 0; p < 3; p++) {
                uint32_t r[4];
                ldsm4(r, st + swz128(48 + p * 16 + br, bc));
                bhf[p * 2][0] = r[0]; bhf[p * 2][1] = r[1];
                bhf[p * 2 + 1][0] = r[2]; bhf[p * 2 + 1][1] = r[3];
            }
#pragma unroll
            for (int nt = 0; nt < 6; nt++)
                mma_f16(acc[nt], ah, bhf[nt]);
        }
        __syncthreads();
    }
#undef AS_LOAD

    float* Sp = g_Spart + ((long)blockIdx.x * 32 + bh) * (CH * CH);
    int c0 = w * 16 + (lane >> 2);
#pragma unroll
    for (int nt = 0; nt < 6; nt++) {
        int d = nt * 8 + (lane & 3) * 2;
        *(float2*)&Sp[c0 * CH + d] = make_float2(acc[nt][0], acc[nt][1]);
        *(float2*)&Sp[(c0 + 8) * CH + d] = make_float2(acc[nt][2], acc[nt][3]);
    }
}

// ---------------- finalize: reduce partials, scale, clamp, softmax ----------------
__global__ __launch_bounds__(64)
void softmax_kernel(const float* __restrict__ temp)
{
    int blk = blockIdx.x;
    int bh = blk / CH, c = blk % CH;
    int b = bh >> 3, head = bh & 7;
    int d = threadIdx.x;
    __shared__ float sm[64];

    float myv = 0.f, val = -1e30f;
    if (d < CH) {
        float raw = 0.f;
#pragma unroll
        for (int ch = 0; ch < NCHUNKS; ch++)
            raw += g_Spart[((long)ch * 32 + bh) * (CH * CH) + c * CH + d];
        float invq = g_invnorm[b * 2 * DIM + head * CH + c];
        float invk = g_invnorm[b * 2 * DIM + DIM + head * CH + d];
        myv = raw * invq * invk * temp[head];
        myv = fminf(fmaxf(myv, -CLAMPV), CLAMPV);
        val = myv;
    }
    sm[d] = val; __syncthreads();
    for (int s = 32; s > 0; s >>= 1) { if (d < s) sm[d] = fmaxf(sm[d], sm[d + s]); __syncthreads(); }
    float m = sm[0]; __syncthreads();
    float e = (d < CH) ? expf(myv - m) : 0.f;
    sm[d] = e; __syncthreads();
    for (int s = 32; s > 0; s >>= 1) { if (d < s) sm[d] += sm[d + s]; __syncthreads(); }
    if (d < CH) g_S[(long)bh * (CH * CH) + c * CH + d] = e / sm[0];
}

// ---------------- launch ----------------
extern "C" void kernel_launch(void* const* d_in, const int* in_sizes, int n_in,
                              void* d_out, int out_size)
{
    const float* x     = (const float*)d_in[0];
    const float* qkvw  = (const float*)d_in[1];
    const float* dww   = (const float*)d_in[2];
    const float* projw = (const float*)d_in[3];
    const float* temp  = (const float*)d_in[4];
    const float* uq    = (const float*)d_in[5];
    const float* ud    = (const float*)d_in[6];
    const float* up    = (const float*)d_in[7];
    float* out = (float*)d_out;

    __half *t0h, *t1h, *x16, *wqh, *wp2;
    cudaGetSymbolAddress((void**)&t0h, g_t0h);
    cudaGetSymbolAddress((void**)&t1h, g_t1h);
    cudaGetSymbolAddress((void**)&x16, g_x16);
    cudaGetSymbolAddress((void**)&wqh, g_wqh);
    cudaGetSymbolAddress((void**)&wp2, g_wp2);

    cudaFuncSetAttribute(bgemmT, cudaFuncAttributeMaxDynamicSharedMemorySize, BG_SMEM);

    // GEMM inputs first, sigma pipeline after
    conv_w<<<(C3 * DIM + 255) / 256, 256>>>(qkvw, wqh);
    convert_x<<<((long)BATCH * DIM * HW / 4 + 255) / 256, 256>>>(x, x16);

    sigma_v<<<dim3(3, 8), 256>>>(qkvw, dww, projw, uq, ud, up);
    sigma_wv<<<dim3(3, 18), 256>>>(qkvw, dww, projw);
    scale_kernel<<<1, 32>>>();

    // qkv 1x1 conv: t0h[b][1152][hw] = wqh @ x16  (B natural layout)
    bgemmT<<<dim3(C3 / 128, HW / 256, BATCH), 256, BG_SMEM>>>(
        wqh, 0L, x16, (long)DIM * HW, nullptr, t0h, (long)C3 * HW, 0);

    // 3x3 depthwise conv (fp16 I/O) with fused q/k L2 norms
    dwconv<<<dim3(C3, BATCH), 128>>>(t0h, dww, t1h);

    // attention logits + softmax
    attn_s<<<dim3(NCHUNKS, BATCH * HEADS), 96>>>(t1h);
    softmax_kernel<<<BATCH * HEADS * CH, 64>>>(temp);

    // W' = wp @ blockdiag(S)  (folds attn@v into proj)
    wprime<<<dim3(HEADS, BATCH), 256>>>(projw, wp2);

    // out = W' @ v, fp32 out with combined sigma scale (v = t1h section, natural layout)
    bgemmT<<<dim3(DIM / 128, HW / 256, BATCH), 256, BG_SMEM>>>(
        wp2, (long)DIM * DIM, t1h + ((long)2 * DIM << 14), (long)C3 * HW,
        out, nullptr, (long)DIM * HW, 1);
}

// round 14
// speedup vs baseline: 5.2533x; 1.1133x over previous
#include <cuda_runtime.h>
#include <cuda_fp16.h>
#include <math.h>
#include <stdint.h>

#define BATCH 4
#define DIM 384
#define HEADS 8
#define CH 48            // DIM/HEADS
#define HW 16384         // 128*128
#define C3 1152          // 3*DIM
#define EPS 1e-12f
#define CLAMPV 50.0f
#define NCHUNKS 16
#define GK 384           // GEMM K (always DIM)

// ---------------- device scratch ----------------
__device__ __half g_t0h[(size_t)BATCH * C3 * HW];   // qkv GEMM output fp16
__device__ __half g_t1h[(size_t)BATCH * C3 * HW];   // depthwise output fp16
__device__ float g_sigma[4];
__device__ float g_invnorm[BATCH * 2 * DIM];
__device__ float g_Spart[NCHUNKS * BATCH * HEADS * CH * CH];
__device__ float g_S[BATCH * HEADS * CH * CH];
// sigma pipeline scratch
__device__ float g_vpart[3][8][DIM];
__device__ float g_wvpart[3][36];
__device__ float g_vssq[3];
// fp16 operands
__device__ __half g_x16[(size_t)BATCH * DIM * HW];  // x converted, natural [b][c][hw]
__device__ __half g_wqh[C3 * DIM];                  // qkv weights fp16 [m][k]
__device__ __half g_wp2[(size_t)BATCH * DIM * DIM]; // W' = wp @ blockdiag(S), per batch

// ---------------- warp-mma helpers ----------------
__device__ __forceinline__ uint32_t smem_u32(const void* p) {
    uint32_t a;
    asm("{ .reg .u64 t; cvta.to.shared.u64 t, %1; cvt.u32.u64 %0, t; }" : "=r"(a) : "l"(p));
    return a;
}
__device__ __forceinline__ void cpasync16(uint32_t s, const void* g) {
    asm volatile("cp.async.cg.shared.global [%0], [%1], 16;" :: "r"(s), "l"(g));
}
#define CP_COMMIT() asm volatile("cp.async.commit_group;" ::: "memory")
#define CP_WAIT2()  asm volatile("cp.async.wait_group 2;" ::: "memory")
#define CP_WAIT1()  asm volatile("cp.async.wait_group 1;" ::: "memory")
#define CP_WAIT0()  asm volatile("cp.async.wait_group 0;" ::: "memory")

__device__ __forceinline__ void ldsm4(uint32_t* r, uint32_t addr) {
    asm volatile("ldmatrix.sync.aligned.m8n8.x4.shared.b16 {%0,%1,%2,%3}, [%4];"
        : "=r"(r[0]), "=r"(r[1]), "=r"(r[2]), "=r"(r[3]) : "r"(addr));
}
__device__ __forceinline__ void ldsm4t(uint32_t* r, uint32_t addr) {
    asm volatile("ldmatrix.sync.aligned.m8n8.x4.trans.shared.b16 {%0,%1,%2,%3}, [%4];"
        : "=r"(r[0]), "=r"(r[1]), "=r"(r[2]), "=r"(r[3]) : "r"(addr));
}
__device__ __forceinline__ void mma_f16(float* c, const uint32_t* a, const uint32_t* b) {
    asm volatile(
        "mma.sync.aligned.m16n8k16.row.col.f32.f16.f16.f32 "
        "{%0,%1,%2,%3}, {%4,%5,%6,%7}, {%8,%9}, {%0,%1,%2,%3};"
        : "+f"(c[0]), "+f"(c[1]), "+f"(c[2]), "+f"(c[3])
        : "r"(a[0]), "r"(a[1]), "r"(a[2]), "r"(a[3]), "r"(b[0]), "r"(b[1]));
}

// A-tile swizzle: R rows x 32 f16 (64B) packed 2 rows per 128B line.
__device__ __forceinline__ uint32_t swz(uint32_t row, uint32_t c) {
    return (row >> 1) * 128 + ((((row & 1) * 4 + c) ^ ((row >> 1) & 7)) * 16);
}
// natural 128B rows (64 f16 per row), chunk c in 16B units
__device__ __forceinline__ uint32_t swz128(uint32_t row, uint32_t c) {
    return row * 128 + ((c ^ (row & 7)) * 16);
}
// B-tile (k-rows of 256 f16 = 512B): XOR 16B-chunk within each 128B window by row&7
__device__ __forceinline__ uint32_t bswz(uint32_t row, uint32_t chunk) {
    return row * 512 + (((chunk) & 24u) | (((chunk) & 7u) ^ ((row) & 7u))) * 16;
}

// ---------------- sigma pipeline ----------------
__global__ __launch_bounds__(256)
void sigma_v(const float* __restrict__ qkvw, const float* __restrict__ dww,
             const float* __restrict__ projw, const float* __restrict__ uq,
             const float* __restrict__ ud, const float* __restrict__ up)
{
    int which = blockIdx.x, ic = blockIdx.y;
    const float* wm; const float* u; int h, w;
    if (which == 0)      { wm = qkvw;  u = uq; h = C3;  w = DIM; }
    else if (which == 1) { wm = dww;   u = ud; h = C3;  w = 9;   }
    else                 { wm = projw; u = up; h = DIM; w = DIM; }
    int chunk = h >> 3;
    int i0 = ic * chunk, i1 = i0 + chunk;
    for (int j = threadIdx.x; j < w; j += 256) {
        float s = 0.f;
        for (int i = i0; i < i1; i++) s += wm[i * w + j] * u[i];
        g_vpart[which][ic][j] = s;
    }
}

// partials of ||wm v||^2 with UNNORMALIZED v. 32 rows/block, 8-way j-split.
// grid (3, 36), block 256.
__global__ __launch_bounds__(256)
void sigma_wv(const float* __restrict__ qkvw, const float* __restrict__ dww,
              const float* __restrict__ projw)
{
    int which = blockIdx.x;
    const float* wm; int h, w;
    if (which == 0)      { wm = qkvw;  h = C3;  w = DIM; }
    else if (which == 1) { wm = dww;   h = C3;  w = 9;   }
    else                 { wm = projw; h = DIM; w = DIM; }
    if (blockIdx.y * 32 >= h) return;

    __shared__ float v[DIM];
    __shared__ float red[256];
    int tid = threadIdx.x;

    for (int j = tid; j < w; j += 256) {
        float s = 0.f;
#pragma unroll
        for (int ic = 0; ic < 8; ic++) s += g_vpart[which][ic][j];
        v[j] = s;
    }
    __syncthreads();

    if (blockIdx.y == 0 && tid < 32) {
        float ss = 0.f;
        for (int j = tid; j < w; j += 32) ss += v[j] * v[j];
#pragma unroll
        for (int o = 16; o > 0; o >>= 1) ss += __shfl_xor_sync(0xffffffff, ss, o);
        if (tid == 0) g_vssq[which] = ss;
    }

    int r = tid >> 3, seg = tid & 7;
    int i = blockIdx.y * 32 + r;
    float s = 0.f;
    if (i < h) {
        int j0 = seg * (w / 8), j1 = (seg + 1) * (w / 8);
        if (w == 9) { j0 = (seg == 0) ? 0 : 9; j1 = 9; }
        for (int j = j0; j < j1; j++) s += wm[i * w + j] * v[j];
    }
    s += __shfl_xor_sync(0xffffffff, s, 1);
    s += __shfl_xor_sync(0xffffffff, s, 2);
    s += __shfl_xor_sync(0xffffffff, s, 4);
    float ssq = (seg == 0 && i < h) ? s * s : 0.f;

    red[tid] = ssq; __syncthreads();
    for (int st = 128; st > 0; st >>= 1) {
        if (tid < st) red[tid] += red[tid + st];
        __syncthreads();
    }
    if (tid == 0) g_wvpart[which][blockIdx.y] = red[0];
}

__global__ void scale_kernel()
{
    if (threadIdx.x == 0) {
        float comb = 1.f;
        int np[3] = {36, 36, 12};
        for (int which = 0; which < 3; which++) {
            float wv = 0.f;
            for (int j = 0; j < np[which]; j++) wv += g_wvpart[which][j];
            float mv = fmaxf(sqrtf(g_vssq[which]), EPS);
            float s2 = wv / (mv * mv);
            float sig = s2 / fmaxf(sqrtf(s2), EPS);
            comb /= (sig + EPS);
        }
        g_sigma[3] = comb;
    }
}

// ---------------- qkv weights fp32->fp16 ----------------
__global__ __launch_bounds__(256)
void conv_w(const float* __restrict__ qkvw, __half* __restrict__ qh)
{
    int i = blockIdx.x * 256 + threadIdx.x;
    if (i < C3 * DIM) qh[i] = __float2half_rn(qkvw[i]);
}

// ---------------- x fp32 -> fp16, same layout ----------------
__global__ __launch_bounds__(256)
void convert_x(const float* __restrict__ x, __half* __restrict__ x16)
{
    long i = ((long)blockIdx.x * 256 + threadIdx.x) * 4;
    if (i < (long)BATCH * DIM * HW) {
        float4 v = *(const float4*)&x[i];
        __half2 h[2];
        h[0] = __halves2half2(__float2half_rn(v.x), __float2half_rn(v.y));
        h[1] = __halves2half2(__float2half_rn(v.z), __float2half_rn(v.w));
        *(uint2*)&x16[i] = *(const uint2*)h;
    }
}

// ---------------- W' = wp @ blockdiag(S): grid (HEADS, BATCH), block 256 ----------------
__global__ __launch_bounds__(256)
void wprime(const float* __restrict__ projw, __half* __restrict__ wp2)
{
    int head = blockIdx.x, b = blockIdx.y;
    int bh = b * HEADS + head;
    __shared__ float S[CH][CH];
    for (int i = threadIdx.x; i < CH * CH; i += 256)
        S[i / CH][i % CH] = g_S[(long)bh * CH * CH + i];
    __syncthreads();

    int h0 = head * CH;
    for (int idx = threadIdx.x; idx < DIM * CH; idx += 256) {
        int o = idx / CH, d = idx % CH;
        const float* wr = projw + (long)o * DIM + h0;
        float s = 0.f;
#pragma unroll 8
        for (int c = 0; c < CH; c++) s += wr[c] * S[c][d];
        wp2[((long)b * DIM + o) * DIM + h0 + d] = __float2half_rn(s);
    }
}

// ---------------- fp16 GEMM, B natural [K][N] layout, 4-stage single-sync pipeline ------
// C[m][n] = sum_k A[m][k] * B[k][n].  mode 0: fp16 out. mode 1: fp32 out * sigma.
// Block 128x256x32, 8 warps (2Mx4N), warp tile 64x64.
// Stage: A (8KB) + B (16KB) = 24KB; 4 stages = 96KB.
#define BG_STAGE 24576
#define BG_SMEM (4 * BG_STAGE)
#define KTILES (GK / 32)

__global__ void __launch_bounds__(256)
bgemmT(const __half* __restrict__ A, long strideA,
       const __half* __restrict__ B, long strideB,
       float* __restrict__ C, __half* __restrict__ Ch, long strideC, int mode)
{
    extern __shared__ char smem[];
    uint32_t sb = smem_u32(smem);
    int tid = threadIdx.x, wid = tid >> 5, lane = tid & 31;
    int m0 = blockIdx.x << 7, n0 = blockIdx.y << 8, bz = blockIdx.z;
    int wm = (wid >> 2) * 64;
    int wn = (wid & 3) * 64;

    const __half* ap = A + (long)bz * strideA + (long)m0 * GK;
    const __half* bp = B + (long)bz * strideB + n0;

    float acc[4][8][4];
#pragma unroll
    for (int i = 0; i < 4; i++)
#pragma unroll
        for (int j = 0; j < 8; j++)
#pragma unroll
            for (int k = 0; k < 4; k++) acc[i][j][k] = 0.f;

    int arow_l = tid >> 2, ac_l = tid & 3;       // A loader
    int brow_l = tid >> 3, bc_l = tid & 7;       // B loader

#define LOAD_STAGE(kc) do { \
        int _k0 = (kc) << 5; \
        uint32_t _sb = sb + ((kc) & 3) * BG_STAGE; \
        _Pragma("unroll") \
        for (int _i = 0; _i < 2; _i++) { \
            int _row = (_i << 6) + arow_l; \
            cpasync16(_sb + swz(_row, ac_l), ap + (long)_row * GK + _k0 + ac_l * 8); \
        } \
        _Pragma("unroll") \
        for (int _i = 0; _i < 4; _i++) { \
            int _ch = bc_l + _i * 8; \
            cpasync16(_sb + 8192 + bswz(brow_l, _ch), \
                      bp + (long)(_k0 + brow_l) * HW + _ch * 8); \
        } \
        CP_COMMIT(); \
    } while (0)

    LOAD_STAGE(0);
    LOAD_STAGE(1);
    LOAD_STAGE(2);

    for (int kc = 0; kc < KTILES; kc++) {
        // stage kc ready when pending groups <= (groups issued after kc)
        if (kc < KTILES - 2)       CP_WAIT2();
        else if (kc == KTILES - 2) CP_WAIT1();
        else                       CP_WAIT0();
        __syncthreads();

        uint32_t st = sb + (kc & 3) * BG_STAGE;
#pragma unroll
        for (int ks = 0; ks < 2; ks++) {
            uint32_t bh[8][2];
#pragma unroll
            for (int p = 0; p < 4; p++) {
                int row = ks * 16 + (lane & 7) + ((lane >> 3) & 1) * 8;
                int nh = wn + p * 16 + ((lane >> 4) & 1) * 8;
                uint32_t r[4];
                ldsm4t(r, st + 8192 + bswz(row, nh >> 3));
                bh[p * 2][0] = r[0]; bh[p * 2][1] = r[1];
                bh[p * 2 + 1][0] = r[2]; bh[p * 2 + 1][1] = r[3];
            }
#pragma unroll
            for (int mt = 0; mt < 4; mt++) {
                int ar = wm + mt * 16 + (lane & 7) + ((lane >> 3) & 1) * 8;
                int ac = ks * 2 + ((lane >> 4) & 1);
                uint32_t ah[4];
                ldsm4(ah, st + swz(ar, ac));
#pragma unroll
                for (int nt = 0; nt < 8; nt++)
                    mma_f16(acc[mt][nt], ah, bh[nt]);
            }
        }
        // buffer (kc+3)&3 was last read at iteration kc-1; all warps passed this
        // iteration's barrier after those reads, so no trailing barrier is needed.
        if (kc + 3 < KTILES) LOAD_STAGE(kc + 3);
    }

    if (mode == 0) {
        __half* Cb = Ch + (long)bz * strideC;
#pragma unroll
        for (int mt = 0; mt < 4; mt++) {
            int m = m0 + wm + mt * 16 + (lane >> 2);
#pragma unroll
            for (int nt = 0; nt < 8; nt++) {
                int n = n0 + wn + nt * 8 + (lane & 3) * 2;
                *(__half2*)&Cb[(long)m * HW + n] = __halves2half2(
                    __float2half_rn(acc[mt][nt][0]), __float2half_rn(acc[mt][nt][1]));
                *(__half2*)&Cb[(long)(m + 8) * HW + n] = __halves2half2(
                    __float2half_rn(acc[mt][nt][2]), __float2half_rn(acc[mt][nt][3]));
            }
        }
    } else {
        float sc = g_sigma[3];
        float* Cb = C + (long)bz * strideC;
#pragma unroll
        for (int mt = 0; mt < 4; mt++) {
            int m = m0 + wm + mt * 16 + (lane >> 2);
#pragma unroll
            for (int nt = 0; nt < 8; nt++) {
                int n = n0 + wn + nt * 8 + (lane & 3) * 2;
                float2 v0 = make_float2(acc[mt][nt][0] * sc, acc[mt][nt][1] * sc);
                float2 v1 = make_float2(acc[mt][nt][2] * sc, acc[mt][nt][3] * sc);
                *(float2*)&Cb[(long)m * HW + n] = v0;
                *(float2*)&Cb[(long)(m + 8) * HW + n] = v1;
            }
        }
    }
#undef LOAD_STAGE
}

// ---------------- 3x3 depthwise conv (fp16 I/O, fp32 math), 2 rows/iter, fused norm -----
__global__ __launch_bounds__(128)
void dwconv(const __half* __restrict__ in, const float* __restrict__ w,
            __half* __restrict__ out)
{
    int ch = blockIdx.x, b = blockIdx.y;
    const __half* ip = in + (((long)b * C3 + ch) << 14);
    __half* op = out + (((long)b * C3 + ch) << 14);
    int x = threadIdx.x;

    __shared__ float sr[4][130];
    __shared__ float red[128];

    float w00 = w[ch * 9 + 0], w01 = w[ch * 9 + 1], w02 = w[ch * 9 + 2];
    float w10 = w[ch * 9 + 3], w11 = w[ch * 9 + 4], w12 = w[ch * 9 + 5];
    float w20 = w[ch * 9 + 6], w21 = w[ch * 9 + 7], w22 = w[ch * 9 + 8];

    // triples (l,m,r) for rows y-1 (A), y (B), y+1 (C)
    float Al = 0.f, Am = 0.f, Ar = 0.f;
    float Bl, Bm, Br, Cl, Cm, Cr;

    float v0 = __half2float(ip[x]);
    float v1 = __half2float(ip[128 + x]);
    sr[0][x + 1] = v0;
    sr[1][x + 1] = v1;
    if (x == 0) {
        sr[0][0] = 0.f; sr[0][129] = 0.f;
        sr[1][0] = 0.f; sr[1][129] = 0.f;
    }
    __syncthreads();
    Bl = sr[0][x]; Bm = v0; Br = sr[0][x + 2];
    Cl = sr[1][x]; Cm = v1; Cr = sr[1][x + 2];

    float pre2 = __half2float(ip[256 + x]);   // row 2
    float pre3 = __half2float(ip[384 + x]);   // row 3

    float ssq = 0.f;
    for (int y = 0; y < 128; y += 2) {
        float m2 = pre2, m3 = pre3;
        int b2 = (y + 2) & 3, b3 = (y + 3) & 3;
        if (y + 2 < 128) {
            sr[b2][x + 1] = m2;
            if (x == 0) { sr[b2][0] = 0.f; sr[b2][129] = 0.f; }
        }
        if (y + 3 < 128) {
            sr[b3][x + 1] = m3;
            if (x == 0) { sr[b3][0] = 0.f; sr[b3][129] = 0.f; }
        }
        pre2 = (y + 4 < 128) ? __half2float(ip[((y + 4) << 7) + x]) : 0.f;
        pre3 = (y + 5 < 128) ? __half2float(ip[((y + 5) << 7) + x]) : 0.f;
        __syncthreads();

        float Dl = 0.f, Dm = 0.f, Dr = 0.f, El = 0.f, Em = 0.f, Er = 0.f;
        if (y + 2 < 128) { Dl = sr[b2][x]; Dm = m2; Dr = sr[b2][x + 2]; }
        if (y + 3 < 128) { El = sr[b3][x]; Em = m3; Er = sr[b3][x + 2]; }

        float s0 = Al * w00 + Am * w01 + Ar * w02
                 + Bl * w10 + Bm * w11 + Br * w12
                 + Cl * w20 + Cm * w21 + Cr * w22;
        float s1 = Bl * w00 + Bm * w01 + Br * w02
                 + Cl * w10 + Cm * w11 + Cr * w12
                 + Dl * w20 + Dm * w21 + Dr * w22;
        op[(y << 7) + x] = __float2half_rn(s0);
        op[((y + 1) << 7) + x] = __float2half_rn(s1);
        ssq += s0 * s0 + s1 * s1;

        Al = Cl; Am = Cm; Ar = Cr;
        Bl = Dl; Bm = Dm; Br = Dr;
        Cl = El; Cm = Em; Cr = Er;
    }

    if (ch < 2 * DIM) {
        red[x] = ssq; __syncthreads();
        for (int s = 64; s > 0; s >>= 1) {
            if (x < s) red[x] += red[x + s];
            __syncthreads();
        }
        if (x == 0) g_invnorm[b * 2 * DIM + ch] = 1.f / fmaxf(sqrtf(red[0]), EPS);
    }
}

// ---------------- attention logits via mma.sync (fp16, cp.async staged) -------
__global__ __launch_bounds__(96)
void attn_s(const __half* __restrict__ t)
{
    int bh = blockIdx.y;
    int b = bh >> 3, head = bh & 7;
    int nb = blockIdx.x * (HW / NCHUNKS);   // 1024
    const __half* qp = t + ((((long)b * C3) + head * CH) << 14);
    const __half* kp = t + ((((long)b * C3) + DIM + head * CH) << 14);

    __shared__ __align__(16) char smem[2 * 96 * 128];
    uint32_t sb = smem_u32(smem);
    int tid = threadIdx.x, w = tid >> 5, lane = tid & 31;

    float acc[6][4];
#pragma unroll
    for (int i = 0; i < 6; i++)
#pragma unroll
        for (int j = 0; j < 4; j++) acc[i][j] = 0.f;

#define AS_LOAD(kc) do { \
        int _off = nb + (kc) * 64; \
        uint32_t _sb = sb + ((kc) & 1) * 12288; \
        _Pragma("unroll") \
        for (int _i = 0; _i < 8; _i++) { \
            int _g = _i * 96 + tid; \
            int _row = _g >> 3, _c = _g & 7; \
            const __half* _src = (_row < 48) \
                ? qp + (((long)_row) << 14) + _off + _c * 8 \
                : kp + (((long)(_row - 48)) << 14) + _off + _c * 8; \
            cpasync16(_sb + swz128(_row, _c), _src); \
        } \
        CP_COMMIT(); \
    } while (0)

    AS_LOAD(0);
    for (int kc = 0; kc < 16; kc++) {
        if (kc < 15) { AS_LOAD(kc + 1); CP_WAIT1(); }
        else         { CP_WAIT0(); }
        __syncthreads();

        uint32_t st = sb + (kc & 1) * 12288;
#pragma unroll
        for (int ks = 0; ks < 4; ks++) {
            int ar = w * 16 + (lane & 7) + ((lane >> 3) & 1) * 8;
            int ac = ks * 2 + ((lane >> 4) & 1);
            uint32_t ah[4];
            ldsm4(ah, st + swz128(ar, ac));

            uint32_t bhf[6][2];
            int br = (lane & 7) + ((lane >> 4) & 1) * 8;
            int bc = ks * 2 + ((lane >> 3) & 1);
#pragma unroll
            for (int p = 0; p < 3; p++) {
                uint32_t r[4];
                ldsm4(r, st + swz128(48 + p * 16 + br, bc));
                bhf[p * 2][0] = r[0]; bhf[p * 2][1] = r[1];
                bhf[p * 2 + 1][0] = r[2]; bhf[p * 2 + 1][1] = r[3];
            }
#pragma unroll
            for (int nt = 0; nt < 6; nt++)
                mma_f16(acc[nt], ah, bhf[nt]);
        }
        __syncthreads();
    }
#undef AS_LOAD

    float* Sp = g_Spart + ((long)blockIdx.x * 32 + bh) * (CH * CH);
    int c0 = w * 16 + (lane >> 2);
#pragma unroll
    for (int nt = 0; nt < 6; nt++) {
        int d = nt * 8 + (lane & 3) * 2;
        *(float2*)&Sp[c0 * CH + d] = make_float2(acc[nt][0], acc[nt][1]);
        *(float2*)&Sp[(c0 + 8) * CH + d] = make_float2(acc[nt][2], acc[nt][3]);
    }
}

// ---------------- finalize: reduce partials, scale, clamp, softmax ----------------
__global__ __launch_bounds__(64)
void softmax_kernel(const float* __restrict__ temp)
{
    int blk = blockIdx.x;
    int bh = blk / CH, c = blk % CH;
    int b = bh >> 3, head = bh & 7;
    int d = threadIdx.x;
    __shared__ float sm[64];

    float myv = 0.f, val = -1e30f;
    if (d < CH) {
        float raw = 0.f;
#pragma unroll
        for (int ch = 0; ch < NCHUNKS; ch++)
            raw += g_Spart[((long)ch * 32 + bh) * (CH * CH) + c * CH + d];
        float invq = g_invnorm[b * 2 * DIM + head * CH + c];
        float invk = g_invnorm[b * 2 * DIM + DIM + head * CH + d];
        myv = raw * invq * invk * temp[head];
        myv = fminf(fmaxf(myv, -CLAMPV), CLAMPV);
        val = myv;
    }
    sm[d] = val; __syncthreads();
    for (int s = 32; s > 0; s >>= 1) { if (d < s) sm[d] = fmaxf(sm[d], sm[d + s]); __syncthreads(); }
    float m = sm[0]; __syncthreads();
    float e = (d < CH) ? expf(myv - m) : 0.f;
    sm[d] = e; __syncthreads();
    for (int s = 32; s > 0; s >>= 1) { if (d < s) sm[d] += sm[d + s]; __syncthreads(); }
    if (d < CH) g_S[(long)bh * (CH * CH) + c * CH + d] = e / sm[0];
}

// ---------------- launch ----------------
extern "C" void kernel_launch(void* const* d_in, const int* in_sizes, int n_in,
                              void* d_out, int out_size)
{
    const float* x     = (const float*)d_in[0];
    const float* qkvw  = (const float*)d_in[1];
    const float* dww   = (const float*)d_in[2];
    const float* projw = (const float*)d_in[3];
    const float* temp  = (const float*)d_in[4];
    const float* uq    = (const float*)d_in[5];
    const float* ud    = (const float*)d_in[6];
    const float* up    = (const float*)d_in[7];
    float* out = (float*)d_out;

    __half *t0h, *t1h, *x16, *wqh, *wp2;
    cudaGetSymbolAddress((void**)&t0h, g_t0h);
    cudaGetSymbolAddress((void**)&t1h, g_t1h);
    cudaGetSymbolAddress((void**)&x16, g_x16);
    cudaGetSymbolAddress((void**)&wqh, g_wqh);
    cudaGetSymbolAddress((void**)&wp2, g_wp2);

    cudaFuncSetAttribute(bgemmT, cudaFuncAttributeMaxDynamicSharedMemorySize, BG_SMEM);

    // GEMM inputs first, sigma pipeline after
    conv_w<<<(C3 * DIM + 255) / 256, 256>>>(qkvw, wqh);
    convert_x<<<((long)BATCH * DIM * HW / 4 + 255) / 256, 256>>>(x, x16);

    sigma_v<<<dim3(3, 8), 256>>>(qkvw, dww, projw, uq, ud, up);
    sigma_wv<<<dim3(3, 36), 256>>>(qkvw, dww, projw);
    scale_kernel<<<1, 32>>>();

    // qkv 1x1 conv: t0h[b][1152][hw] = wqh @ x16  (B natural layout)
    bgemmT<<<dim3(C3 / 128, HW / 256, BATCH), 256, BG_SMEM>>>(
        wqh, 0L, x16, (long)DIM * HW, nullptr, t0h, (long)C3 * HW, 0);

    // 3x3 depthwise conv (fp16 I/O) with fused q/k L2 norms
    dwconv<<<dim3(C3, BATCH), 128>>>(t0h, dww, t1h);

    // attention logits + softmax
    attn_s<<<dim3(NCHUNKS, BATCH * HEADS), 96>>>(t1h);
    softmax_kernel<<<BATCH * HEADS * CH, 64>>>(temp);

    // W' = wp @ blockdiag(S)  (folds attn@v into proj)
    wprime<<<dim3(HEADS, BATCH), 256>>>(projw, wp2);

    // out = W' @ v, fp32 out with combined sigma scale (v = t1h section, natural layout)
    bgemmT<<<dim3(DIM / 128, HW / 256, BATCH), 256, BG_SMEM>>>(
        wp2, (long)DIM * DIM, t1h + ((long)2 * DIM << 14), (long)C3 * HW,
        out, nullptr, (long)DIM * HW, 1);
}

// round 16
// speedup vs baseline: 5.3135x; 1.0115x over previous
#include <cuda_runtime.h>
#include <cuda_fp16.h>
#include <math.h>
#include <stdint.h>

#define BATCH 4
#define DIM 384
#define HEADS 8
#define CH 48            // DIM/HEADS
#define HW 16384         // 128*128
#define C3 1152          // 3*DIM
#define EPS 1e-12f
#define CLAMPV 50.0f
#define NCHUNKS 16
#define GK 384           // GEMM K (always DIM)

// ---------------- device scratch ----------------
__device__ __half g_t0h[(size_t)BATCH * C3 * HW];   // qkv GEMM output fp16
__device__ __half g_t1h[(size_t)BATCH * C3 * HW];   // depthwise output fp16
__device__ float g_sigma[4];
__device__ float g_invnorm[BATCH * 2 * DIM];
__device__ float g_Spart[NCHUNKS * BATCH * HEADS * CH * CH];
__device__ float g_S[BATCH * HEADS * CH * CH];
// sigma pipeline scratch
__device__ float g_vpart[3][8][DIM];
__device__ float g_wvpart[3][36];
__device__ float g_vssq[3];
// fp16 operands
__device__ __half g_x16[(size_t)BATCH * DIM * HW];  // x converted, natural [b][c][hw]
__device__ __half g_wqh[C3 * DIM];                  // qkv weights fp16 [m][k]
__device__ __half g_wp2[(size_t)BATCH * DIM * DIM]; // W' = wp @ blockdiag(S), per batch

// ---------------- warp-mma helpers ----------------
__device__ __forceinline__ uint32_t smem_u32(const void* p) {
    uint32_t a;
    asm("{ .reg .u64 t; cvta.to.shared.u64 t, %1; cvt.u32.u64 %0, t; }" : "=r"(a) : "l"(p));
    return a;
}
__device__ __forceinline__ void cpasync16(uint32_t s, const void* g) {
    asm volatile("cp.async.cg.shared.global [%0], [%1], 16;" :: "r"(s), "l"(g));
}
#define CP_COMMIT() asm volatile("cp.async.commit_group;" ::: "memory")
#define CP_WAIT1()  asm volatile("cp.async.wait_group 1;" ::: "memory")
#define CP_WAIT0()  asm volatile("cp.async.wait_group 0;" ::: "memory")

__device__ __forceinline__ void ldsm4(uint32_t* r, uint32_t addr) {
    asm volatile("ldmatrix.sync.aligned.m8n8.x4.shared.b16 {%0,%1,%2,%3}, [%4];"
        : "=r"(r[0]), "=r"(r[1]), "=r"(r[2]), "=r"(r[3]) : "r"(addr));
}
__device__ __forceinline__ void ldsm4t(uint32_t* r, uint32_t addr) {
    asm volatile("ldmatrix.sync.aligned.m8n8.x4.trans.shared.b16 {%0,%1,%2,%3}, [%4];"
        : "=r"(r[0]), "=r"(r[1]), "=r"(r[2]), "=r"(r[3]) : "r"(addr));
}
__device__ __forceinline__ void mma_f16(float* c, const uint32_t* a, const uint32_t* b) {
    asm volatile(
        "mma.sync.aligned.m16n8k16.row.col.f32.f16.f16.f32 "
        "{%0,%1,%2,%3}, {%4,%5,%6,%7}, {%8,%9}, {%0,%1,%2,%3};"
        : "+f"(c[0]), "+f"(c[1]), "+f"(c[2]), "+f"(c[3])
        : "r"(a[0]), "r"(a[1]), "r"(a[2]), "r"(a[3]), "r"(b[0]), "r"(b[1]));
}

// natural 128B rows (64 f16 per row), chunk c in 16B units
__device__ __forceinline__ uint32_t swz128(uint32_t row, uint32_t c) {
    return row * 128 + ((c ^ (row & 7)) * 16);
}
// B-tile (k-rows of 256 f16 = 512B): XOR 16B-chunk within each 128B window by row&7
__device__ __forceinline__ uint32_t bswz(uint32_t row, uint32_t chunk) {
    return row * 512 + (((chunk) & 24u) | (((chunk) & 7u) ^ ((row) & 7u))) * 16;
}

// ---------------- sigma pipeline ----------------
__global__ __launch_bounds__(256)
void sigma_v(const float* __restrict__ qkvw, const float* __restrict__ dww,
             const float* __restrict__ projw, const float* __restrict__ uq,
             const float* __restrict__ ud, const float* __restrict__ up)
{
    int which = blockIdx.x, ic = blockIdx.y;
    const float* wm; const float* u; int h, w;
    if (which == 0)      { wm = qkvw;  u = uq; h = C3;  w = DIM; }
    else if (which == 1) { wm = dww;   u = ud; h = C3;  w = 9;   }
    else                 { wm = projw; u = up; h = DIM; w = DIM; }
    int chunk = h >> 3;
    int i0 = ic * chunk, i1 = i0 + chunk;
    for (int j = threadIdx.x; j < w; j += 256) {
        float s = 0.f;
        for (int i = i0; i < i1; i++) s += wm[i * w + j] * u[i];
        g_vpart[which][ic][j] = s;
    }
}

__global__ __launch_bounds__(256)
void sigma_wv(const float* __restrict__ qkvw, const float* __restrict__ dww,
              const float* __restrict__ projw)
{
    int which = blockIdx.x;
    const float* wm; int h, w;
    if (which == 0)      { wm = qkvw;  h = C3;  w = DIM; }
    else if (which == 1) { wm = dww;   h = C3;  w = 9;   }
    else                 { wm = projw; h = DIM; w = DIM; }
    if (blockIdx.y * 32 >= h) return;

    __shared__ float v[DIM];
    __shared__ float red[256];
    int tid = threadIdx.x;

    for (int j = tid; j < w; j += 256) {
        float s = 0.f;
#pragma unroll
        for (int ic = 0; ic < 8; ic++) s += g_vpart[which][ic][j];
        v[j] = s;
    }
    __syncthreads();

    if (blockIdx.y == 0 && tid < 32) {
        float ss = 0.f;
        for (int j = tid; j < w; j += 32) ss += v[j] * v[j];
#pragma unroll
        for (int o = 16; o > 0; o >>= 1) ss += __shfl_xor_sync(0xffffffff, ss, o);
        if (tid == 0) g_vssq[which] = ss;
    }

    int r = tid >> 3, seg = tid & 7;
    int i = blockIdx.y * 32 + r;
    float s = 0.f;
    if (i < h) {
        int j0 = seg * (w / 8), j1 = (seg + 1) * (w / 8);
        if (w == 9) { j0 = (seg == 0) ? 0 : 9; j1 = 9; }
        for (int j = j0; j < j1; j++) s += wm[i * w + j] * v[j];
    }
    s += __shfl_xor_sync(0xffffffff, s, 1);
    s += __shfl_xor_sync(0xffffffff, s, 2);
    s += __shfl_xor_sync(0xffffffff, s, 4);
    float ssq = (seg == 0 && i < h) ? s * s : 0.f;

    red[tid] = ssq; __syncthreads();
    for (int st = 128; st > 0; st >>= 1) {
        if (tid < st) red[tid] += red[tid + st];
        __syncthreads();
    }
    if (tid == 0) g_wvpart[which][blockIdx.y] = red[0];
}

__global__ void scale_kernel()
{
    if (threadIdx.x == 0) {
        float comb = 1.f;
        int np[3] = {36, 36, 12};
        for (int which = 0; which < 3; which++) {
            float wv = 0.f;
            for (int j = 0; j < np[which]; j++) wv += g_wvpart[which][j];
            float mv = fmaxf(sqrtf(g_vssq[which]), EPS);
            float s2 = wv / (mv * mv);
            float sig = s2 / fmaxf(sqrtf(s2), EPS);
            comb /= (sig + EPS);
        }
        g_sigma[3] = comb;
    }
}

// ---------------- fused: qkv weight fp32->fp16 + x fp32->fp16 ----------------
#define WBLK ((C3 * DIM + 255) / 256)
#define XBLK ((int)(((long)BATCH * DIM * HW / 4 + 255) / 256))
__global__ __launch_bounds__(256)
void conv_inputs(const float* __restrict__ qkvw, const float* __restrict__ x,
                 __half* __restrict__ qh, __half* __restrict__ x16)
{
    if (blockIdx.x < WBLK) {
        int i = blockIdx.x * 256 + threadIdx.x;
        if (i < C3 * DIM) qh[i] = __float2half_rn(qkvw[i]);
    } else {
        long i = ((long)(blockIdx.x - WBLK) * 256 + threadIdx.x) * 4;
        if (i < (long)BATCH * DIM * HW) {
            float4 v = *(const float4*)&x[i];
            __half2 h[2];
            h[0] = __halves2half2(__float2half_rn(v.x), __float2half_rn(v.y));
            h[1] = __halves2half2(__float2half_rn(v.z), __float2half_rn(v.w));
            *(uint2*)&x16[i] = *(const uint2*)h;
        }
    }
}

// ---------------- W' = wp @ blockdiag(S): grid (HEADS, BATCH), block 256 ----------------
__global__ __launch_bounds__(256)
void wprime(const float* __restrict__ projw, __half* __restrict__ wp2)
{
    int head = blockIdx.x, b = blockIdx.y;
    int bh = b * HEADS + head;
    __shared__ float S[CH][CH];
    for (int i = threadIdx.x; i < CH * CH; i += 256)
        S[i / CH][i % CH] = g_S[(long)bh * CH * CH + i];
    __syncthreads();

    int h0 = head * CH;
    for (int idx = threadIdx.x; idx < DIM * CH; idx += 256) {
        int o = idx / CH, d = idx % CH;
        const float* wr = projw + (long)o * DIM + h0;
        float s = 0.f;
#pragma unroll 8
        for (int c = 0; c < CH; c++) s += wr[c] * S[c][d];
        wp2[((long)b * DIM + o) * DIM + h0 + d] = __float2half_rn(s);
    }
}

// ---------------- fp16 GEMM, B natural [K][N], K-chunk 64, 3-stage ----------------
// Order per iteration: WAIT(stage kc) -> barrier -> issue LOAD(kc+2) -> compute kc.
// The barrier both publishes stage-kc smem writes from all threads and proves all
// threads finished compute kc-1 (which read buffer (kc+2)%3), so the refill is safe.
// Block 128x256x64, 8 warps (2Mx4N), warp tile 64x64.
// Stage: A (16KB, 128 rows x 128B swz128) + B (32KB, 64 k-rows x 512B bswz) = 48KB; x3.
#define BG_STAGE 49152
#define BG_SMEM (3 * BG_STAGE)
#define KTILES (GK / 64)    // 6

__global__ void __launch_bounds__(256)
bgemmT(const __half* __restrict__ A, long strideA,
       const __half* __restrict__ B, long strideB,
       float* __restrict__ C, __half* __restrict__ Ch, long strideC, int mode)
{
    extern __shared__ char smem[];
    uint32_t sb = smem_u32(smem);
    int tid = threadIdx.x, wid = tid >> 5, lane = tid & 31;
    int m0 = blockIdx.x << 7, n0 = blockIdx.y << 8, bz = blockIdx.z;
    int wm = (wid >> 2) * 64;
    int wn = (wid & 3) * 64;

    const __half* ap = A + (long)bz * strideA + (long)m0 * GK;
    const __half* bp = B + (long)bz * strideB + n0;

    float acc[4][8][4];
#pragma unroll
    for (int i = 0; i < 4; i++)
#pragma unroll
        for (int j = 0; j < 8; j++)
#pragma unroll
            for (int k = 0; k < 4; k++) acc[i][j][k] = 0.f;

#define LOAD_STAGE(kc) do { \
        int _k0 = (kc) << 6; \
        uint32_t _sb = sb + ((kc) % 3) * BG_STAGE; \
        _Pragma("unroll") \
        for (int _i = 0; _i < 4; _i++) { \
            int _g = _i * 256 + tid; \
            int _row = _g >> 3, _c = _g & 7; \
            cpasync16(_sb + swz128(_row, _c), ap + (long)_row * GK + _k0 + _c * 8); \
        } \
        _Pragma("unroll") \
        for (int _i = 0; _i < 8; _i++) { \
            int _g = _i * 256 + tid; \
            int _row = _g >> 5, _ch = _g & 31; \
            cpasync16(_sb + 16384 + bswz(_row, _ch), \
                      bp + (long)(_k0 + _row) * HW + _ch * 8); \
        } \
        CP_COMMIT(); \
    } while (0)

    LOAD_STAGE(0);
    LOAD_STAGE(1);

    for (int kc = 0; kc < KTILES; kc++) {
        // in-flight groups: {kc, kc+1} (or just {kc} on the last iteration)
        if (kc < KTILES - 1) CP_WAIT1();
        else                 CP_WAIT0();
        __syncthreads();
        if (kc + 2 < KTILES) LOAD_STAGE(kc + 2);

        uint32_t st = sb + (kc % 3) * BG_STAGE;
#pragma unroll
        for (int ks = 0; ks < 4; ks++) {
            uint32_t bh[8][2];
#pragma unroll
            for (int p = 0; p < 4; p++) {
                int row = ks * 16 + (lane & 7) + ((lane >> 3) & 1) * 8;
                int nh = wn + p * 16 + ((lane >> 4) & 1) * 8;
                uint32_t r[4];
                ldsm4t(r, st + 16384 + bswz(row, nh >> 3));
                bh[p * 2][0] = r[0]; bh[p * 2][1] = r[1];
                bh[p * 2 + 1][0] = r[2]; bh[p * 2 + 1][1] = r[3];
            }
#pragma unroll
            for (int mt = 0; mt < 4; mt++) {
                int ar = wm + mt * 16 + (lane & 7) + ((lane >> 3) & 1) * 8;
                int ac = ks * 2 + ((lane >> 4) & 1);
                uint32_t ah[4];
                ldsm4(ah, st + swz128(ar, ac));
#pragma unroll
                for (int nt = 0; nt < 8; nt++)
                    mma_f16(acc[mt][nt], ah, bh[nt]);
            }
        }
    }

    if (mode == 0) {
        __half* Cb = Ch + (long)bz * strideC;
#pragma unroll
        for (int mt = 0; mt < 4; mt++) {
            int m = m0 + wm + mt * 16 + (lane >> 2);
#pragma unroll
            for (int nt = 0; nt < 8; nt++) {
                int n = n0 + wn + nt * 8 + (lane & 3) * 2;
                *(__half2*)&Cb[(long)m * HW + n] = __halves2half2(
                    __float2half_rn(acc[mt][nt][0]), __float2half_rn(acc[mt][nt][1]));
                *(__half2*)&Cb[(long)(m + 8) * HW + n] = __halves2half2(
                    __float2half_rn(acc[mt][nt][2]), __float2half_rn(acc[mt][nt][3]));
            }
        }
    } else {
        float sc = g_sigma[3];
        float* Cb = C + (long)bz * strideC;
#pragma unroll
        for (int mt = 0; mt < 4; mt++) {
            int m = m0 + wm + mt * 16 + (lane >> 2);
#pragma unroll
            for (int nt = 0; nt < 8; nt++) {
                int n = n0 + wn + nt * 8 + (lane & 3) * 2;
                float2 v0 = make_float2(acc[mt][nt][0] * sc, acc[mt][nt][1] * sc);
                float2 v1 = make_float2(acc[mt][nt][2] * sc, acc[mt][nt][3] * sc);
                *(float2*)&Cb[(long)m * HW + n] = v0;
                *(float2*)&Cb[(long)(m + 8) * HW + n] = v1;
            }
        }
    }
#undef LOAD_STAGE
}

// ---------------- 3x3 depthwise conv (fp16 I/O, fp32 math), 2 rows/iter, fused norm -----
__global__ __launch_bounds__(128)
void dwconv(const __half* __restrict__ in, const float* __restrict__ w,
            __half* __restrict__ out)
{
    int ch = blockIdx.x, b = blockIdx.y;
    const __half* ip = in + (((long)b * C3 + ch) << 14);
    __half* op = out + (((long)b * C3 + ch) << 14);
    int x = threadIdx.x;

    __shared__ float sr[4][130];
    __shared__ float red[128];

    float w00 = w[ch * 9 + 0], w01 = w[ch * 9 + 1], w02 = w[ch * 9 + 2];
    float w10 = w[ch * 9 + 3], w11 = w[ch * 9 + 4], w12 = w[ch * 9 + 5];
    float w20 = w[ch * 9 + 6], w21 = w[ch * 9 + 7], w22 = w[ch * 9 + 8];

    float Al = 0.f, Am = 0.f, Ar = 0.f;
    float Bl, Bm, Br, Cl, Cm, Cr;

    float v0 = __half2float(ip[x]);
    float v1 = __half2float(ip[128 + x]);
    sr[0][x + 1] = v0;
    sr[1][x + 1] = v1;
    if (x == 0) {
        sr[0][0] = 0.f; sr[0][129] = 0.f;
        sr[1][0] = 0.f; sr[1][129] = 0.f;
    }
    __syncthreads();
    Bl = sr[0][x]; Bm = v0; Br = sr[0][x + 2];
    Cl = sr[1][x]; Cm = v1; Cr = sr[1][x + 2];

    float pre2 = __half2float(ip[256 + x]);
    float pre3 = __half2float(ip[384 + x]);

    float ssq = 0.f;
    for (int y = 0; y < 128; y += 2) {
        float m2 = pre2, m3 = pre3;
        int b2 = (y + 2) & 3, b3 = (y + 3) & 3;
        if (y + 2 < 128) {
            sr[b2][x + 1] = m2;
            if (x == 0) { sr[b2][0] = 0.f; sr[b2][129] = 0.f; }
        }
        if (y + 3 < 128) {
            sr[b3][x + 1] = m3;
            if (x == 0) { sr[b3][0] = 0.f; sr[b3][129] = 0.f; }
        }
        pre2 = (y + 4 < 128) ? __half2float(ip[((y + 4) << 7) + x]) : 0.f;
        pre3 = (y + 5 < 128) ? __half2float(ip[((y + 5) << 7) + x]) : 0.f;
        __syncthreads();

        float Dl = 0.f, Dm = 0.f, Dr = 0.f, El = 0.f, Em = 0.f, Er = 0.f;
        if (y + 2 < 128) { Dl = sr[b2][x]; Dm = m2; Dr = sr[b2][x + 2]; }
        if (y + 3 < 128) { El = sr[b3][x]; Em = m3; Er = sr[b3][x + 2]; }

        float s0 = Al * w00 + Am * w01 + Ar * w02
                 + Bl * w10 + Bm * w11 + Br * w12
                 + Cl * w20 + Cm * w21 + Cr * w22;
        float s1 = Bl * w00 + Bm * w01 + Br * w02
                 + Cl * w10 + Cm * w11 + Cr * w12
                 + Dl * w20 + Dm * w21 + Dr * w22;
        op[(y << 7) + x] = __float2half_rn(s0);
        op[((y + 1) << 7) + x] = __float2half_rn(s1);
        ssq += s0 * s0 + s1 * s1;

        Al = Cl; Am = Cm; Ar = Cr;
        Bl = Dl; Bm = Dm; Br = Dr;
        Cl = El; Cm = Em; Cr = Er;
    }

    if (ch < 2 * DIM) {
        red[x] = ssq; __syncthreads();
        for (int s = 64; s > 0; s >>= 1) {
            if (x < s) red[x] += red[x + s];
            __syncthreads();
        }
        if (x == 0) g_invnorm[b * 2 * DIM + ch] = 1.f / fmaxf(sqrtf(red[0]), EPS);
    }
}

// ---------------- attention logits via mma.sync (fp16, cp.async staged) -------
__global__ __launch_bounds__(96)
void attn_s(const __half* __restrict__ t)
{
    int bh = blockIdx.y;
    int b = bh >> 3, head = bh & 7;
    int nb = blockIdx.x * (HW / NCHUNKS);   // 1024
    const __half* qp = t + ((((long)b * C3) + head * CH) << 14);
    const __half* kp = t + ((((long)b * C3) + DIM + head * CH) << 14);

    __shared__ __align__(16) char smem[2 * 96 * 128];
    uint32_t sb = smem_u32(smem);
    int tid = threadIdx.x, w = tid >> 5, lane = tid & 31;

    float acc[6][4];
#pragma unroll
    for (int i = 0; i < 6; i++)
#pragma unroll
        for (int j = 0; j < 4; j++) acc[i][j] = 0.f;

#define AS_LOAD(kc) do { \
        int _off = nb + (kc) * 64; \
        uint32_t _sb = sb + ((kc) & 1) * 12288; \
        _Pragma("unroll") \
        for (int _i = 0; _i < 8; _i++) { \
            int _g = _i * 96 + tid; \
            int _row = _g >> 3, _c = _g & 7; \
            const __half* _src = (_row < 48) \
                ? qp + (((long)_row) << 14) + _off + _c * 8 \
                : kp + (((long)(_row - 48)) << 14) + _off + _c * 8; \
            cpasync16(_sb + swz128(_row, _c), _src); \
        } \
        CP_COMMIT(); \
    } while (0)

    AS_LOAD(0);
    for (int kc = 0; kc < 16; kc++) {
        if (kc < 15) { AS_LOAD(kc + 1); CP_WAIT1(); }
        else         { CP_WAIT0(); }
        __syncthreads();

        uint32_t st = sb + (kc & 1) * 12288;
#pragma unroll
        for (int ks = 0; ks < 4; ks++) {
            int ar = w * 16 + (lane & 7) + ((lane >> 3) & 1) * 8;
            int ac = ks * 2 + ((lane >> 4) & 1);
            uint32_t ah[4];
            ldsm4(ah, st + swz128(ar, ac));

            uint32_t bhf[6][2];
            int br = (lane & 7) + ((lane >> 4) & 1) * 8;
            int bc = ks * 2 + ((lane >> 3) & 1);
#pragma unroll
            for (int p = 0; p < 3; p++) {
                uint32_t r[4];
                ldsm4(r, st + swz128(48 + p * 16 + br, bc));
                bhf[p * 2][0] = r[0]; bhf[p * 2][1] = r[1];
                bhf[p * 2 + 1][0] = r[2]; bhf[p * 2 + 1][1] = r[3];
            }
#pragma unroll
            for (int nt = 0; nt < 6; nt++)
                mma_f16(acc[nt], ah, bhf[nt]);
        }
        __syncthreads();
    }
#undef AS_LOAD

    float* Sp = g_Spart + ((long)blockIdx.x * 32 + bh) * (CH * CH);
    int c0 = w * 16 + (lane >> 2);
#pragma unroll
    for (int nt = 0; nt < 6; nt++) {
        int d = nt * 8 + (lane & 3) * 2;
        *(float2*)&Sp[c0 * CH + d] = make_float2(acc[nt][0], acc[nt][1]);
        *(float2*)&Sp[(c0 + 8) * CH + d] = make_float2(acc[nt][2], acc[nt][3]);
    }
}

// ---------------- finalize: reduce partials, scale, clamp, softmax ----------------
__global__ __launch_bounds__(64)
void softmax_kernel(const float* __restrict__ temp)
{
    int blk = blockIdx.x;
    int bh = blk / CH, c = blk % CH;
    int b = bh >> 3, head = bh & 7;
    int d = threadIdx.x;
    __shared__ float sm[64];

    float myv = 0.f, val = -1e30f;
    if (d < CH) {
        float raw = 0.f;
#pragma unroll
        for (int ch = 0; ch < NCHUNKS; ch++)
            raw += g_Spart[((long)ch * 32 + bh) * (CH * CH) + c * CH + d];
        float invq = g_invnorm[b * 2 * DIM + head * CH + c];
        float invk = g_invnorm[b * 2 * DIM + DIM + head * CH + d];
        myv = raw * invq * invk * temp[head];
        myv = fminf(fmaxf(myv, -CLAMPV), CLAMPV);
        val = myv;
    }
    sm[d] = val; __syncthreads();
    for (int s = 32; s > 0; s >>= 1) { if (d < s) sm[d] = fmaxf(sm[d], sm[d + s]); __syncthreads(); }
    float m = sm[0]; __syncthreads();
    float e = (d < CH) ? expf(myv - m) : 0.f;
    sm[d] = e; __syncthreads();
    for (int s = 32; s > 0; s >>= 1) { if (d < s) sm[d] += sm[d + s]; __syncthreads(); }
    if (d < CH) g_S[(long)bh * (CH * CH) + c * CH + d] = e / sm[0];
}

// ---------------- launch ----------------
extern "C" void kernel_launch(void* const* d_in, const int* in_sizes, int n_in,
                              void* d_out, int out_size)
{
    const float* x     = (const float*)d_in[0];
    const float* qkvw  = (const float*)d_in[1];
    const float* dww   = (const float*)d_in[2];
    const float* projw = (const float*)d_in[3];
    const float* temp  = (const float*)d_in[4];
    const float* uq    = (const float*)d_in[5];
    const float* ud    = (const float*)d_in[6];
    const float* up    = (const float*)d_in[7];
    float* out = (float*)d_out;

    __half *t0h, *t1h, *x16, *wqh, *wp2;
    cudaGetSymbolAddress((void**)&t0h, g_t0h);
    cudaGetSymbolAddress((void**)&t1h, g_t1h);
    cudaGetSymbolAddress((void**)&x16, g_x16);
    cudaGetSymbolAddress((void**)&wqh, g_wqh);
    cudaGetSymbolAddress((void**)&wp2, g_wp2);

    cudaFuncSetAttribute(bgemmT, cudaFuncAttributeMaxDynamicSharedMemorySize, BG_SMEM);

    // GEMM inputs first (fused weight+x convert), sigma pipeline after
    conv_inputs<<<WBLK + XBLK, 256>>>(qkvw, x, wqh, x16);

    sigma_v<<<dim3(3, 8), 256>>>(qkvw, dww, projw, uq, ud, up);
    sigma_wv<<<dim3(3, 36), 256>>>(qkvw, dww, projw);
    scale_kernel<<<1, 32>>>();

    // qkv 1x1 conv: t0h[b][1152][hw] = wqh @ x16  (B natural layout)
    bgemmT<<<dim3(C3 / 128, HW / 256, BATCH), 256, BG_SMEM>>>(
        wqh, 0L, x16, (long)DIM * HW, nullptr, t0h, (long)C3 * HW, 0);

    // 3x3 depthwise conv (fp16 I/O) with fused q/k L2 norms
    dwconv<<<dim3(C3, BATCH), 128>>>(t0h, dww, t1h);

    // attention logits + softmax
    attn_s<<<dim3(NCHUNKS, BATCH * HEADS), 96>>>(t1h);
    softmax_kernel<<<BATCH * HEADS * CH, 64>>>(temp);

    // W' = wp @ blockdiag(S)  (folds attn@v into proj)
    wprime<<<dim3(HEADS, BATCH), 256>>>(projw, wp2);

    // out = W' @ v, fp32 out with combined sigma scale (v = t1h section, natural layout)
    bgemmT<<<dim3(DIM / 128, HW / 256, BATCH), 256, BG_SMEM>>>(
        wp2, (long)DIM * DIM, t1h + ((long)2 * DIM << 14), (long)C3 * HW,
        out, nullptr, (long)DIM * HW, 1);
}

// round 17
// speedup vs baseline: 5.3867x; 1.0138x over previous
#include <cuda_runtime.h>
#include <cuda_fp16.h>
#include <math.h>
#include <stdint.h>

#define BATCH 4
#define DIM 384
#define HEADS 8
#define CH 48            // DIM/HEADS
#define HW 16384         // 128*128
#define C3 1152          // 3*DIM
#define EPS 1e-12f
#define CLAMPV 50.0f
#define NCHUNKS 16
#define GK 384           // GEMM K (always DIM)

// ---------------- device scratch ----------------
__device__ __half g_t0h[(size_t)BATCH * C3 * HW];   // qkv GEMM output fp16
__device__ __half g_t1h[(size_t)BATCH * C3 * HW];   // depthwise output fp16
__device__ float g_sigma[4];
__device__ float g_invnorm[BATCH * 2 * DIM];
__device__ float g_Spart[NCHUNKS * BATCH * HEADS * CH * CH];
__device__ float g_S[BATCH * HEADS * CH * CH];
// sigma pipeline scratch
__device__ float g_vpart[3][8][DIM];
__device__ float g_wvpart[3][36];
__device__ float g_vssq[3];
// fp16 operands
__device__ __half g_x16[(size_t)BATCH * DIM * HW];  // x converted, natural [b][c][hw]
__device__ __half g_wqh[C3 * DIM];                  // qkv weights fp16 [m][k]
__device__ __half g_wp2[(size_t)BATCH * DIM * DIM]; // W' = wp @ blockdiag(S), per batch

// ---------------- warp-mma helpers ----------------
__device__ __forceinline__ uint32_t smem_u32(const void* p) {
    uint32_t a;
    asm("{ .reg .u64 t; cvta.to.shared.u64 t, %1; cvt.u32.u64 %0, t; }" : "=r"(a) : "l"(p));
    return a;
}
__device__ __forceinline__ void cpasync16(uint32_t s, const void* g) {
    asm volatile("cp.async.cg.shared.global [%0], [%1], 16;" :: "r"(s), "l"(g));
}
#define CP_COMMIT() asm volatile("cp.async.commit_group;" ::: "memory")
#define CP_WAIT1()  asm volatile("cp.async.wait_group 1;" ::: "memory")
#define CP_WAIT0()  asm volatile("cp.async.wait_group 0;" ::: "memory")

__device__ __forceinline__ void ldsm4(uint32_t* r, uint32_t addr) {
    asm volatile("ldmatrix.sync.aligned.m8n8.x4.shared.b16 {%0,%1,%2,%3}, [%4];"
        : "=r"(r[0]), "=r"(r[1]), "=r"(r[2]), "=r"(r[3]) : "r"(addr));
}
__device__ __forceinline__ void ldsm4t(uint32_t* r, uint32_t addr) {
    asm volatile("ldmatrix.sync.aligned.m8n8.x4.trans.shared.b16 {%0,%1,%2,%3}, [%4];"
        : "=r"(r[0]), "=r"(r[1]), "=r"(r[2]), "=r"(r[3]) : "r"(addr));
}
__device__ __forceinline__ void mma_f16(float* c, const uint32_t* a, const uint32_t* b) {
    asm volatile(
        "mma.sync.aligned.m16n8k16.row.col.f32.f16.f16.f32 "
        "{%0,%1,%2,%3}, {%4,%5,%6,%7}, {%8,%9}, {%0,%1,%2,%3};"
        : "+f"(c[0]), "+f"(c[1]), "+f"(c[2]), "+f"(c[3])
        : "r"(a[0]), "r"(a[1]), "r"(a[2]), "r"(a[3]), "r"(b[0]), "r"(b[1]));
}

// natural 128B rows (64 f16 per row), chunk c in 16B units
__device__ __forceinline__ uint32_t swz128(uint32_t row, uint32_t c) {
    return row * 128 + ((c ^ (row & 7)) * 16);
}
// B-tile (k-rows of 256 f16 = 512B): XOR 16B-chunk within each 128B window by row&7
__device__ __forceinline__ uint32_t bswz(uint32_t row, uint32_t chunk) {
    return row * 512 + (((chunk) & 24u) | (((chunk) & 7u) ^ ((row) & 7u))) * 16;
}

// ---------------- sigma pipeline ----------------
__global__ __launch_bounds__(256)
void sigma_v(const float* __restrict__ qkvw, const float* __restrict__ dww,
             const float* __restrict__ projw, const float* __restrict__ uq,
             const float* __restrict__ ud, const float* __restrict__ up)
{
    int which = blockIdx.x, ic = blockIdx.y;
    const float* wm; const float* u; int h, w;
    if (which == 0)      { wm = qkvw;  u = uq; h = C3;  w = DIM; }
    else if (which == 1) { wm = dww;   u = ud; h = C3;  w = 9;   }
    else                 { wm = projw; u = up; h = DIM; w = DIM; }
    int chunk = h >> 3;
    int i0 = ic * chunk, i1 = i0 + chunk;
    for (int j = threadIdx.x; j < w; j += 256) {
        float s = 0.f;
        for (int i = i0; i < i1; i++) s += wm[i * w + j] * u[i];
        g_vpart[which][ic][j] = s;
    }
}

__global__ __launch_bounds__(256)
void sigma_wv(const float* __restrict__ qkvw, const float* __restrict__ dww,
              const float* __restrict__ projw)
{
    int which = blockIdx.x;
    const float* wm; int h, w;
    if (which == 0)      { wm = qkvw;  h = C3;  w = DIM; }
    else if (which == 1) { wm = dww;   h = C3;  w = 9;   }
    else                 { wm = projw; h = DIM; w = DIM; }
    if (blockIdx.y * 32 >= h) return;

    __shared__ float v[DIM];
    __shared__ float red[256];
    int tid = threadIdx.x;

    for (int j = tid; j < w; j += 256) {
        float s = 0.f;
#pragma unroll
        for (int ic = 0; ic < 8; ic++) s += g_vpart[which][ic][j];
        v[j] = s;
    }
    __syncthreads();

    if (blockIdx.y == 0 && tid < 32) {
        float ss = 0.f;
        for (int j = tid; j < w; j += 32) ss += v[j] * v[j];
#pragma unroll
        for (int o = 16; o > 0; o >>= 1) ss += __shfl_xor_sync(0xffffffff, ss, o);
        if (tid == 0) g_vssq[which] = ss;
    }

    int r = tid >> 3, seg = tid & 7;
    int i = blockIdx.y * 32 + r;
    float s = 0.f;
    if (i < h) {
        int j0 = seg * (w / 8), j1 = (seg + 1) * (w / 8);
        if (w == 9) { j0 = (seg == 0) ? 0 : 9; j1 = 9; }
        for (int j = j0; j < j1; j++) s += wm[i * w + j] * v[j];
    }
    s += __shfl_xor_sync(0xffffffff, s, 1);
    s += __shfl_xor_sync(0xffffffff, s, 2);
    s += __shfl_xor_sync(0xffffffff, s, 4);
    float ssq = (seg == 0 && i < h) ? s * s : 0.f;

    red[tid] = ssq; __syncthreads();
    for (int st = 128; st > 0; st >>= 1) {
        if (tid < st) red[tid] += red[tid + st];
        __syncthreads();
    }
    if (tid == 0) g_wvpart[which][blockIdx.y] = red[0];
}

// parallel: warp w handles matrix w; lanes reduce partials; thread 0 combines.
__global__ __launch_bounds__(96)
void scale_kernel()
{
    __shared__ float sigs[3];
    int w = threadIdx.x >> 5, lane = threadIdx.x & 31;
    const int np[3] = {36, 36, 12};
    float wv = 0.f;
    for (int j = lane; j < np[w]; j += 32) wv += g_wvpart[w][j];
#pragma unroll
    for (int o = 16; o > 0; o >>= 1) wv += __shfl_xor_sync(0xffffffff, wv, o);
    if (lane == 0) {
        float mv = fmaxf(sqrtf(g_vssq[w]), EPS);
        float s2 = wv / (mv * mv);
        sigs[w] = s2 / fmaxf(sqrtf(s2), EPS);
    }
    __syncthreads();
    if (threadIdx.x == 0) {
        float comb = 1.f;
        for (int i = 0; i < 3; i++) comb /= (sigs[i] + EPS);
        g_sigma[3] = comb;
    }
}

// ---------------- fused: qkv weight fp32->fp16 + x fp32->fp16 ----------------
#define WBLK ((C3 * DIM + 255) / 256)
#define XBLK ((int)(((long)BATCH * DIM * HW / 4 + 255) / 256))
__global__ __launch_bounds__(256)
void conv_inputs(const float* __restrict__ qkvw, const float* __restrict__ x,
                 __half* __restrict__ qh, __half* __restrict__ x16)
{
    if (blockIdx.x < WBLK) {
        int i = blockIdx.x * 256 + threadIdx.x;
        if (i < C3 * DIM) qh[i] = __float2half_rn(qkvw[i]);
    } else {
        long i = ((long)(blockIdx.x - WBLK) * 256 + threadIdx.x) * 4;
        if (i < (long)BATCH * DIM * HW) {
            float4 v = *(const float4*)&x[i];
            __half2 h[2];
            h[0] = __halves2half2(__float2half_rn(v.x), __float2half_rn(v.y));
            h[1] = __halves2half2(__float2half_rn(v.z), __float2half_rn(v.w));
            *(uint2*)&x16[i] = *(const uint2*)h;
        }
    }
}

// ---------------- W' = wp @ blockdiag(S): grid (HEADS, BATCH), block 256 ----------------
__global__ __launch_bounds__(256)
void wprime(const float* __restrict__ projw, __half* __restrict__ wp2)
{
    int head = blockIdx.x, b = blockIdx.y;
    int bh = b * HEADS + head;
    __shared__ float S[CH][CH];
    for (int i = threadIdx.x; i < CH * CH; i += 256)
        S[i / CH][i % CH] = g_S[(long)bh * CH * CH + i];
    __syncthreads();

    int h0 = head * CH;
    for (int idx = threadIdx.x; idx < DIM * CH; idx += 256) {
        int o = idx / CH, d = idx % CH;
        const float* wr = projw + (long)o * DIM + h0;
        float s = 0.f;
#pragma unroll 8
        for (int c = 0; c < CH; c++) s += wr[c] * S[c][d];
        wp2[((long)b * DIM + o) * DIM + h0 + d] = __float2half_rn(s);
    }
}

// ---------------- fp16 GEMM, B natural [K][N], K-chunk 64, 3-stage ----------------
// Order per iteration: WAIT(stage kc) -> barrier -> issue LOAD(kc+2) -> compute kc.
// mode 0: fp16 out, smem-staged coalesced 512B-row stores. mode 1: fp32 out * sigma.
#define BG_STAGE 49152
#define BG_SMEM (3 * BG_STAGE)
#define KTILES (GK / 64)    // 6
#define EP_PITCH 264        // halves per staged row (528B; +16B to dodge bank phase)

__global__ void __launch_bounds__(256)
bgemmT(const __half* __restrict__ A, long strideA,
       const __half* __restrict__ B, long strideB,
       float* __restrict__ C, __half* __restrict__ Ch, long strideC, int mode)
{
    extern __shared__ char smem[];
    uint32_t sb = smem_u32(smem);
    int tid = threadIdx.x, wid = tid >> 5, lane = tid & 31;
    int m0 = blockIdx.x << 7, n0 = blockIdx.y << 8, bz = blockIdx.z;
    int wm = (wid >> 2) * 64;
    int wn = (wid & 3) * 64;

    const __half* ap = A + (long)bz * strideA + (long)m0 * GK;
    const __half* bp = B + (long)bz * strideB + n0;

    float acc[4][8][4];
#pragma unroll
    for (int i = 0; i < 4; i++)
#pragma unroll
        for (int j = 0; j < 8; j++)
#pragma unroll
            for (int k = 0; k < 4; k++) acc[i][j][k] = 0.f;

#define LOAD_STAGE(kc) do { \
        int _k0 = (kc) << 6; \
        uint32_t _sb = sb + ((kc) % 3) * BG_STAGE; \
        _Pragma("unroll") \
        for (int _i = 0; _i < 4; _i++) { \
            int _g = _i * 256 + tid; \
            int _row = _g >> 3, _c = _g & 7; \
            cpasync16(_sb + swz128(_row, _c), ap + (long)_row * GK + _k0 + _c * 8); \
        } \
        _Pragma("unroll") \
        for (int _i = 0; _i < 8; _i++) { \
            int _g = _i * 256 + tid; \
            int _row = _g >> 5, _ch = _g & 31; \
            cpasync16(_sb + 16384 + bswz(_row, _ch), \
                      bp + (long)(_k0 + _row) * HW + _ch * 8); \
        } \
        CP_COMMIT(); \
    } while (0)

    LOAD_STAGE(0);
    LOAD_STAGE(1);

    for (int kc = 0; kc < KTILES; kc++) {
        if (kc < KTILES - 1) CP_WAIT1();
        else                 CP_WAIT0();
        __syncthreads();
        if (kc + 2 < KTILES) LOAD_STAGE(kc + 2);

        uint32_t st = sb + (kc % 3) * BG_STAGE;
#pragma unroll
        for (int ks = 0; ks < 4; ks++) {
            uint32_t bh[8][2];
#pragma unroll
            for (int p = 0; p < 4; p++) {
                int row = ks * 16 + (lane & 7) + ((lane >> 3) & 1) * 8;
                int nh = wn + p * 16 + ((lane >> 4) & 1) * 8;
                uint32_t r[4];
                ldsm4t(r, st + 16384 + bswz(row, nh >> 3));
                bh[p * 2][0] = r[0]; bh[p * 2][1] = r[1];
                bh[p * 2 + 1][0] = r[2]; bh[p * 2 + 1][1] = r[3];
            }
#pragma unroll
            for (int mt = 0; mt < 4; mt++) {
                int ar = wm + mt * 16 + (lane & 7) + ((lane >> 3) & 1) * 8;
                int ac = ks * 2 + ((lane >> 4) & 1);
                uint32_t ah[4];
                ldsm4(ah, st + swz128(ar, ac));
#pragma unroll
                for (int nt = 0; nt < 8; nt++)
                    mma_f16(acc[mt][nt], ah, bh[nt]);
            }
        }
    }

    if (mode == 0) {
        // stage fp16 tile to smem, then coalesced 512B-row stores (warp per row)
        __syncthreads();   // all warps done reading stage buffers
        __half* es = (__half*)smem;
#pragma unroll
        for (int mt = 0; mt < 4; mt++) {
            int m = wm + mt * 16 + (lane >> 2);
#pragma unroll
            for (int nt = 0; nt < 8; nt++) {
                int n = wn + nt * 8 + (lane & 3) * 2;
                *(__half2*)&es[m * EP_PITCH + n] = __halves2half2(
                    __float2half_rn(acc[mt][nt][0]), __float2half_rn(acc[mt][nt][1]));
                *(__half2*)&es[(m + 8) * EP_PITCH + n] = __halves2half2(
                    __float2half_rn(acc[mt][nt][2]), __float2half_rn(acc[mt][nt][3]));
            }
        }
        __syncthreads();
        __half* Cb = Ch + (long)bz * strideC;
#pragma unroll
        for (int it = 0; it < 16; it++) {
            int r = it * 8 + wid;
            uint4 v = *(uint4*)&es[r * EP_PITCH + lane * 8];
            *(uint4*)&Cb[(long)(m0 + r) * HW + n0 + lane * 8] = v;
        }
    } else {
        float sc = g_sigma[3];
        float* Cb = C + (long)bz * strideC;
#pragma unroll
        for (int mt = 0; mt < 4; mt++) {
            int m = m0 + wm + mt * 16 + (lane >> 2);
#pragma unroll
            for (int nt = 0; nt < 8; nt++) {
                int n = n0 + wn + nt * 8 + (lane & 3) * 2;
                float2 v0 = make_float2(acc[mt][nt][0] * sc, acc[mt][nt][1] * sc);
                float2 v1 = make_float2(acc[mt][nt][2] * sc, acc[mt][nt][3] * sc);
                *(float2*)&Cb[(long)m * HW + n] = v0;
                *(float2*)&Cb[(long)(m + 8) * HW + n] = v1;
            }
        }
    }
#undef LOAD_STAGE
}

// ---------------- 3x3 depthwise conv (fp16 I/O, fp32 math), 2 rows/iter, fused norm -----
__global__ __launch_bounds__(128)
void dwconv(const __half* __restrict__ in, const float* __restrict__ w,
            __half* __restrict__ out)
{
    int ch = blockIdx.x, b = blockIdx.y;
    const __half* ip = in + (((long)b * C3 + ch) << 14);
    __half* op = out + (((long)b * C3 + ch) << 14);
    int x = threadIdx.x;

    __shared__ float sr[4][130];
    __shared__ float red[128];

    float w00 = w[ch * 9 + 0], w01 = w[ch * 9 + 1], w02 = w[ch * 9 + 2];
    float w10 = w[ch * 9 + 3], w11 = w[ch * 9 + 4], w12 = w[ch * 9 + 5];
    float w20 = w[ch * 9 + 6], w21 = w[ch * 9 + 7], w22 = w[ch * 9 + 8];

    float Al = 0.f, Am = 0.f, Ar = 0.f;
    float Bl, Bm, Br, Cl, Cm, Cr;

    float v0 = __half2float(ip[x]);
    float v1 = __half2float(ip[128 + x]);
    sr[0][x + 1] = v0;
    sr[1][x + 1] = v1;
    if (x == 0) {
        sr[0][0] = 0.f; sr[0][129] = 0.f;
        sr[1][0] = 0.f; sr[1][129] = 0.f;
    }
    __syncthreads();
    Bl = sr[0][x]; Bm = v0; Br = sr[0][x + 2];
    Cl = sr[1][x]; Cm = v1; Cr = sr[1][x + 2];

    float pre2 = __half2float(ip[256 + x]);
    float pre3 = __half2float(ip[384 + x]);

    float ssq = 0.f;
    for (int y = 0; y < 128; y += 2) {
        float m2 = pre2, m3 = pre3;
        int b2 = (y + 2) & 3, b3 = (y + 3) & 3;
        if (y + 2 < 128) {
            sr[b2][x + 1] = m2;
            if (x == 0) { sr[b2][0] = 0.f; sr[b2][129] = 0.f; }
        }
        if (y + 3 < 128) {
            sr[b3][x + 1] = m3;
            if (x == 0) { sr[b3][0] = 0.f; sr[b3][129] = 0.f; }
        }
        pre2 = (y + 4 < 128) ? __half2float(ip[((y + 4) << 7) + x]) : 0.f;
        pre3 = (y + 5 < 128) ? __half2float(ip[((y + 5) << 7) + x]) : 0.f;
        __syncthreads();

        float Dl = 0.f, Dm = 0.f, Dr = 0.f, El = 0.f, Em = 0.f, Er = 0.f;
        if (y + 2 < 128) { Dl = sr[b2][x]; Dm = m2; Dr = sr[b2][x + 2]; }
        if (y + 3 < 128) { El = sr[b3][x]; Em = m3; Er = sr[b3][x + 2]; }

        float s0 = Al * w00 + Am * w01 + Ar * w02
                 + Bl * w10 + Bm * w11 + Br * w12
                 + Cl * w20 + Cm * w21 + Cr * w22;
        float s1 = Bl * w00 + Bm * w01 + Br * w02
                 + Cl * w10 + Cm * w11 + Cr * w12
                 + Dl * w20 + Dm * w21 + Dr * w22;
        op[(y << 7) + x] = __float2half_rn(s0);
        op[((y + 1) << 7) + x] = __float2half_rn(s1);
        ssq += s0 * s0 + s1 * s1;

        Al = Cl; Am = Cm; Ar = Cr;
        Bl = Dl; Bm = Dm; Br = Dr;
        Cl = El; Cm = Em; Cr = Er;
    }

    if (ch < 2 * DIM) {
        red[x] = ssq; __syncthreads();
        for (int s = 64; s > 0; s >>= 1) {
            if (x < s) red[x] += red[x + s];
            __syncthreads();
        }
        if (x == 0) g_invnorm[b * 2 * DIM + ch] = 1.f / fmaxf(sqrtf(red[0]), EPS);
    }
}

// ---------------- attention logits via mma.sync (fp16, cp.async staged) -------
__global__ __launch_bounds__(96)
void attn_s(const __half* __restrict__ t)
{
    int bh = blockIdx.y;
    int b = bh >> 3, head = bh & 7;
    int nb = blockIdx.x * (HW / NCHUNKS);   // 1024
    const __half* qp = t + ((((long)b * C3) + head * CH) << 14);
    const __half* kp = t + ((((long)b * C3) + DIM + head * CH) << 14);

    __shared__ __align__(16) char smem[2 * 96 * 128];
    uint32_t sb = smem_u32(smem);
    int tid = threadIdx.x, w = tid >> 5, lane = tid & 31;

    float acc[6][4];
#pragma unroll
    for (int i = 0; i < 6; i++)
#pragma unroll
        for (int j = 0; j < 4; j++) acc[i][j] = 0.f;

#define AS_LOAD(kc) do { \
        int _off = nb + (kc) * 64; \
        uint32_t _sb = sb + ((kc) & 1) * 12288; \
        _Pragma("unroll") \
        for (int _i = 0; _i < 8; _i++) { \
            int _g = _i * 96 + tid; \
            int _row = _g >> 3, _c = _g & 7; \
            const __half* _src = (_row < 48) \
                ? qp + (((long)_row) << 14) + _off + _c * 8 \
                : kp + (((long)(_row - 48)) << 14) + _off + _c * 8; \
            cpasync16(_sb + swz128(_row, _c), _src); \
        } \
        CP_COMMIT(); \
    } while (0)

    AS_LOAD(0);
    for (int kc = 0; kc < 16; kc++) {
        if (kc < 15) { AS_LOAD(kc + 1); CP_WAIT1(); }
        else         { CP_WAIT0(); }
        __syncthreads();

        uint32_t st = sb + (kc & 1) * 12288;
#pragma unroll
        for (int ks = 0; ks < 4; ks++) {
            int ar = w * 16 + (lane & 7) + ((lane >> 3) & 1) * 8;
            int ac = ks * 2 + ((lane >> 4) & 1);
            uint32_t ah[4];
            ldsm4(ah, st + swz128(ar, ac));

            uint32_t bhf[6][2];
            int br = (lane & 7) + ((lane >> 4) & 1) * 8;
            int bc = ks * 2 + ((lane >> 3) & 1);
#pragma unroll
            for (int p = 0; p < 3; p++) {
                uint32_t r[4];
                ldsm4(r, st + swz128(48 + p * 16 + br, bc));
                bhf[p * 2][0] = r[0]; bhf[p * 2][1] = r[1];
                bhf[p * 2 + 1][0] = r[2]; bhf[p * 2 + 1][1] = r[3];
            }
#pragma unroll
            for (int nt = 0; nt < 6; nt++)
                mma_f16(acc[nt], ah, bhf[nt]);
        }
        __syncthreads();
    }
#undef AS_LOAD

    float* Sp = g_Spart + ((long)blockIdx.x * 32 + bh) * (CH * CH);
    int c0 = w * 16 + (lane >> 2);
#pragma unroll
    for (int nt = 0; nt < 6; nt++) {
        int d = nt * 8 + (lane & 3) * 2;
        *(float2*)&Sp[c0 * CH + d] = make_float2(acc[nt][0], acc[nt][1]);
        *(float2*)&Sp[(c0 + 8) * CH + d] = make_float2(acc[nt][2], acc[nt][3]);
    }
}

// ---------------- finalize: reduce partials, scale, clamp, softmax ----------------
__global__ __launch_bounds__(64)
void softmax_kernel(const float* __restrict__ temp)
{
    int blk = blockIdx.x;
    int bh = blk / CH, c = blk % CH;
    int b = bh >> 3, head = bh & 7;
    int d = threadIdx.x;
    __shared__ float sm[64];

    float myv = 0.f, val = -1e30f;
    if (d < CH) {
        float raw = 0.f;
#pragma unroll
        for (int ch = 0; ch < NCHUNKS; ch++)
            raw += g_Spart[((long)ch * 32 + bh) * (CH * CH) + c * CH + d];
        float invq = g_invnorm[b * 2 * DIM + head * CH + c];
        float invk = g_invnorm[b * 2 * DIM + DIM + head * CH + d];
        myv = raw * invq * invk * temp[head];
        myv = fminf(fmaxf(myv, -CLAMPV), CLAMPV);
        val = myv;
    }
    sm[d] = val; __syncthreads();
    for (int s = 32; s > 0; s >>= 1) { if (d < s) sm[d] = fmaxf(sm[d], sm[d + s]); __syncthreads(); }
    float m = sm[0]; __syncthreads();
    float e = (d < CH) ? expf(myv - m) : 0.f;
    sm[d] = e; __syncthreads();
    for (int s = 32; s > 0; s >>= 1) { if (d < s) sm[d] += sm[d + s]; __syncthreads(); }
    if (d < CH) g_S[(long)bh * (CH * CH) + c * CH + d] = e / sm[0];
}

// ---------------- launch ----------------
extern "C" void kernel_launch(void* const* d_in, const int* in_sizes, int n_in,
                              void* d_out, int out_size)
{
    const float* x     = (const float*)d_in[0];
    const float* qkvw  = (const float*)d_in[1];
    const float* dww   = (const float*)d_in[2];
    const float* projw = (const float*)d_in[3];
    const float* temp  = (const float*)d_in[4];
    const float* uq    = (const float*)d_in[5];
    const float* ud    = (const float*)d_in[6];
    const float* up    = (const float*)d_in[7];
    float* out = (float*)d_out;

    __half *t0h, *t1h, *x16, *wqh, *wp2;
    cudaGetSymbolAddress((void**)&t0h, g_t0h);
    cudaGetSymbolAddress((void**)&t1h, g_t1h);
    cudaGetSymbolAddress((void**)&x16, g_x16);
    cudaGetSymbolAddress((void**)&wqh, g_wqh);
    cudaGetSymbolAddress((void**)&wp2, g_wp2);

    cudaFuncSetAttribute(bgemmT, cudaFuncAttributeMaxDynamicSharedMemorySize, BG_SMEM);

    // GEMM inputs first (fused weight+x convert), sigma pipeline after
    conv_inputs<<<WBLK + XBLK, 256>>>(qkvw, x, wqh, x16);

    sigma_v<<<dim3(3, 8), 256>>>(qkvw, dww, projw, uq, ud, up);
    sigma_wv<<<dim3(3, 36), 256>>>(qkvw, dww, projw);
    scale_kernel<<<1, 96>>>();

    // qkv 1x1 conv: t0h[b][1152][hw] = wqh @ x16  (B natural layout)
    bgemmT<<<dim3(C3 / 128, HW / 256, BATCH), 256, BG_SMEM>>>(
        wqh, 0L, x16, (long)DIM * HW, nullptr, t0h, (long)C3 * HW, 0);

    // 3x3 depthwise conv (fp16 I/O) with fused q/k L2 norms
    dwconv<<<dim3(C3, BATCH), 128>>>(t0h, dww, t1h);

    // attention logits + softmax
    attn_s<<<dim3(NCHUNKS, BATCH * HEADS), 96>>>(t1h);
    softmax_kernel<<<BATCH * HEADS * CH, 64>>>(temp);

    // W' = wp @ blockdiag(S)  (folds attn@v into proj)
    wprime<<<dim3(HEADS, BATCH), 256>>>(projw, wp2);

    // out = W' @ v, fp32 out with combined sigma scale (v = t1h section, natural layout)
    bgemmT<<<dim3(DIM / 128, HW / 256, BATCH), 256, BG_SMEM>>>(
        wp2, (long)DIM * DIM, t1h + ((long)2 * DIM << 14), (long)C3 * HW,
        out, nullptr, (long)DIM * HW, 1);
}